// round 7
// baseline (speedup 1.0000x reference)
#include <cuda_runtime.h>
#include <cuda_bf16.h>
#include <cuda_fp16.h>
#include <math.h>
#include <stdint.h>

#define DIM   768
#define HEADS 12
#define HD    64
#define B_    2
#define WW    48
#define NTOK  2304
#define BHC   24
#define MROWS 4608

// -------- scratch (device globals; no allocation allowed) --------
__device__ __half g_qh[BHC*NTOK*HD], g_ql[BHC*NTOK*HD];
__device__ __half g_kh[BHC*NTOK*HD], g_kl[BHC*NTOK*HD];
__device__ __half g_vh[BHC*NTOK*HD], g_vl[BHC*NTOK*HD];
__device__ __nv_bfloat16 g_xh[MROWS*DIM],  g_xl[MROWS*DIM];
__device__ __nv_bfloat16 g_wqh[3*DIM*DIM], g_wql[3*DIM*DIM];
__device__ __nv_bfloat16 g_wph[DIM*DIM],   g_wpl[DIM*DIM];
__device__ __nv_bfloat16 g_ohh[MROWS*DIM], g_oll[MROWS*DIM];
__device__ float g_sin[NTOK*32], g_cos[NTOK*32];

// ==================== helpers ====================
__device__ __forceinline__ uint32_t smem_u32(const void* p) {
    uint32_t a;
    asm("{ .reg .u64 t; cvta.to.shared.u64 t, %1; cvt.u32.u64 %0, t; }" : "=r"(a) : "l"(p));
    return a;
}
__device__ __forceinline__ void ldsm4(uint32_t* r, uint32_t addr) {
    asm volatile("ldmatrix.sync.aligned.m8n8.x4.shared.b16 {%0,%1,%2,%3}, [%4];"
                 : "=r"(r[0]), "=r"(r[1]), "=r"(r[2]), "=r"(r[3]) : "r"(addr));
}
__device__ __forceinline__ void ldsm4t(uint32_t* r, uint32_t addr) {
    asm volatile("ldmatrix.sync.aligned.m8n8.x4.trans.shared.b16 {%0,%1,%2,%3}, [%4];"
                 : "=r"(r[0]), "=r"(r[1]), "=r"(r[2]), "=r"(r[3]) : "r"(addr));
}
__device__ __forceinline__ void mma_bf(float* d, const uint32_t* a,
                                       uint32_t b0, uint32_t b1) {
    asm volatile(
        "mma.sync.aligned.m16n8k16.row.col.f32.bf16.bf16.f32 "
        "{%0,%1,%2,%3}, {%4,%5,%6,%7}, {%8,%9}, {%0,%1,%2,%3};"
        : "+f"(d[0]), "+f"(d[1]), "+f"(d[2]), "+f"(d[3])
        : "r"(a[0]), "r"(a[1]), "r"(a[2]), "r"(a[3]), "r"(b0), "r"(b1));
}
__device__ __forceinline__ void mma_fp(float* d, const uint32_t* a,
                                       uint32_t b0, uint32_t b1) {
    asm volatile(
        "mma.sync.aligned.m16n8k16.row.col.f32.f16.f16.f32 "
        "{%0,%1,%2,%3}, {%4,%5,%6,%7}, {%8,%9}, {%0,%1,%2,%3};"
        : "+f"(d[0]), "+f"(d[1]), "+f"(d[2]), "+f"(d[3])
        : "r"(a[0]), "r"(a[1]), "r"(a[2]), "r"(a[3]), "r"(b0), "r"(b1));
}
__device__ __forceinline__ void cp16(uint32_t s, const void* g) {
    asm volatile("cp.async.cg.shared.global [%0], [%1], 16;" :: "r"(s), "l"(g) : "memory");
}
#define CP_COMMIT() asm volatile("cp.async.commit_group;" ::: "memory")
#define CP_WAIT1()  asm volatile("cp.async.wait_group 1;" ::: "memory")

// fast e^x on FMA/ALU pipes (no MUFU). |rel err| ~1e-7, x clamped >= -80.
__device__ __forceinline__ float fast_exp(float x) {
    x = fmaxf(x, -80.0f);
    float y = fmaf(x, 1.4426950409f, 12582912.0f);
    float z = y - 12582912.0f;
    int   n = __float_as_int(y) - 0x4B400000;
    float f = fmaf(x, 1.4426950409f, -z);
    float p = 1.3333558e-3f;
    p = fmaf(p, f, 9.6181291e-3f);
    p = fmaf(p, f, 5.5504109e-2f);
    p = fmaf(p, f, 2.4022651e-1f);
    p = fmaf(p, f, 6.9314718e-1f);
    p = fmaf(p, f, 1.0f);
    return __int_as_float(__float_as_int(p) + (n << 23));
}
__device__ __forceinline__ void split_h2(float a, float b,
                                         uint32_t& hi, uint32_t& lo) {
    __half2 hh = __floats2half2_rn(a, b);
    __half2 ll = __floats2half2_rn(a - __low2float(hh), b - __high2float(hh));
    hi = *(uint32_t*)&hh;
    lo = *(uint32_t*)&ll;
}

// ==================== prep kernels ====================
__global__ void __launch_bounds__(256) split_kernel(
    const float* __restrict__ src, __nv_bfloat16* __restrict__ hi,
    __nv_bfloat16* __restrict__ lo, int n4)
{
    int i = blockIdx.x * 256 + threadIdx.x;
    if (i >= n4) return;
    float4 v = ((const float4*)src)[i];
    float f[4] = {v.x, v.y, v.z, v.w};
    __nv_bfloat16 h[4], l[4];
    #pragma unroll
    for (int j = 0; j < 4; j++) {
        h[j] = __float2bfloat16(f[j]);
        l[j] = __float2bfloat16(f[j] - __bfloat162float(h[j]));
    }
    ((__nv_bfloat162*)hi)[2*i]   = __halves2bfloat162(h[0], h[1]);
    ((__nv_bfloat162*)hi)[2*i+1] = __halves2bfloat162(h[2], h[3]);
    ((__nv_bfloat162*)lo)[2*i]   = __halves2bfloat162(l[0], l[1]);
    ((__nv_bfloat162*)lo)[2*i+1] = __halves2bfloat162(l[2], l[3]);
}

__global__ void __launch_bounds__(256) rope_tab_kernel()
{
    int idx = blockIdx.x * 256 + threadIdx.x;
    if (idx >= NTOK * 32) return;
    int n = idx >> 5, j = idx & 31;
    int axis = j >> 4, p = j & 15;
    int y = n / WW, x = n - y * WW;
    float idxf  = axis ? (float)x : (float)y;
    float coord = 2.0f * ((idxf + 0.5f) / 48.0f) - 1.0f;
    float invp  = exp2f(-(float)p * 0.41524101186092607f);  // 100^(-p/16)
    float sn, cs; sincosf(6.283185307179586f * coord * invp, &sn, &cs);
    g_sin[idx] = sn; g_cos[idx] = cs;
}

// ==================== mma.sync bf16-split GEMM (cp.async 3-stage) =====
#define TSTRIDE 40
#define TILE_B  (128*TSTRIDE*2)        // 10240 bytes per sub-tile
#define STAGE_B (4*TILE_B)             // 40960 bytes per stage
#define GEMM_SMEM_B (3*STAGE_B)        // 122880 bytes

__device__ __forceinline__ void g2s_gemm(uint32_t stg,
    const __nv_bfloat16* Ah, const __nv_bfloat16* Al,
    const __nv_bfloat16* Bh, const __nv_bfloat16* Bl,
    int bm, int bn, int K, int k0, int tid)
{
    #pragma unroll
    for (int p = 0; p < 2; p++) {
        int id = p * 256 + tid;
        int row = id >> 2, kc = id & 3;
        uint32_t soff = (uint32_t)((id >> 2) * TSTRIDE + (id & 3) * 8) * 2;
        size_t oA = (size_t)(bm + row) * K + k0 + kc * 8;
        size_t oB = (size_t)(bn + row) * K + k0 + kc * 8;
        cp16(stg + 0*TILE_B + soff, &Ah[oA]);
        cp16(stg + 1*TILE_B + soff, &Al[oA]);
        cp16(stg + 2*TILE_B + soff, &Bh[oB]);
        cp16(stg + 3*TILE_B + soff, &Bl[oB]);
    }
}

template<int EPI>
__global__ void __launch_bounds__(256, 1) gemm_mma(
    const __nv_bfloat16* __restrict__ Ah, const __nv_bfloat16* __restrict__ Al,
    const __nv_bfloat16* __restrict__ Bh, const __nv_bfloat16* __restrict__ Bl,
    const float* __restrict__ bias, float* __restrict__ C, int M, int N, int K)
{
    extern __shared__ __align__(16) __nv_bfloat16 sm[];
    const uint32_t sbase = smem_u32(sm);
    const int tid = threadIdx.x;
    const int lane = tid & 31, wid = tid >> 5;
    const int wm = wid & 3, wn = wid >> 2;
    const int bm = blockIdx.y * 128, bn = blockIdx.x * 128;
    const int piece = lane >> 3, pr = lane & 7;

    float acc[2][8][4];
    #pragma unroll
    for (int i = 0; i < 2; i++)
        #pragma unroll
        for (int j = 0; j < 8; j++)
            #pragma unroll
            for (int k = 0; k < 4; k++) acc[i][j][k] = 0.0f;

    const int nit = K >> 5;     // 24
    g2s_gemm(sbase,           Ah, Al, Bh, Bl, bm, bn, K, 0,  tid); CP_COMMIT();
    g2s_gemm(sbase + STAGE_B, Ah, Al, Bh, Bl, bm, bn, K, 32, tid); CP_COMMIT();

    const int arow = wm*32 + (piece & 1)*8 + pr;
    const int brow = wn*64 + (piece & 1)*8 + pr;
    const int kofp = (piece >> 1) * 8;

    for (int it = 0; it < nit; it++) {
        CP_WAIT1();
        __syncthreads();
        if (it + 2 < nit)
            g2s_gemm(sbase + ((it + 2) % 3) * STAGE_B,
                     Ah, Al, Bh, Bl, bm, bn, K, (it + 2) << 5, tid);
        CP_COMMIT();

        uint32_t tA = sbase + (uint32_t)(it % 3) * STAGE_B;
        #pragma unroll
        for (int ks = 0; ks < 2; ks++) {
            int koff = ks*16 + kofp;
            uint32_t ah[2][4], al[2][4];
            #pragma unroll
            for (int mt = 0; mt < 2; mt++) {
                uint32_t ad = tA + ((arow + mt*16) * TSTRIDE + koff) * 2;
                ldsm4(ah[mt], ad);
                ldsm4(al[mt], ad + TILE_B);
            }
            #pragma unroll
            for (int np = 0; np < 4; np++) {
                uint32_t bd = tA + 2*TILE_B
                            + ((brow + np*16) * TSTRIDE + koff) * 2;
                uint32_t bh[4], bl[4];
                ldsm4(bh, bd);
                ldsm4(bl, bd + TILE_B);
                #pragma unroll
                for (int mt = 0; mt < 2; mt++) {
                    mma_bf(acc[mt][np*2],   ah[mt], bh[0], bh[2]);
                    mma_bf(acc[mt][np*2+1], ah[mt], bh[1], bh[3]);
                    mma_bf(acc[mt][np*2],   ah[mt], bl[0], bl[2]);
                    mma_bf(acc[mt][np*2+1], ah[mt], bl[1], bl[3]);
                    mma_bf(acc[mt][np*2],   al[mt], bh[0], bh[2]);
                    mma_bf(acc[mt][np*2+1], al[mt], bh[1], bh[3]);
                }
            }
        }
        __syncthreads();
    }

    const int cbase = bn + wn * 64;
    if (EPI == 0) {
        #pragma unroll
        for (int mt = 0; mt < 2; mt++)
            #pragma unroll
            for (int half = 0; half < 2; half++) {
                int m = bm + wm*32 + mt*16 + (lane >> 2) + half*8;
                #pragma unroll
                for (int nt = 0; nt < 8; nt++) {
                    int c = cbase + nt*8 + (lane & 3)*2;
                    float2 v;
                    v.x = acc[mt][nt][half*2+0] + bias[c];
                    v.y = acc[mt][nt][half*2+1] + bias[c+1];
                    *(float2*)&C[(size_t)m * N + c] = v;
                }
            }
    } else {
        int which = cbase / DIM;
        int h = (cbase % DIM) >> 6;
        __half* bhp = (which == 0) ? g_qh : (which == 1) ? g_kh : g_vh;
        __half* blp = (which == 0) ? g_ql : (which == 1) ? g_kl : g_vl;
        const float qs = (which == 0) ? 0.125f : 1.0f;
        #pragma unroll
        for (int mt = 0; mt < 2; mt++)
            #pragma unroll
            for (int half = 0; half < 2; half++) {
                int m = bm + wm*32 + mt*16 + (lane >> 2) + half*8;
                int bb = m / NTOK, pos = m - bb * NTOK;
                size_t dof = ((size_t)(bb*HEADS + h) * NTOK + pos) * HD;
                __half* dsth = bhp + dof;
                __half* dstl = blp + dof;
                if (which < 2) {
                    #pragma unroll
                    for (int nt = 0; nt < 4; nt++) {
                        int d0 = nt*8 + (lane & 3)*2;
                        float rl[2], rh[2];
                        #pragma unroll
                        for (int j = 0; j < 2; j++) {
                            float vlo = acc[mt][nt][half*2+j]   + bias[cbase + d0 + j];
                            float vhi = acc[mt][nt+4][half*2+j] + bias[cbase + 32 + d0 + j];
                            float sn = g_sin[pos*32 + d0 + j];
                            float cs = g_cos[pos*32 + d0 + j];
                            rl[j] = (vlo*cs - vhi*sn) * qs;
                            rh[j] = (vhi*cs + vlo*sn) * qs;
                        }
                        uint32_t hh, ll;
                        split_h2(rl[0], rl[1], hh, ll);
                        *(uint32_t*)&dsth[d0] = hh; *(uint32_t*)&dstl[d0] = ll;
                        split_h2(rh[0], rh[1], hh, ll);
                        *(uint32_t*)&dsth[32 + d0] = hh; *(uint32_t*)&dstl[32 + d0] = ll;
                    }
                } else {
                    #pragma unroll
                    for (int nt = 0; nt < 8; nt++) {
                        int d = nt*8 + (lane & 3)*2;
                        float v0 = acc[mt][nt][half*2+0] + bias[cbase + d];
                        float v1 = acc[mt][nt][half*2+1] + bias[cbase + d + 1];
                        uint32_t hh, ll;
                        split_h2(v0, v1, hh, ll);
                        *(uint32_t*)&dsth[d] = hh; *(uint32_t*)&dstl[d] = ll;
                    }
                }
            }
    }
}

// ==================== attention: HMMA fp16-split flash (cp.async 2-stage)
#define AST 72
#define ARR_B (64*AST*2)          // 9216 bytes per array (Kh/Kl/Vh/Vl)
#define ASTAGE_B (4*ARR_B)        // 36864 bytes per stage
#define ATTN_SMEM (2*ASTAGE_B)    // 73728 bytes

__device__ __forceinline__ void g2s_attn(uint32_t stg,
    const __half* Kh, const __half* Kl, const __half* Vh, const __half* Vl,
    int k0, int tid)
{
    #pragma unroll
    for (int i = 0; i < 8; i++) {
        int lin = i * 256 + tid;
        int arr = lin >> 9, rem = lin & 511;
        int row = rem >> 3, c = (rem & 7) * 8;
        const __half* src = (arr == 0 ? Kh : arr == 1 ? Kl : arr == 2 ? Vh : Vl)
                            + (size_t)(k0 + row) * HD + c;
        cp16(stg + (uint32_t)arr * ARR_B + (row * AST + c) * 2, src);
    }
}

__global__ void __launch_bounds__(256, 2) attn_mma()
{
    extern __shared__ __align__(16) __half smh[];
    const uint32_t sb = smem_u32(smh);

    const int tid = threadIdx.x;
    const int lane = tid & 31, w = tid >> 5;
    const int l15 = lane & 15, l16 = lane >> 4;
    const int bh = blockIdx.y, q0 = blockIdx.x * 128;

    const __half* Qh = g_qh + ((size_t)bh * NTOK + q0) * HD;
    const __half* Ql = g_ql + ((size_t)bh * NTOK + q0) * HD;
    const __half* Kh = g_kh + (size_t)bh * NTOK * HD;
    const __half* Kl = g_kl + (size_t)bh * NTOK * HD;
    const __half* Vh = g_vh + (size_t)bh * NTOK * HD;
    const __half* Vl = g_vl + (size_t)bh * NTOK * HD;

    // ---- stage Q (hi/lo) into stage-0 region, extract A-fragments ----
    #pragma unroll
    for (int t = 0; t < 8; t++) {
        int lin = t * 256 + tid;
        int arr = lin >> 10, rem = lin & 1023;
        int row = rem >> 3, c = (rem & 7) * 8;
        const __half* src = (arr ? Ql : Qh) + (size_t)row * HD + c;
        __half* dst = smh + arr * 128*AST + row * AST + c;
        *(uint4*)dst = *(const uint4*)src;
    }
    __syncthreads();
    uint32_t qfh[4][4], qfl[4][4];
    {
        uint32_t qa = sb + (((w*16 + l15) * AST) + l16*8) * 2;
        #pragma unroll
        for (int ks = 0; ks < 4; ks++) {
            ldsm4(qfh[ks], qa + ks*32);
            ldsm4(qfl[ks], qa + ks*32 + 128*AST*2);
        }
    }
    __syncthreads();   // Q frags extracted before cp.async overwrites stage 0

    g2s_attn(sb,            Kh, Kl, Vh, Vl, 0,  tid); CP_COMMIT();
    g2s_attn(sb + ASTAGE_B, Kh, Kl, Vh, Vl, 64, tid); CP_COMMIT();

    float acc[8][4];
    #pragma unroll
    for (int i = 0; i < 8; i++)
        #pragma unroll
        for (int j = 0; j < 4; j++) acc[i][j] = 0.0f;
    float m0 = -1e30f, m1 = -1e30f, l0 = 0.0f, l1 = 0.0f;

    const uint32_t lko = (l15 * AST + l16*8) * 2;

    for (int t = 0; t < NTOK/64; t++) {
        CP_WAIT1();
        __syncthreads();
        uint32_t stg = sb + (uint32_t)(t & 1) * ASTAGE_B;
        uint32_t kbase = stg + lko;
        uint32_t vbase = stg + 2*ARR_B + lko;

        // ---- S = Q K^T (warp: 16 x 64) ----
        float s[8][4];
        #pragma unroll
        for (int i = 0; i < 8; i++)
            #pragma unroll
            for (int j = 0; j < 4; j++) s[i][j] = 0.0f;
        #pragma unroll
        for (int ks = 0; ks < 4; ks++) {
            #pragma unroll
            for (int nbp = 0; nbp < 8; nbp += 2) {
                uint32_t kh4[4], kl4[4];
                uint32_t ka = kbase + (nbp*8*AST + ks*16) * 2;
                ldsm4(kh4, ka);
                ldsm4(kl4, ka + ARR_B);
                mma_fp(s[nbp],   qfh[ks], kh4[0], kh4[2]);
                mma_fp(s[nbp+1], qfh[ks], kh4[1], kh4[3]);
                mma_fp(s[nbp],   qfl[ks], kh4[0], kh4[2]);
                mma_fp(s[nbp+1], qfl[ks], kh4[1], kh4[3]);
                mma_fp(s[nbp],   qfh[ks], kl4[0], kl4[2]);
                mma_fp(s[nbp+1], qfh[ks], kl4[1], kl4[3]);
            }
        }

        // ---- online softmax ----
        float mx0 = -1e30f, mx1 = -1e30f;
        #pragma unroll
        for (int i = 0; i < 8; i++) {
            mx0 = fmaxf(mx0, fmaxf(s[i][0], s[i][1]));
            mx1 = fmaxf(mx1, fmaxf(s[i][2], s[i][3]));
        }
        mx0 = fmaxf(mx0, __shfl_xor_sync(0xffffffffu, mx0, 1));
        mx0 = fmaxf(mx0, __shfl_xor_sync(0xffffffffu, mx0, 2));
        mx1 = fmaxf(mx1, __shfl_xor_sync(0xffffffffu, mx1, 1));
        mx1 = fmaxf(mx1, __shfl_xor_sync(0xffffffffu, mx1, 2));
        float nm0 = fmaxf(m0, mx0), nm1 = fmaxf(m1, mx1);
        float f0 = fast_exp(m0 - nm0), f1 = fast_exp(m1 - nm1);
        m0 = nm0; m1 = nm1;
        float sum0 = 0.0f, sum1 = 0.0f;
        #pragma unroll
        for (int i = 0; i < 8; i++) {
            s[i][0] = fast_exp(s[i][0] - nm0); sum0 += s[i][0];
            s[i][1] = fast_exp(s[i][1] - nm0); sum0 += s[i][1];
            s[i][2] = fast_exp(s[i][2] - nm1); sum1 += s[i][2];
            s[i][3] = fast_exp(s[i][3] - nm1); sum1 += s[i][3];
        }
        sum0 += __shfl_xor_sync(0xffffffffu, sum0, 1);
        sum0 += __shfl_xor_sync(0xffffffffu, sum0, 2);
        sum1 += __shfl_xor_sync(0xffffffffu, sum1, 1);
        sum1 += __shfl_xor_sync(0xffffffffu, sum1, 2);
        l0 = l0 * f0 + sum0;
        l1 = l1 * f1 + sum1;
        #pragma unroll
        for (int i = 0; i < 8; i++) {
            acc[i][0] *= f0; acc[i][1] *= f0;
            acc[i][2] *= f1; acc[i][3] *= f1;
        }

        // ---- P -> fp16 hi/lo A-fragments ----
        uint32_t aph[4][4], apl[4][4];
        #pragma unroll
        for (int ks = 0; ks < 4; ks++) {
            int n0 = 2*ks, n1 = 2*ks + 1;
            split_h2(s[n0][0], s[n0][1], aph[ks][0], apl[ks][0]);
            split_h2(s[n0][2], s[n0][3], aph[ks][1], apl[ks][1]);
            split_h2(s[n1][0], s[n1][1], aph[ks][2], apl[ks][2]);
            split_h2(s[n1][2], s[n1][3], aph[ks][3], apl[ks][3]);
        }

        // ---- O += P V (warp: 16 x 64) ----
        #pragma unroll
        for (int ks = 0; ks < 4; ks++) {
            #pragma unroll
            for (int nbp = 0; nbp < 8; nbp += 2) {
                uint32_t vh4[4], vl4[4];
                uint32_t va = vbase + (ks*16*AST + nbp*8) * 2;
                ldsm4t(vh4, va);
                ldsm4t(vl4, va + ARR_B);
                mma_fp(acc[nbp],   aph[ks], vh4[0], vh4[1]);
                mma_fp(acc[nbp+1], aph[ks], vh4[2], vh4[3]);
                mma_fp(acc[nbp],   apl[ks], vh4[0], vh4[1]);
                mma_fp(acc[nbp+1], apl[ks], vh4[2], vh4[3]);
                mma_fp(acc[nbp],   aph[ks], vl4[0], vl4[1]);
                mma_fp(acc[nbp+1], aph[ks], vl4[2], vl4[3]);
            }
        }

        __syncthreads();   // all readers done before refilling this stage
        if (t + 2 < NTOK/64)
            g2s_attn(stg, Kh, Kl, Vh, Vl, (t + 2) * 64, tid);
        CP_COMMIT();
    }

    // ---- normalize + write O as bf16 hi/lo, [b, n, h*64 + d] ----
    float inv0 = 1.0f / l0, inv1 = 1.0f / l1;
    int b = bh / HEADS, h = bh - b * HEADS;
    int r0 = q0 + w*16 + (lane >> 2);
    int col = h*HD + (lane & 3)*2;
    #pragma unroll
    for (int nb = 0; nb < 8; nb++) {
        size_t o0 = ((size_t)(b*NTOK + r0))     * DIM + col + nb*8;
        size_t o1 = ((size_t)(b*NTOK + r0 + 8)) * DIM + col + nb*8;
        float a0 = acc[nb][0]*inv0, a1 = acc[nb][1]*inv0;
        float a2 = acc[nb][2]*inv1, a3 = acc[nb][3]*inv1;
        __nv_bfloat162 hh, ll;
        hh = __floats2bfloat162_rn(a0, a1);
        ll = __floats2bfloat162_rn(a0 - __bfloat162float(hh.x),
                                   a1 - __bfloat162float(hh.y));
        *(__nv_bfloat162*)&g_ohh[o0] = hh;
        *(__nv_bfloat162*)&g_oll[o0] = ll;
        hh = __floats2bfloat162_rn(a2, a3);
        ll = __floats2bfloat162_rn(a2 - __bfloat162float(hh.x),
                                   a3 - __bfloat162float(hh.y));
        *(__nv_bfloat162*)&g_ohh[o1] = hh;
        *(__nv_bfloat162*)&g_oll[o1] = ll;
    }
}

// ==================== launcher ====================
extern "C" void kernel_launch(void* const* d_in, const int* in_sizes, int n_in,
                              void* d_out, int out_size)
{
    const float* x      = (const float*)d_in[0];
    const float* w_qkv  = (const float*)d_in[1];
    const float* b_qkv  = (const float*)d_in[2];
    const float* w_proj = (const float*)d_in[3];
    const float* b_proj = (const float*)d_in[4];
    float* out = (float*)d_out;

    void *xh, *xl, *wqh, *wql, *wph, *wpl, *ohh, *oll;
    cudaGetSymbolAddress(&xh,  g_xh);  cudaGetSymbolAddress(&xl,  g_xl);
    cudaGetSymbolAddress(&wqh, g_wqh); cudaGetSymbolAddress(&wql, g_wql);
    cudaGetSymbolAddress(&wph, g_wph); cudaGetSymbolAddress(&wpl, g_wpl);
    cudaGetSymbolAddress(&ohh, g_ohh); cudaGetSymbolAddress(&oll, g_oll);

    cudaFuncSetAttribute(gemm_mma<0>, cudaFuncAttributeMaxDynamicSharedMemorySize,
                         GEMM_SMEM_B);
    cudaFuncSetAttribute(gemm_mma<1>, cudaFuncAttributeMaxDynamicSharedMemorySize,
                         GEMM_SMEM_B);
    cudaFuncSetAttribute(attn_mma, cudaFuncAttributeMaxDynamicSharedMemorySize,
                         ATTN_SMEM);

    split_kernel<<<(MROWS*DIM/4 + 255)/256, 256>>>(
        x, (__nv_bfloat16*)xh, (__nv_bfloat16*)xl, MROWS*DIM/4);
    split_kernel<<<(3*DIM*DIM/4 + 255)/256, 256>>>(
        w_qkv, (__nv_bfloat16*)wqh, (__nv_bfloat16*)wql, 3*DIM*DIM/4);
    split_kernel<<<(DIM*DIM/4 + 255)/256, 256>>>(
        w_proj, (__nv_bfloat16*)wph, (__nv_bfloat16*)wpl, DIM*DIM/4);
    rope_tab_kernel<<<(NTOK*32 + 255)/256, 256>>>();

    // 1) QKV GEMM + bias + RoPE + fp16 hi/lo scatter
    gemm_mma<1><<<dim3(3*DIM/128, MROWS/128), 256, GEMM_SMEM_B>>>(
        (const __nv_bfloat16*)xh, (const __nv_bfloat16*)xl,
        (const __nv_bfloat16*)wqh, (const __nv_bfloat16*)wql,
        b_qkv, nullptr, MROWS, 3*DIM, DIM);

    // 2) attention (HMMA fp16-split flash, cp.async double-buffered)
    attn_mma<<<dim3(NTOK/128, BHC), 256, ATTN_SMEM>>>();

    // 3) output projection -> d_out
    gemm_mma<0><<<dim3(DIM/128, MROWS/128), 256, GEMM_SMEM_B>>>(
        (const __nv_bfloat16*)ohh, (const __nv_bfloat16*)oll,
        (const __nv_bfloat16*)wph, (const __nv_bfloat16*)wpl,
        b_proj, out, MROWS, DIM, DIM);
}

// round 8
// speedup vs baseline: 1.3232x; 1.3232x over previous
#include <cuda_runtime.h>
#include <cuda_bf16.h>
#include <cuda_fp16.h>
#include <math.h>
#include <stdint.h>

#define DIM   768
#define HEADS 12
#define HD    64
#define B_    2
#define WW    48
#define NTOK  2304
#define BHC   24
#define MROWS 4608

// -------- scratch (device globals; no allocation allowed) --------
__device__ __half g_qh[BHC*NTOK*HD], g_ql[BHC*NTOK*HD];
__device__ __half g_kh[BHC*NTOK*HD], g_kl[BHC*NTOK*HD];
__device__ __half g_vh[BHC*NTOK*HD], g_vl[BHC*NTOK*HD];
__device__ __nv_bfloat16 g_xh[MROWS*DIM],  g_xl[MROWS*DIM];
__device__ __nv_bfloat16 g_wqh[3*DIM*DIM], g_wql[3*DIM*DIM];
__device__ __nv_bfloat16 g_wph[DIM*DIM],   g_wpl[DIM*DIM];
__device__ __nv_bfloat16 g_ohh[MROWS*DIM], g_oll[MROWS*DIM];
__device__ float g_sin[NTOK*32], g_cos[NTOK*32];

// ==================== helpers ====================
__device__ __forceinline__ uint32_t smem_u32(const void* p) {
    uint32_t a;
    asm("{ .reg .u64 t; cvta.to.shared.u64 t, %1; cvt.u32.u64 %0, t; }" : "=r"(a) : "l"(p));
    return a;
}
__device__ __forceinline__ void ldsm4(uint32_t* r, uint32_t addr) {
    asm volatile("ldmatrix.sync.aligned.m8n8.x4.shared.b16 {%0,%1,%2,%3}, [%4];"
                 : "=r"(r[0]), "=r"(r[1]), "=r"(r[2]), "=r"(r[3]) : "r"(addr));
}
__device__ __forceinline__ void ldsm4t(uint32_t* r, uint32_t addr) {
    asm volatile("ldmatrix.sync.aligned.m8n8.x4.trans.shared.b16 {%0,%1,%2,%3}, [%4];"
                 : "=r"(r[0]), "=r"(r[1]), "=r"(r[2]), "=r"(r[3]) : "r"(addr));
}
__device__ __forceinline__ void mma_bf(float* d, const uint32_t* a,
                                       uint32_t b0, uint32_t b1) {
    asm volatile(
        "mma.sync.aligned.m16n8k16.row.col.f32.bf16.bf16.f32 "
        "{%0,%1,%2,%3}, {%4,%5,%6,%7}, {%8,%9}, {%0,%1,%2,%3};"
        : "+f"(d[0]), "+f"(d[1]), "+f"(d[2]), "+f"(d[3])
        : "r"(a[0]), "r"(a[1]), "r"(a[2]), "r"(a[3]), "r"(b0), "r"(b1));
}
__device__ __forceinline__ void mma_fp(float* d, const uint32_t* a,
                                       uint32_t b0, uint32_t b1) {
    asm volatile(
        "mma.sync.aligned.m16n8k16.row.col.f32.f16.f16.f32 "
        "{%0,%1,%2,%3}, {%4,%5,%6,%7}, {%8,%9}, {%0,%1,%2,%3};"
        : "+f"(d[0]), "+f"(d[1]), "+f"(d[2]), "+f"(d[3])
        : "r"(a[0]), "r"(a[1]), "r"(a[2]), "r"(a[3]), "r"(b0), "r"(b1));
}
// fast e^x on FMA/ALU pipes (no MUFU). |rel err| ~1e-7, x clamped >= -80.
__device__ __forceinline__ float fast_exp(float x) {
    x = fmaxf(x, -80.0f);
    float y = fmaf(x, 1.4426950409f, 12582912.0f);
    float z = y - 12582912.0f;
    int   n = __float_as_int(y) - 0x4B400000;
    float f = fmaf(x, 1.4426950409f, -z);
    float p = 1.3333558e-3f;
    p = fmaf(p, f, 9.6181291e-3f);
    p = fmaf(p, f, 5.5504109e-2f);
    p = fmaf(p, f, 2.4022651e-1f);
    p = fmaf(p, f, 6.9314718e-1f);
    p = fmaf(p, f, 1.0f);
    return __int_as_float(__float_as_int(p) + (n << 23));
}
__device__ __forceinline__ void split_h2(float a, float b,
                                         uint32_t& hi, uint32_t& lo) {
    __half2 hh = __floats2half2_rn(a, b);
    __half2 ll = __floats2half2_rn(a - __low2float(hh), b - __high2float(hh));
    hi = *(uint32_t*)&hh;
    lo = *(uint32_t*)&ll;
}

// ==================== prep kernels ====================
__global__ void __launch_bounds__(256) split_kernel(
    const float* __restrict__ src, __nv_bfloat16* __restrict__ hi,
    __nv_bfloat16* __restrict__ lo, int n4)
{
    int i = blockIdx.x * 256 + threadIdx.x;
    if (i >= n4) return;
    float4 v = ((const float4*)src)[i];
    float f[4] = {v.x, v.y, v.z, v.w};
    __nv_bfloat16 h[4], l[4];
    #pragma unroll
    for (int j = 0; j < 4; j++) {
        h[j] = __float2bfloat16(f[j]);
        l[j] = __float2bfloat16(f[j] - __bfloat162float(h[j]));
    }
    ((__nv_bfloat162*)hi)[2*i]   = __halves2bfloat162(h[0], h[1]);
    ((__nv_bfloat162*)hi)[2*i+1] = __halves2bfloat162(h[2], h[3]);
    ((__nv_bfloat162*)lo)[2*i]   = __halves2bfloat162(l[0], l[1]);
    ((__nv_bfloat162*)lo)[2*i+1] = __halves2bfloat162(l[2], l[3]);
}

__global__ void __launch_bounds__(256) rope_tab_kernel()
{
    int idx = blockIdx.x * 256 + threadIdx.x;
    if (idx >= NTOK * 32) return;
    int n = idx >> 5, j = idx & 31;
    int axis = j >> 4, p = j & 15;
    int y = n / WW, x = n - y * WW;
    float idxf  = axis ? (float)x : (float)y;
    float coord = 2.0f * ((idxf + 0.5f) / 48.0f) - 1.0f;
    float invp  = exp2f(-(float)p * 0.41524101186092607f);  // 100^(-p/16)
    float sn, cs; sincosf(6.283185307179586f * coord * invp, &sn, &cs);
    g_sin[idx] = sn; g_cos[idx] = cs;
}

// ==================== mma.sync bf16-split GEMM ====================
#define TSTRIDE 40
#define TILE_E  (128*TSTRIDE)
#define GEMM_SMEM_B (8*TILE_E*2)

__device__ __forceinline__ void g2r(uint4* r,
    const __nv_bfloat16* Ah, const __nv_bfloat16* Al,
    const __nv_bfloat16* Bh, const __nv_bfloat16* Bl,
    int bm, int bn, int K, int k0, int tid)
{
    #pragma unroll
    for (int p = 0; p < 2; p++) {
        int id = p * 256 + tid;
        int row = id >> 2, kc = id & 3;
        size_t oA = (size_t)(bm + row) * K + k0 + kc * 8;
        size_t oB = (size_t)(bn + row) * K + k0 + kc * 8;
        r[0+p] = *(const uint4*)&Ah[oA];
        r[2+p] = *(const uint4*)&Al[oA];
        r[4+p] = *(const uint4*)&Bh[oB];
        r[6+p] = *(const uint4*)&Bl[oB];
    }
}
__device__ __forceinline__ void r2s(__nv_bfloat16* sm, const uint4* r,
                                    int tid, int st)
{
    #pragma unroll
    for (int p = 0; p < 2; p++) {
        int id = p * 256 + tid;
        int off = (id >> 2) * TSTRIDE + (id & 3) * 8;
        #pragma unroll
        for (int t = 0; t < 4; t++)
            *(uint4*)&sm[(st*4 + t) * TILE_E + off] = r[t*2 + p];
    }
}

template<int EPI>
__global__ void __launch_bounds__(256, 2) gemm_mma(
    const __nv_bfloat16* __restrict__ Ah, const __nv_bfloat16* __restrict__ Al,
    const __nv_bfloat16* __restrict__ Bh, const __nv_bfloat16* __restrict__ Bl,
    const float* __restrict__ bias, float* __restrict__ C, int M, int N, int K)
{
    extern __shared__ __align__(16) __nv_bfloat16 sm[];
    const uint32_t sbase = smem_u32(sm);
    const int tid = threadIdx.x;
    const int lane = tid & 31, wid = tid >> 5;
    const int wm = wid & 3, wn = wid >> 2;
    const int bm = blockIdx.y * 128, bn = blockIdx.x * 128;
    const int piece = lane >> 3, pr = lane & 7;

    float acc[2][8][4];
    #pragma unroll
    for (int i = 0; i < 2; i++)
        #pragma unroll
        for (int j = 0; j < 8; j++)
            #pragma unroll
            for (int k = 0; k < 4; k++) acc[i][j][k] = 0.0f;

    const int nit = K >> 5;
    uint4 r[8];
    g2r(r, Ah, Al, Bh, Bl, bm, bn, K, 0, tid);
    r2s(sm, r, tid, 0);
    __syncthreads();

    const int arow = wm*32 + (piece & 1)*8 + pr;
    const int brow = wn*64 + (piece & 1)*8 + pr;
    const int kofp = (piece >> 1) * 8;

    for (int it = 0; it < nit; it++) {
        int st = it & 1;
        bool more = (it + 1) < nit;
        if (more) g2r(r, Ah, Al, Bh, Bl, bm, bn, K, (it + 1) << 5, tid);

        uint32_t tA = sbase + (uint32_t)(st*4) * (TILE_E*2);
        #pragma unroll
        for (int ks = 0; ks < 2; ks++) {
            int koff = ks*16 + kofp;
            uint32_t ah[2][4], al[2][4];
            #pragma unroll
            for (int mt = 0; mt < 2; mt++) {
                uint32_t ad = tA + ((arow + mt*16) * TSTRIDE + koff) * 2;
                ldsm4(ah[mt], ad);
                ldsm4(al[mt], ad + TILE_E*2);
            }
            #pragma unroll
            for (int np = 0; np < 4; np++) {
                uint32_t bd = tA + 2*(TILE_E*2)
                            + ((brow + np*16) * TSTRIDE + koff) * 2;
                uint32_t bh[4], bl[4];
                ldsm4(bh, bd);
                ldsm4(bl, bd + TILE_E*2);
                #pragma unroll
                for (int mt = 0; mt < 2; mt++) {
                    mma_bf(acc[mt][np*2],   ah[mt], bh[0], bh[2]);
                    mma_bf(acc[mt][np*2+1], ah[mt], bh[1], bh[3]);
                    mma_bf(acc[mt][np*2],   ah[mt], bl[0], bl[2]);
                    mma_bf(acc[mt][np*2+1], ah[mt], bl[1], bl[3]);
                    mma_bf(acc[mt][np*2],   al[mt], bh[0], bh[2]);
                    mma_bf(acc[mt][np*2+1], al[mt], bh[1], bh[3]);
                }
            }
        }
        // NOTE: no barrier between compute(st) and store(st^1): different
        // buffers, and the trailing barrier of the previous iteration fences
        // the last readers of st^1. One barrier per iteration.
        if (more) r2s(sm, r, tid, st ^ 1);
        __syncthreads();
    }

    const int cbase = bn + wn * 64;
    if (EPI == 0) {
        #pragma unroll
        for (int mt = 0; mt < 2; mt++)
            #pragma unroll
            for (int half = 0; half < 2; half++) {
                int m = bm + wm*32 + mt*16 + (lane >> 2) + half*8;
                #pragma unroll
                for (int nt = 0; nt < 8; nt++) {
                    int c = cbase + nt*8 + (lane & 3)*2;
                    float2 v;
                    v.x = acc[mt][nt][half*2+0] + bias[c];
                    v.y = acc[mt][nt][half*2+1] + bias[c+1];
                    *(float2*)&C[(size_t)m * N + c] = v;
                }
            }
    } else {
        int which = cbase / DIM;
        int h = (cbase % DIM) >> 6;
        __half* bhp = (which == 0) ? g_qh : (which == 1) ? g_kh : g_vh;
        __half* blp = (which == 0) ? g_ql : (which == 1) ? g_kl : g_vl;
        const float qs = (which == 0) ? 0.125f : 1.0f;
        #pragma unroll
        for (int mt = 0; mt < 2; mt++)
            #pragma unroll
            for (int half = 0; half < 2; half++) {
                int m = bm + wm*32 + mt*16 + (lane >> 2) + half*8;
                int bb = m / NTOK, pos = m - bb * NTOK;
                size_t dof = ((size_t)(bb*HEADS + h) * NTOK + pos) * HD;
                __half* dsth = bhp + dof;
                __half* dstl = blp + dof;
                if (which < 2) {
                    #pragma unroll
                    for (int nt = 0; nt < 4; nt++) {
                        int d0 = nt*8 + (lane & 3)*2;
                        float rl[2], rh[2];
                        #pragma unroll
                        for (int j = 0; j < 2; j++) {
                            float vlo = acc[mt][nt][half*2+j]   + bias[cbase + d0 + j];
                            float vhi = acc[mt][nt+4][half*2+j] + bias[cbase + 32 + d0 + j];
                            float sn = g_sin[pos*32 + d0 + j];
                            float cs = g_cos[pos*32 + d0 + j];
                            rl[j] = (vlo*cs - vhi*sn) * qs;
                            rh[j] = (vhi*cs + vlo*sn) * qs;
                        }
                        uint32_t hh, ll;
                        split_h2(rl[0], rl[1], hh, ll);
                        *(uint32_t*)&dsth[d0] = hh; *(uint32_t*)&dstl[d0] = ll;
                        split_h2(rh[0], rh[1], hh, ll);
                        *(uint32_t*)&dsth[32 + d0] = hh; *(uint32_t*)&dstl[32 + d0] = ll;
                    }
                } else {
                    #pragma unroll
                    for (int nt = 0; nt < 8; nt++) {
                        int d = nt*8 + (lane & 3)*2;
                        float v0 = acc[mt][nt][half*2+0] + bias[cbase + d];
                        float v1 = acc[mt][nt][half*2+1] + bias[cbase + d + 1];
                        uint32_t hh, ll;
                        split_h2(v0, v1, hh, ll);
                        *(uint32_t*)&dsth[d] = hh; *(uint32_t*)&dstl[d] = ll;
                    }
                }
            }
    }
}

// ==================== attention: HMMA fp16-split flash (R6) ====
#define AST 72
#define ATTN_SMEM (128*AST*2*2)   // 36864 bytes

__global__ void __launch_bounds__(256, 2) attn_mma()
{
    extern __shared__ __align__(16) __half smh[];
    const uint32_t sb = smem_u32(smh);
    __half* sKh = smh;  __half* sKl = smh + 64*AST;
    __half* sVh = smh + 2*64*AST;  __half* sVl = smh + 3*64*AST;

    const int tid = threadIdx.x;
    const int lane = tid & 31, w = tid >> 5;
    const int l15 = lane & 15, l16 = lane >> 4;
    const int bh = blockIdx.y, q0 = blockIdx.x * 128;

    const __half* Qh = g_qh + ((size_t)bh * NTOK + q0) * HD;
    const __half* Ql = g_ql + ((size_t)bh * NTOK + q0) * HD;
    const __half* Kh = g_kh + (size_t)bh * NTOK * HD;
    const __half* Kl = g_kl + (size_t)bh * NTOK * HD;
    const __half* Vh = g_vh + (size_t)bh * NTOK * HD;
    const __half* Vl = g_vl + (size_t)bh * NTOK * HD;

    // ---- stage Q (hi/lo), move to A-fragments, then free the buffer ----
    #pragma unroll
    for (int t = 0; t < 8; t++) {
        int lin = t * 256 + tid;
        int arr = lin >> 10, rem = lin & 1023;
        int row = rem >> 3, c = (rem & 7) * 8;
        const __half* src = (arr ? Ql : Qh) + (size_t)row * HD + c;
        __half* dst = smh + arr * 128*AST + row * AST + c;
        *(uint4*)dst = *(const uint4*)src;
    }
    __syncthreads();
    uint32_t qfh[4][4], qfl[4][4];
    {
        uint32_t qa = sb + (((w*16 + l15) * AST) + l16*8) * 2;
        #pragma unroll
        for (int ks = 0; ks < 4; ks++) {
            ldsm4(qfh[ks], qa + ks*32);
            ldsm4(qfl[ks], qa + ks*32 + 128*AST*2);
        }
    }

    float acc[8][4];
    #pragma unroll
    for (int i = 0; i < 8; i++)
        #pragma unroll
        for (int j = 0; j < 4; j++) acc[i][j] = 0.0f;
    float m0 = -1e30f, m1 = -1e30f, l0 = 0.0f, l1 = 0.0f;

    const uint32_t kbase = sb + (l15 * AST + l16*8) * 2;
    const uint32_t vbase = sb + 2*64*AST*2 + (l15 * AST + l16*8) * 2;

    for (int t = 0; t < NTOK/64; t++) {
        const int k0 = t * 64;
        uint4 rv[8];
        #pragma unroll
        for (int i = 0; i < 8; i++) {
            int lin = i * 256 + tid;
            int arr = lin >> 9, rem = lin & 511;
            int row = rem >> 3, c = (rem & 7) * 8;
            const __half* src = (arr == 0 ? Kh : arr == 1 ? Kl : arr == 2 ? Vh : Vl)
                                + (size_t)(k0 + row) * HD + c;
            rv[i] = *(const uint4*)src;
        }
        __syncthreads();
        #pragma unroll
        for (int i = 0; i < 8; i++) {
            int lin = i * 256 + tid;
            int arr = lin >> 9, rem = lin & 511;
            int row = rem >> 3, c = (rem & 7) * 8;
            __half* dst = (arr == 0 ? sKh : arr == 1 ? sKl : arr == 2 ? sVh : sVl)
                          + row * AST + c;
            *(uint4*)dst = rv[i];
        }
        __syncthreads();

        // ---- S = Q K^T ----
        float s[8][4];
        #pragma unroll
        for (int i = 0; i < 8; i++)
            #pragma unroll
            for (int j = 0; j < 4; j++) s[i][j] = 0.0f;
        #pragma unroll
        for (int ks = 0; ks < 4; ks++) {
            #pragma unroll
            for (int nbp = 0; nbp < 8; nbp += 2) {
                uint32_t kh4[4], kl4[4];
                uint32_t ka = kbase + (nbp*8*AST + ks*16) * 2;
                ldsm4(kh4, ka);
                ldsm4(kl4, ka + 64*AST*2);
                mma_fp(s[nbp],   qfh[ks], kh4[0], kh4[2]);
                mma_fp(s[nbp+1], qfh[ks], kh4[1], kh4[3]);
                mma_fp(s[nbp],   qfl[ks], kh4[0], kh4[2]);
                mma_fp(s[nbp+1], qfl[ks], kh4[1], kh4[3]);
                mma_fp(s[nbp],   qfh[ks], kl4[0], kl4[2]);
                mma_fp(s[nbp+1], qfh[ks], kl4[1], kl4[3]);
            }
        }

        // ---- online softmax ----
        float mx0 = -1e30f, mx1 = -1e30f;
        #pragma unroll
        for (int i = 0; i < 8; i++) {
            mx0 = fmaxf(mx0, fmaxf(s[i][0], s[i][1]));
            mx1 = fmaxf(mx1, fmaxf(s[i][2], s[i][3]));
        }
        mx0 = fmaxf(mx0, __shfl_xor_sync(0xffffffffu, mx0, 1));
        mx0 = fmaxf(mx0, __shfl_xor_sync(0xffffffffu, mx0, 2));
        mx1 = fmaxf(mx1, __shfl_xor_sync(0xffffffffu, mx1, 1));
        mx1 = fmaxf(mx1, __shfl_xor_sync(0xffffffffu, mx1, 2));
        float nm0 = fmaxf(m0, mx0), nm1 = fmaxf(m1, mx1);
        float f0 = fast_exp(m0 - nm0), f1 = fast_exp(m1 - nm1);
        m0 = nm0; m1 = nm1;
        float sum0 = 0.0f, sum1 = 0.0f;
        #pragma unroll
        for (int i = 0; i < 8; i++) {
            s[i][0] = fast_exp(s[i][0] - nm0); sum0 += s[i][0];
            s[i][1] = fast_exp(s[i][1] - nm0); sum0 += s[i][1];
            s[i][2] = fast_exp(s[i][2] - nm1); sum1 += s[i][2];
            s[i][3] = fast_exp(s[i][3] - nm1); sum1 += s[i][3];
        }
        sum0 += __shfl_xor_sync(0xffffffffu, sum0, 1);
        sum0 += __shfl_xor_sync(0xffffffffu, sum0, 2);
        sum1 += __shfl_xor_sync(0xffffffffu, sum1, 1);
        sum1 += __shfl_xor_sync(0xffffffffu, sum1, 2);
        l0 = l0 * f0 + sum0;
        l1 = l1 * f1 + sum1;
        #pragma unroll
        for (int i = 0; i < 8; i++) {
            acc[i][0] *= f0; acc[i][1] *= f0;
            acc[i][2] *= f1; acc[i][3] *= f1;
        }

        // ---- P -> fp16 hi/lo A-fragments ----
        uint32_t aph[4][4], apl[4][4];
        #pragma unroll
        for (int ks = 0; ks < 4; ks++) {
            int n0 = 2*ks, n1 = 2*ks + 1;
            split_h2(s[n0][0], s[n0][1], aph[ks][0], apl[ks][0]);
            split_h2(s[n0][2], s[n0][3], aph[ks][1], apl[ks][1]);
            split_h2(s[n1][0], s[n1][1], aph[ks][2], apl[ks][2]);
            split_h2(s[n1][2], s[n1][3], aph[ks][3], apl[ks][3]);
        }

        // ---- O += P V ----
        #pragma unroll
        for (int ks = 0; ks < 4; ks++) {
            #pragma unroll
            for (int nbp = 0; nbp < 8; nbp += 2) {
                uint32_t vh4[4], vl4[4];
                uint32_t va = vbase + (ks*16*AST + nbp*8) * 2;
                ldsm4t(vh4, va);
                ldsm4t(vl4, va + 64*AST*2);
                mma_fp(acc[nbp],   aph[ks], vh4[0], vh4[1]);
                mma_fp(acc[nbp+1], aph[ks], vh4[2], vh4[3]);
                mma_fp(acc[nbp],   apl[ks], vh4[0], vh4[1]);
                mma_fp(acc[nbp+1], apl[ks], vh4[2], vh4[3]);
                mma_fp(acc[nbp],   aph[ks], vl4[0], vl4[1]);
                mma_fp(acc[nbp+1], aph[ks], vl4[2], vl4[3]);
            }
        }
    }

    // ---- normalize + write O as bf16 hi/lo, [b, n, h*64 + d] ----
    float inv0 = 1.0f / l0, inv1 = 1.0f / l1;
    int b = bh / HEADS, h = bh - b * HEADS;
    int r0 = q0 + w*16 + (lane >> 2);
    int col = h*HD + (lane & 3)*2;
    #pragma unroll
    for (int nb = 0; nb < 8; nb++) {
        size_t o0 = ((size_t)(b*NTOK + r0))     * DIM + col + nb*8;
        size_t o1 = ((size_t)(b*NTOK + r0 + 8)) * DIM + col + nb*8;
        float a0 = acc[nb][0]*inv0, a1 = acc[nb][1]*inv0;
        float a2 = acc[nb][2]*inv1, a3 = acc[nb][3]*inv1;
        __nv_bfloat162 hh, ll;
        hh = __floats2bfloat162_rn(a0, a1);
        ll = __floats2bfloat162_rn(a0 - __bfloat162float(hh.x),
                                   a1 - __bfloat162float(hh.y));
        *(__nv_bfloat162*)&g_ohh[o0] = hh;
        *(__nv_bfloat162*)&g_oll[o0] = ll;
        hh = __floats2bfloat162_rn(a2, a3);
        ll = __floats2bfloat162_rn(a2 - __bfloat162float(hh.x),
                                   a3 - __bfloat162float(hh.y));
        *(__nv_bfloat162*)&g_ohh[o1] = hh;
        *(__nv_bfloat162*)&g_oll[o1] = ll;
    }
}

// ==================== launcher ====================
extern "C" void kernel_launch(void* const* d_in, const int* in_sizes, int n_in,
                              void* d_out, int out_size)
{
    const float* x      = (const float*)d_in[0];
    const float* w_qkv  = (const float*)d_in[1];
    const float* b_qkv  = (const float*)d_in[2];
    const float* w_proj = (const float*)d_in[3];
    const float* b_proj = (const float*)d_in[4];
    float* out = (float*)d_out;

    void *xh, *xl, *wqh, *wql, *wph, *wpl, *ohh, *oll;
    cudaGetSymbolAddress(&xh,  g_xh);  cudaGetSymbolAddress(&xl,  g_xl);
    cudaGetSymbolAddress(&wqh, g_wqh); cudaGetSymbolAddress(&wql, g_wql);
    cudaGetSymbolAddress(&wph, g_wph); cudaGetSymbolAddress(&wpl, g_wpl);
    cudaGetSymbolAddress(&ohh, g_ohh); cudaGetSymbolAddress(&oll, g_oll);

    cudaFuncSetAttribute(gemm_mma<0>, cudaFuncAttributeMaxDynamicSharedMemorySize,
                         GEMM_SMEM_B);
    cudaFuncSetAttribute(gemm_mma<1>, cudaFuncAttributeMaxDynamicSharedMemorySize,
                         GEMM_SMEM_B);
    cudaFuncSetAttribute(attn_mma, cudaFuncAttributeMaxDynamicSharedMemorySize,
                         ATTN_SMEM);

    split_kernel<<<(MROWS*DIM/4 + 255)/256, 256>>>(
        x, (__nv_bfloat16*)xh, (__nv_bfloat16*)xl, MROWS*DIM/4);
    split_kernel<<<(3*DIM*DIM/4 + 255)/256, 256>>>(
        w_qkv, (__nv_bfloat16*)wqh, (__nv_bfloat16*)wql, 3*DIM*DIM/4);
    split_kernel<<<(DIM*DIM/4 + 255)/256, 256>>>(
        w_proj, (__nv_bfloat16*)wph, (__nv_bfloat16*)wpl, DIM*DIM/4);
    rope_tab_kernel<<<(NTOK*32 + 255)/256, 256>>>();

    // 1) QKV GEMM + bias + RoPE + fp16 hi/lo scatter
    gemm_mma<1><<<dim3(3*DIM/128, MROWS/128), 256, GEMM_SMEM_B>>>(
        (const __nv_bfloat16*)xh, (const __nv_bfloat16*)xl,
        (const __nv_bfloat16*)wqh, (const __nv_bfloat16*)wql,
        b_qkv, nullptr, MROWS, 3*DIM, DIM);

    // 2) attention (HMMA fp16-split flash)
    attn_mma<<<dim3(NTOK/128, BHC), 256, ATTN_SMEM>>>();

    // 3) output projection -> d_out
    gemm_mma<0><<<dim3(DIM/128, MROWS/128), 256, GEMM_SMEM_B>>>(
        (const __nv_bfloat16*)ohh, (const __nv_bfloat16*)oll,
        (const __nv_bfloat16*)wph, (const __nv_bfloat16*)wpl,
        b_proj, out, MROWS, DIM, DIM);
}

// round 9
// speedup vs baseline: 1.5793x; 1.1936x over previous
#include <cuda_runtime.h>
#include <cuda_bf16.h>
#include <cuda_fp16.h>
#include <math.h>
#include <stdint.h>

#define DIM   768
#define HEADS 12
#define HD    64
#define B_    2
#define WW    48
#define NTOK  2304
#define BHC   24
#define MROWS 4608

// -------- scratch (device globals; no allocation allowed) --------
__device__ __half g_qh[BHC*NTOK*HD], g_ql[BHC*NTOK*HD];
__device__ __half g_kh[BHC*NTOK*HD], g_kl[BHC*NTOK*HD];
__device__ __half g_vh[BHC*NTOK*HD], g_vl[BHC*NTOK*HD];
__device__ __nv_bfloat16 g_xh[MROWS*DIM],  g_xl[MROWS*DIM];
__device__ __nv_bfloat16 g_wqh[3*DIM*DIM], g_wql[3*DIM*DIM];
__device__ __nv_bfloat16 g_wph[DIM*DIM],   g_wpl[DIM*DIM];
__device__ __nv_bfloat16 g_ohh[MROWS*DIM], g_oll[MROWS*DIM];
__device__ float g_sin[NTOK*32], g_cos[NTOK*32];

// ==================== helpers ====================
__device__ __forceinline__ uint32_t smem_u32(const void* p) {
    uint32_t a;
    asm("{ .reg .u64 t; cvta.to.shared.u64 t, %1; cvt.u32.u64 %0, t; }" : "=r"(a) : "l"(p));
    return a;
}
__device__ __forceinline__ void ldsm4(uint32_t* r, uint32_t addr) {
    asm volatile("ldmatrix.sync.aligned.m8n8.x4.shared.b16 {%0,%1,%2,%3}, [%4];"
                 : "=r"(r[0]), "=r"(r[1]), "=r"(r[2]), "=r"(r[3]) : "r"(addr));
}
__device__ __forceinline__ void ldsm4t(uint32_t* r, uint32_t addr) {
    asm volatile("ldmatrix.sync.aligned.m8n8.x4.trans.shared.b16 {%0,%1,%2,%3}, [%4];"
                 : "=r"(r[0]), "=r"(r[1]), "=r"(r[2]), "=r"(r[3]) : "r"(addr));
}
__device__ __forceinline__ void mma_bf(float* d, const uint32_t* a,
                                       uint32_t b0, uint32_t b1) {
    asm volatile(
        "mma.sync.aligned.m16n8k16.row.col.f32.bf16.bf16.f32 "
        "{%0,%1,%2,%3}, {%4,%5,%6,%7}, {%8,%9}, {%0,%1,%2,%3};"
        : "+f"(d[0]), "+f"(d[1]), "+f"(d[2]), "+f"(d[3])
        : "r"(a[0]), "r"(a[1]), "r"(a[2]), "r"(a[3]), "r"(b0), "r"(b1));
}
__device__ __forceinline__ void mma_fp(float* d, const uint32_t* a,
                                       uint32_t b0, uint32_t b1) {
    asm volatile(
        "mma.sync.aligned.m16n8k16.row.col.f32.f16.f16.f32 "
        "{%0,%1,%2,%3}, {%4,%5,%6,%7}, {%8,%9}, {%0,%1,%2,%3};"
        : "+f"(d[0]), "+f"(d[1]), "+f"(d[2]), "+f"(d[3])
        : "r"(a[0]), "r"(a[1]), "r"(a[2]), "r"(a[3]), "r"(b0), "r"(b1));
}
// fast e^x on FMA/ALU pipes (no MUFU). |rel err| ~1e-7, x clamped >= -80.
__device__ __forceinline__ float fast_exp(float x) {
    x = fmaxf(x, -80.0f);
    float y = fmaf(x, 1.4426950409f, 12582912.0f);
    float z = y - 12582912.0f;
    int   n = __float_as_int(y) - 0x4B400000;
    float f = fmaf(x, 1.4426950409f, -z);
    float p = 1.3333558e-3f;
    p = fmaf(p, f, 9.6181291e-3f);
    p = fmaf(p, f, 5.5504109e-2f);
    p = fmaf(p, f, 2.4022651e-1f);
    p = fmaf(p, f, 6.9314718e-1f);
    p = fmaf(p, f, 1.0f);
    return __int_as_float(__float_as_int(p) + (n << 23));
}
__device__ __forceinline__ void split_h2(float a, float b,
                                         uint32_t& hi, uint32_t& lo) {
    __half2 hh = __floats2half2_rn(a, b);
    __half2 ll = __floats2half2_rn(a - __low2float(hh), b - __high2float(hh));
    hi = *(uint32_t*)&hh;
    lo = *(uint32_t*)&ll;
}

// ==================== prep kernels ====================
__global__ void __launch_bounds__(256) split_kernel(
    const float* __restrict__ src, __nv_bfloat16* __restrict__ hi,
    __nv_bfloat16* __restrict__ lo, int n4)
{
    int i = blockIdx.x * 256 + threadIdx.x;
    if (i >= n4) return;
    float4 v = ((const float4*)src)[i];
    float f[4] = {v.x, v.y, v.z, v.w};
    __nv_bfloat16 h[4], l[4];
    #pragma unroll
    for (int j = 0; j < 4; j++) {
        h[j] = __float2bfloat16(f[j]);
        l[j] = __float2bfloat16(f[j] - __bfloat162float(h[j]));
    }
    ((__nv_bfloat162*)hi)[2*i]   = __halves2bfloat162(h[0], h[1]);
    ((__nv_bfloat162*)hi)[2*i+1] = __halves2bfloat162(h[2], h[3]);
    ((__nv_bfloat162*)lo)[2*i]   = __halves2bfloat162(l[0], l[1]);
    ((__nv_bfloat162*)lo)[2*i+1] = __halves2bfloat162(l[2], l[3]);
}

__global__ void __launch_bounds__(256) rope_tab_kernel()
{
    int idx = blockIdx.x * 256 + threadIdx.x;
    if (idx >= NTOK * 32) return;
    int n = idx >> 5, j = idx & 31;
    int axis = j >> 4, p = j & 15;
    int y = n / WW, x = n - y * WW;
    float idxf  = axis ? (float)x : (float)y;
    float coord = 2.0f * ((idxf + 0.5f) / 48.0f) - 1.0f;
    float invp  = exp2f(-(float)p * 0.41524101186092607f);  // 100^(-p/16)
    float sn, cs; sincosf(6.283185307179586f * coord * invp, &sn, &cs);
    g_sin[idx] = sn; g_cos[idx] = cs;
}

// ==================== mma.sync bf16-split GEMM ====================
#define TSTRIDE 40
#define TILE_E  (128*TSTRIDE)
#define GEMM_SMEM_B (8*TILE_E*2)

__device__ __forceinline__ void g2r(uint4* r,
    const __nv_bfloat16* Ah, const __nv_bfloat16* Al,
    const __nv_bfloat16* Bh, const __nv_bfloat16* Bl,
    int bm, int bn, int K, int k0, int tid)
{
    #pragma unroll
    for (int p = 0; p < 2; p++) {
        int id = p * 256 + tid;
        int row = id >> 2, kc = id & 3;
        size_t oA = (size_t)(bm + row) * K + k0 + kc * 8;
        size_t oB = (size_t)(bn + row) * K + k0 + kc * 8;
        r[0+p] = *(const uint4*)&Ah[oA];
        r[2+p] = *(const uint4*)&Al[oA];
        r[4+p] = *(const uint4*)&Bh[oB];
        r[6+p] = *(const uint4*)&Bl[oB];
    }
}
__device__ __forceinline__ void r2s(__nv_bfloat16* sm, const uint4* r,
                                    int tid, int st)
{
    #pragma unroll
    for (int p = 0; p < 2; p++) {
        int id = p * 256 + tid;
        int off = (id >> 2) * TSTRIDE + (id & 3) * 8;
        #pragma unroll
        for (int t = 0; t < 4; t++)
            *(uint4*)&sm[(st*4 + t) * TILE_E + off] = r[t*2 + p];
    }
}

template<int EPI>
__global__ void __launch_bounds__(256, 1) gemm_mma(
    const __nv_bfloat16* __restrict__ Ah, const __nv_bfloat16* __restrict__ Al,
    const __nv_bfloat16* __restrict__ Bh, const __nv_bfloat16* __restrict__ Bl,
    const float* __restrict__ bias, float* __restrict__ C, int M, int N, int K)
{
    extern __shared__ __align__(16) __nv_bfloat16 sm[];
    const uint32_t sbase = smem_u32(sm);
    const int tid = threadIdx.x;
    const int lane = tid & 31, wid = tid >> 5;
    const int wm = wid & 3, wn = wid >> 2;
    const int bm = blockIdx.y * 128, bn = blockIdx.x * 128;
    const int piece = lane >> 3, pr = lane & 7;

    float acc[2][8][4];
    #pragma unroll
    for (int i = 0; i < 2; i++)
        #pragma unroll
        for (int j = 0; j < 8; j++)
            #pragma unroll
            for (int k = 0; k < 4; k++) acc[i][j][k] = 0.0f;

    const int nit = K >> 5;
    uint4 r[8];
    g2r(r, Ah, Al, Bh, Bl, bm, bn, K, 0, tid);
    r2s(sm, r, tid, 0);
    __syncthreads();

    const int arow = wm*32 + (piece & 1)*8 + pr;
    const int brow = wn*64 + (piece & 1)*8 + pr;
    const int kofp = (piece >> 1) * 8;

    for (int it = 0; it < nit; it++) {
        int st = it & 1;
        bool more = (it + 1) < nit;
        if (more) g2r(r, Ah, Al, Bh, Bl, bm, bn, K, (it + 1) << 5, tid);

        uint32_t tA = sbase + (uint32_t)(st*4) * (TILE_E*2);
        #pragma unroll
        for (int ks = 0; ks < 2; ks++) {
            int koff = ks*16 + kofp;
            uint32_t ah[2][4], al[2][4];
            #pragma unroll
            for (int mt = 0; mt < 2; mt++) {
                uint32_t ad = tA + ((arow + mt*16) * TSTRIDE + koff) * 2;
                ldsm4(ah[mt], ad);
                ldsm4(al[mt], ad + TILE_E*2);
            }
            #pragma unroll
            for (int np = 0; np < 4; np++) {
                uint32_t bd = tA + 2*(TILE_E*2)
                            + ((brow + np*16) * TSTRIDE + koff) * 2;
                uint32_t bh[4], bl[4];
                ldsm4(bh, bd);
                ldsm4(bl, bd + TILE_E*2);
                #pragma unroll
                for (int mt = 0; mt < 2; mt++) {
                    mma_bf(acc[mt][np*2],   ah[mt], bh[0], bh[2]);
                    mma_bf(acc[mt][np*2+1], ah[mt], bh[1], bh[3]);
                    mma_bf(acc[mt][np*2],   ah[mt], bl[0], bl[2]);
                    mma_bf(acc[mt][np*2+1], ah[mt], bl[1], bl[3]);
                    mma_bf(acc[mt][np*2],   al[mt], bh[0], bh[2]);
                    mma_bf(acc[mt][np*2+1], al[mt], bh[1], bh[3]);
                }
            }
        }
        // Single barrier per iteration: storing st^1 while computing st is
        // safe (different buffer; last readers of st^1 were fenced by the
        // previous iteration's trailing barrier).
        if (more) r2s(sm, r, tid, st ^ 1);
        __syncthreads();
    }

    const int cbase = bn + wn * 64;
    if (EPI == 0) {
        #pragma unroll
        for (int mt = 0; mt < 2; mt++)
            #pragma unroll
            for (int half = 0; half < 2; half++) {
                int m = bm + wm*32 + mt*16 + (lane >> 2) + half*8;
                #pragma unroll
                for (int nt = 0; nt < 8; nt++) {
                    int c = cbase + nt*8 + (lane & 3)*2;
                    float2 v;
                    v.x = acc[mt][nt][half*2+0] + bias[c];
                    v.y = acc[mt][nt][half*2+1] + bias[c+1];
                    *(float2*)&C[(size_t)m * N + c] = v;
                }
            }
    } else {
        int which = cbase / DIM;
        int h = (cbase % DIM) >> 6;
        __half* bhp = (which == 0) ? g_qh : (which == 1) ? g_kh : g_vh;
        __half* blp = (which == 0) ? g_ql : (which == 1) ? g_kl : g_vl;
        const float qs = (which == 0) ? 0.125f : 1.0f;
        #pragma unroll
        for (int mt = 0; mt < 2; mt++)
            #pragma unroll
            for (int half = 0; half < 2; half++) {
                int m = bm + wm*32 + mt*16 + (lane >> 2) + half*8;
                int bb = m / NTOK, pos = m - bb * NTOK;
                size_t dof = ((size_t)(bb*HEADS + h) * NTOK + pos) * HD;
                __half* dsth = bhp + dof;
                __half* dstl = blp + dof;
                if (which < 2) {
                    #pragma unroll
                    for (int nt = 0; nt < 4; nt++) {
                        int d0 = nt*8 + (lane & 3)*2;
                        float rl[2], rh[2];
                        #pragma unroll
                        for (int j = 0; j < 2; j++) {
                            float vlo = acc[mt][nt][half*2+j]   + bias[cbase + d0 + j];
                            float vhi = acc[mt][nt+4][half*2+j] + bias[cbase + 32 + d0 + j];
                            float sn = g_sin[pos*32 + d0 + j];
                            float cs = g_cos[pos*32 + d0 + j];
                            rl[j] = (vlo*cs - vhi*sn) * qs;
                            rh[j] = (vhi*cs + vlo*sn) * qs;
                        }
                        uint32_t hh, ll;
                        split_h2(rl[0], rl[1], hh, ll);
                        *(uint32_t*)&dsth[d0] = hh; *(uint32_t*)&dstl[d0] = ll;
                        split_h2(rh[0], rh[1], hh, ll);
                        *(uint32_t*)&dsth[32 + d0] = hh; *(uint32_t*)&dstl[32 + d0] = ll;
                    }
                } else {
                    #pragma unroll
                    for (int nt = 0; nt < 8; nt++) {
                        int d = nt*8 + (lane & 3)*2;
                        float v0 = acc[mt][nt][half*2+0] + bias[cbase + d];
                        float v1 = acc[mt][nt][half*2+1] + bias[cbase + d + 1];
                        uint32_t hh, ll;
                        split_h2(v0, v1, hh, ll);
                        *(uint32_t*)&dsth[d] = hh; *(uint32_t*)&dstl[d] = ll;
                    }
                }
            }
    }
}

// ==================== attention: HMMA fp16-split flash (R6) ====
#define AST 72
#define ATTN_SMEM (128*AST*2*2)   // 36864 bytes

__global__ void __launch_bounds__(256, 2) attn_mma()
{
    extern __shared__ __align__(16) __half smh[];
    const uint32_t sb = smem_u32(smh);
    __half* sKh = smh;  __half* sKl = smh + 64*AST;
    __half* sVh = smh + 2*64*AST;  __half* sVl = smh + 3*64*AST;

    const int tid = threadIdx.x;
    const int lane = tid & 31, w = tid >> 5;
    const int l15 = lane & 15, l16 = lane >> 4;
    const int bh = blockIdx.y, q0 = blockIdx.x * 128;

    const __half* Qh = g_qh + ((size_t)bh * NTOK + q0) * HD;
    const __half* Ql = g_ql + ((size_t)bh * NTOK + q0) * HD;
    const __half* Kh = g_kh + (size_t)bh * NTOK * HD;
    const __half* Kl = g_kl + (size_t)bh * NTOK * HD;
    const __half* Vh = g_vh + (size_t)bh * NTOK * HD;
    const __half* Vl = g_vl + (size_t)bh * NTOK * HD;

    // ---- stage Q (hi/lo), move to A-fragments, then free the buffer ----
    #pragma unroll
    for (int t = 0; t < 8; t++) {
        int lin = t * 256 + tid;
        int arr = lin >> 10, rem = lin & 1023;
        int row = rem >> 3, c = (rem & 7) * 8;
        const __half* src = (arr ? Ql : Qh) + (size_t)row * HD + c;
        __half* dst = smh + arr * 128*AST + row * AST + c;
        *(uint4*)dst = *(const uint4*)src;
    }
    __syncthreads();
    uint32_t qfh[4][4], qfl[4][4];
    {
        uint32_t qa = sb + (((w*16 + l15) * AST) + l16*8) * 2;
        #pragma unroll
        for (int ks = 0; ks < 4; ks++) {
            ldsm4(qfh[ks], qa + ks*32);
            ldsm4(qfl[ks], qa + ks*32 + 128*AST*2);
        }
    }

    float acc[8][4];
    #pragma unroll
    for (int i = 0; i < 8; i++)
        #pragma unroll
        for (int j = 0; j < 4; j++) acc[i][j] = 0.0f;
    float m0 = -1e30f, m1 = -1e30f, l0 = 0.0f, l1 = 0.0f;

    const uint32_t kbase = sb + (l15 * AST + l16*8) * 2;
    const uint32_t vbase = sb + 2*64*AST*2 + (l15 * AST + l16*8) * 2;

    for (int t = 0; t < NTOK/64; t++) {
        const int k0 = t * 64;
        uint4 rv[8];
        #pragma unroll
        for (int i = 0; i < 8; i++) {
            int lin = i * 256 + tid;
            int arr = lin >> 9, rem = lin & 511;
            int row = rem >> 3, c = (rem & 7) * 8;
            const __half* src = (arr == 0 ? Kh : arr == 1 ? Kl : arr == 2 ? Vh : Vl)
                                + (size_t)(k0 + row) * HD + c;
            rv[i] = *(const uint4*)src;
        }
        __syncthreads();
        #pragma unroll
        for (int i = 0; i < 8; i++) {
            int lin = i * 256 + tid;
            int arr = lin >> 9, rem = lin & 511;
            int row = rem >> 3, c = (rem & 7) * 8;
            __half* dst = (arr == 0 ? sKh : arr == 1 ? sKl : arr == 2 ? sVh : sVl)
                          + row * AST + c;
            *(uint4*)dst = rv[i];
        }
        __syncthreads();

        // ---- S = Q K^T ----
        float s[8][4];
        #pragma unroll
        for (int i = 0; i < 8; i++)
            #pragma unroll
            for (int j = 0; j < 4; j++) s[i][j] = 0.0f;
        #pragma unroll
        for (int ks = 0; ks < 4; ks++) {
            #pragma unroll
            for (int nbp = 0; nbp < 8; nbp += 2) {
                uint32_t kh4[4], kl4[4];
                uint32_t ka = kbase + (nbp*8*AST + ks*16) * 2;
                ldsm4(kh4, ka);
                ldsm4(kl4, ka + 64*AST*2);
                mma_fp(s[nbp],   qfh[ks], kh4[0], kh4[2]);
                mma_fp(s[nbp+1], qfh[ks], kh4[1], kh4[3]);
                mma_fp(s[nbp],   qfl[ks], kh4[0], kh4[2]);
                mma_fp(s[nbp+1], qfl[ks], kh4[1], kh4[3]);
                mma_fp(s[nbp],   qfh[ks], kl4[0], kl4[2]);
                mma_fp(s[nbp+1], qfh[ks], kl4[1], kl4[3]);
            }
        }

        // ---- online softmax ----
        float mx0 = -1e30f, mx1 = -1e30f;
        #pragma unroll
        for (int i = 0; i < 8; i++) {
            mx0 = fmaxf(mx0, fmaxf(s[i][0], s[i][1]));
            mx1 = fmaxf(mx1, fmaxf(s[i][2], s[i][3]));
        }
        mx0 = fmaxf(mx0, __shfl_xor_sync(0xffffffffu, mx0, 1));
        mx0 = fmaxf(mx0, __shfl_xor_sync(0xffffffffu, mx0, 2));
        mx1 = fmaxf(mx1, __shfl_xor_sync(0xffffffffu, mx1, 1));
        mx1 = fmaxf(mx1, __shfl_xor_sync(0xffffffffu, mx1, 2));
        float nm0 = fmaxf(m0, mx0), nm1 = fmaxf(m1, mx1);
        float f0 = fast_exp(m0 - nm0), f1 = fast_exp(m1 - nm1);
        m0 = nm0; m1 = nm1;
        float sum0 = 0.0f, sum1 = 0.0f;
        #pragma unroll
        for (int i = 0; i < 8; i++) {
            s[i][0] = fast_exp(s[i][0] - nm0); sum0 += s[i][0];
            s[i][1] = fast_exp(s[i][1] - nm0); sum0 += s[i][1];
            s[i][2] = fast_exp(s[i][2] - nm1); sum1 += s[i][2];
            s[i][3] = fast_exp(s[i][3] - nm1); sum1 += s[i][3];
        }
        sum0 += __shfl_xor_sync(0xffffffffu, sum0, 1);
        sum0 += __shfl_xor_sync(0xffffffffu, sum0, 2);
        sum1 += __shfl_xor_sync(0xffffffffu, sum1, 1);
        sum1 += __shfl_xor_sync(0xffffffffu, sum1, 2);
        l0 = l0 * f0 + sum0;
        l1 = l1 * f1 + sum1;
        #pragma unroll
        for (int i = 0; i < 8; i++) {
            acc[i][0] *= f0; acc[i][1] *= f0;
            acc[i][2] *= f1; acc[i][3] *= f1;
        }

        // ---- P -> fp16 hi/lo A-fragments ----
        uint32_t aph[4][4], apl[4][4];
        #pragma unroll
        for (int ks = 0; ks < 4; ks++) {
            int n0 = 2*ks, n1 = 2*ks + 1;
            split_h2(s[n0][0], s[n0][1], aph[ks][0], apl[ks][0]);
            split_h2(s[n0][2], s[n0][3], aph[ks][1], apl[ks][1]);
            split_h2(s[n1][0], s[n1][1], aph[ks][2], apl[ks][2]);
            split_h2(s[n1][2], s[n1][3], aph[ks][3], apl[ks][3]);
        }

        // ---- O += P V ----
        #pragma unroll
        for (int ks = 0; ks < 4; ks++) {
            #pragma unroll
            for (int nbp = 0; nbp < 8; nbp += 2) {
                uint32_t vh4[4], vl4[4];
                uint32_t va = vbase + (ks*16*AST + nbp*8) * 2;
                ldsm4t(vh4, va);
                ldsm4t(vl4, va + 64*AST*2);
                mma_fp(acc[nbp],   aph[ks], vh4[0], vh4[1]);
                mma_fp(acc[nbp+1], aph[ks], vh4[2], vh4[3]);
                mma_fp(acc[nbp],   apl[ks], vh4[0], vh4[1]);
                mma_fp(acc[nbp+1], apl[ks], vh4[2], vh4[3]);
                mma_fp(acc[nbp],   aph[ks], vl4[0], vl4[1]);
                mma_fp(acc[nbp+1], aph[ks], vl4[2], vl4[3]);
            }
        }
    }

    // ---- normalize + write O as bf16 hi/lo, [b, n, h*64 + d] ----
    float inv0 = 1.0f / l0, inv1 = 1.0f / l1;
    int b = bh / HEADS, h = bh - b * HEADS;
    int r0 = q0 + w*16 + (lane >> 2);
    int col = h*HD + (lane & 3)*2;
    #pragma unroll
    for (int nb = 0; nb < 8; nb++) {
        size_t o0 = ((size_t)(b*NTOK + r0))     * DIM + col + nb*8;
        size_t o1 = ((size_t)(b*NTOK + r0 + 8)) * DIM + col + nb*8;
        float a0 = acc[nb][0]*inv0, a1 = acc[nb][1]*inv0;
        float a2 = acc[nb][2]*inv1, a3 = acc[nb][3]*inv1;
        __nv_bfloat162 hh, ll;
        hh = __floats2bfloat162_rn(a0, a1);
        ll = __floats2bfloat162_rn(a0 - __bfloat162float(hh.x),
                                   a1 - __bfloat162float(hh.y));
        *(__nv_bfloat162*)&g_ohh[o0] = hh;
        *(__nv_bfloat162*)&g_oll[o0] = ll;
        hh = __floats2bfloat162_rn(a2, a3);
        ll = __floats2bfloat162_rn(a2 - __bfloat162float(hh.x),
                                   a3 - __bfloat162float(hh.y));
        *(__nv_bfloat162*)&g_ohh[o1] = hh;
        *(__nv_bfloat162*)&g_oll[o1] = ll;
    }
}

// ==================== launcher ====================
extern "C" void kernel_launch(void* const* d_in, const int* in_sizes, int n_in,
                              void* d_out, int out_size)
{
    const float* x      = (const float*)d_in[0];
    const float* w_qkv  = (const float*)d_in[1];
    const float* b_qkv  = (const float*)d_in[2];
    const float* w_proj = (const float*)d_in[3];
    const float* b_proj = (const float*)d_in[4];
    float* out = (float*)d_out;

    void *xh, *xl, *wqh, *wql, *wph, *wpl, *ohh, *oll;
    cudaGetSymbolAddress(&xh,  g_xh);  cudaGetSymbolAddress(&xl,  g_xl);
    cudaGetSymbolAddress(&wqh, g_wqh); cudaGetSymbolAddress(&wql, g_wql);
    cudaGetSymbolAddress(&wph, g_wph); cudaGetSymbolAddress(&wpl, g_wpl);
    cudaGetSymbolAddress(&ohh, g_ohh); cudaGetSymbolAddress(&oll, g_oll);

    cudaFuncSetAttribute(gemm_mma<0>, cudaFuncAttributeMaxDynamicSharedMemorySize,
                         GEMM_SMEM_B);
    cudaFuncSetAttribute(gemm_mma<1>, cudaFuncAttributeMaxDynamicSharedMemorySize,
                         GEMM_SMEM_B);
    cudaFuncSetAttribute(attn_mma, cudaFuncAttributeMaxDynamicSharedMemorySize,
                         ATTN_SMEM);

    split_kernel<<<(MROWS*DIM/4 + 255)/256, 256>>>(
        x, (__nv_bfloat16*)xh, (__nv_bfloat16*)xl, MROWS*DIM/4);
    split_kernel<<<(3*DIM*DIM/4 + 255)/256, 256>>>(
        w_qkv, (__nv_bfloat16*)wqh, (__nv_bfloat16*)wql, 3*DIM*DIM/4);
    split_kernel<<<(DIM*DIM/4 + 255)/256, 256>>>(
        w_proj, (__nv_bfloat16*)wph, (__nv_bfloat16*)wpl, DIM*DIM/4);
    rope_tab_kernel<<<(NTOK*32 + 255)/256, 256>>>();

    // 1) QKV GEMM + bias + RoPE + fp16 hi/lo scatter
    gemm_mma<1><<<dim3(3*DIM/128, MROWS/128), 256, GEMM_SMEM_B>>>(
        (const __nv_bfloat16*)xh, (const __nv_bfloat16*)xl,
        (const __nv_bfloat16*)wqh, (const __nv_bfloat16*)wql,
        b_qkv, nullptr, MROWS, 3*DIM, DIM);

    // 2) attention (HMMA fp16-split flash)
    attn_mma<<<dim3(NTOK/128, BHC), 256, ATTN_SMEM>>>();

    // 3) output projection -> d_out
    gemm_mma<0><<<dim3(DIM/128, MROWS/128), 256, GEMM_SMEM_B>>>(
        (const __nv_bfloat16*)ohh, (const __nv_bfloat16*)oll,
        (const __nv_bfloat16*)wph, (const __nv_bfloat16*)wpl,
        b_proj, out, MROWS, DIM, DIM);
}

// round 10
// speedup vs baseline: 1.7466x; 1.1059x over previous
#include <cuda_runtime.h>
#include <cuda_bf16.h>
#include <cuda_fp16.h>
#include <math.h>
#include <stdint.h>

#define DIM   768
#define HEADS 12
#define HD    64
#define B_    2
#define WW    48
#define NTOK  2304
#define BHC   24
#define MROWS 4608

// -------- scratch (device globals; no allocation allowed) --------
__device__ __half g_qh[BHC*NTOK*HD], g_ql[BHC*NTOK*HD];
__device__ __half g_kh[BHC*NTOK*HD];          // K: fp16 only
__device__ __half g_vh[BHC*NTOK*HD];          // V: fp16 only
__device__ __nv_bfloat16 g_xh[MROWS*DIM],  g_xl[MROWS*DIM];
__device__ __nv_bfloat16 g_wqh[3*DIM*DIM], g_wql[3*DIM*DIM];
__device__ __nv_bfloat16 g_wph[DIM*DIM],   g_wpl[DIM*DIM];
__device__ __nv_bfloat16 g_ohh[MROWS*DIM], g_oll[MROWS*DIM];
__device__ float g_sin[NTOK*32], g_cos[NTOK*32];

// ==================== helpers ====================
__device__ __forceinline__ uint32_t smem_u32(const void* p) {
    uint32_t a;
    asm("{ .reg .u64 t; cvta.to.shared.u64 t, %1; cvt.u32.u64 %0, t; }" : "=r"(a) : "l"(p));
    return a;
}
__device__ __forceinline__ void ldsm4(uint32_t* r, uint32_t addr) {
    asm volatile("ldmatrix.sync.aligned.m8n8.x4.shared.b16 {%0,%1,%2,%3}, [%4];"
                 : "=r"(r[0]), "=r"(r[1]), "=r"(r[2]), "=r"(r[3]) : "r"(addr));
}
__device__ __forceinline__ void ldsm4t(uint32_t* r, uint32_t addr) {
    asm volatile("ldmatrix.sync.aligned.m8n8.x4.trans.shared.b16 {%0,%1,%2,%3}, [%4];"
                 : "=r"(r[0]), "=r"(r[1]), "=r"(r[2]), "=r"(r[3]) : "r"(addr));
}
__device__ __forceinline__ void mma_bf(float* d, const uint32_t* a,
                                       uint32_t b0, uint32_t b1) {
    asm volatile(
        "mma.sync.aligned.m16n8k16.row.col.f32.bf16.bf16.f32 "
        "{%0,%1,%2,%3}, {%4,%5,%6,%7}, {%8,%9}, {%0,%1,%2,%3};"
        : "+f"(d[0]), "+f"(d[1]), "+f"(d[2]), "+f"(d[3])
        : "r"(a[0]), "r"(a[1]), "r"(a[2]), "r"(a[3]), "r"(b0), "r"(b1));
}
__device__ __forceinline__ void mma_fp(float* d, const uint32_t* a,
                                       uint32_t b0, uint32_t b1) {
    asm volatile(
        "mma.sync.aligned.m16n8k16.row.col.f32.f16.f16.f32 "
        "{%0,%1,%2,%3}, {%4,%5,%6,%7}, {%8,%9}, {%0,%1,%2,%3};"
        : "+f"(d[0]), "+f"(d[1]), "+f"(d[2]), "+f"(d[3])
        : "r"(a[0]), "r"(a[1]), "r"(a[2]), "r"(a[3]), "r"(b0), "r"(b1));
}
// fast e^x on FMA/ALU pipes (no MUFU). |rel err| ~1e-7, x clamped >= -80.
__device__ __forceinline__ float fast_exp(float x) {
    x = fmaxf(x, -80.0f);
    float y = fmaf(x, 1.4426950409f, 12582912.0f);
    float z = y - 12582912.0f;
    int   n = __float_as_int(y) - 0x4B400000;
    float f = fmaf(x, 1.4426950409f, -z);
    float p = 1.3333558e-3f;
    p = fmaf(p, f, 9.6181291e-3f);
    p = fmaf(p, f, 5.5504109e-2f);
    p = fmaf(p, f, 2.4022651e-1f);
    p = fmaf(p, f, 6.9314718e-1f);
    p = fmaf(p, f, 1.0f);
    return __int_as_float(__float_as_int(p) + (n << 23));
}
__device__ __forceinline__ void split_h2(float a, float b,
                                         uint32_t& hi, uint32_t& lo) {
    __half2 hh = __floats2half2_rn(a, b);
    __half2 ll = __floats2half2_rn(a - __low2float(hh), b - __high2float(hh));
    hi = *(uint32_t*)&hh;
    lo = *(uint32_t*)&ll;
}

// ==================== prep kernels ====================
__global__ void __launch_bounds__(256) split_kernel(
    const float* __restrict__ src, __nv_bfloat16* __restrict__ hi,
    __nv_bfloat16* __restrict__ lo, int n4)
{
    int i = blockIdx.x * 256 + threadIdx.x;
    if (i >= n4) return;
    float4 v = ((const float4*)src)[i];
    float f[4] = {v.x, v.y, v.z, v.w};
    __nv_bfloat16 h[4], l[4];
    #pragma unroll
    for (int j = 0; j < 4; j++) {
        h[j] = __float2bfloat16(f[j]);
        l[j] = __float2bfloat16(f[j] - __bfloat162float(h[j]));
    }
    ((__nv_bfloat162*)hi)[2*i]   = __halves2bfloat162(h[0], h[1]);
    ((__nv_bfloat162*)hi)[2*i+1] = __halves2bfloat162(h[2], h[3]);
    ((__nv_bfloat162*)lo)[2*i]   = __halves2bfloat162(l[0], l[1]);
    ((__nv_bfloat162*)lo)[2*i+1] = __halves2bfloat162(l[2], l[3]);
}

__global__ void __launch_bounds__(256) rope_tab_kernel()
{
    int idx = blockIdx.x * 256 + threadIdx.x;
    if (idx >= NTOK * 32) return;
    int n = idx >> 5, j = idx & 31;
    int axis = j >> 4, p = j & 15;
    int y = n / WW, x = n - y * WW;
    float idxf  = axis ? (float)x : (float)y;
    float coord = 2.0f * ((idxf + 0.5f) / 48.0f) - 1.0f;
    float invp  = exp2f(-(float)p * 0.41524101186092607f);  // 100^(-p/16)
    float sn, cs; sincosf(6.283185307179586f * coord * invp, &sn, &cs);
    g_sin[idx] = sn; g_cos[idx] = cs;
}

// ==================== mma.sync bf16-split GEMM ====================
#define TSTRIDE 40
#define TILE_E  (128*TSTRIDE)
#define GEMM_SMEM_B (8*TILE_E*2)

__device__ __forceinline__ void g2r(uint4* r,
    const __nv_bfloat16* Ah, const __nv_bfloat16* Al,
    const __nv_bfloat16* Bh, const __nv_bfloat16* Bl,
    int bm, int bn, int K, int k0, int tid)
{
    #pragma unroll
    for (int p = 0; p < 2; p++) {
        int id = p * 256 + tid;
        int row = id >> 2, kc = id & 3;
        size_t oA = (size_t)(bm + row) * K + k0 + kc * 8;
        size_t oB = (size_t)(bn + row) * K + k0 + kc * 8;
        r[0+p] = *(const uint4*)&Ah[oA];
        r[2+p] = *(const uint4*)&Al[oA];
        r[4+p] = *(const uint4*)&Bh[oB];
        r[6+p] = *(const uint4*)&Bl[oB];
    }
}
__device__ __forceinline__ void r2s(__nv_bfloat16* sm, const uint4* r,
                                    int tid, int st)
{
    #pragma unroll
    for (int p = 0; p < 2; p++) {
        int id = p * 256 + tid;
        int off = (id >> 2) * TSTRIDE + (id & 3) * 8;
        #pragma unroll
        for (int t = 0; t < 4; t++)
            *(uint4*)&sm[(st*4 + t) * TILE_E + off] = r[t*2 + p];
    }
}

template<int EPI>
__global__ void __launch_bounds__(256, 1) gemm_mma(
    const __nv_bfloat16* __restrict__ Ah, const __nv_bfloat16* __restrict__ Al,
    const __nv_bfloat16* __restrict__ Bh, const __nv_bfloat16* __restrict__ Bl,
    const float* __restrict__ bias, float* __restrict__ C, int M, int N, int K)
{
    extern __shared__ __align__(16) __nv_bfloat16 sm[];
    const uint32_t sbase = smem_u32(sm);
    const int tid = threadIdx.x;
    const int lane = tid & 31, wid = tid >> 5;
    const int wm = wid & 3, wn = wid >> 2;
    const int bm = blockIdx.y * 128, bn = blockIdx.x * 128;
    const int piece = lane >> 3, pr = lane & 7;

    float acc[2][8][4];
    #pragma unroll
    for (int i = 0; i < 2; i++)
        #pragma unroll
        for (int j = 0; j < 8; j++)
            #pragma unroll
            for (int k = 0; k < 4; k++) acc[i][j][k] = 0.0f;

    const int nit = K >> 5;
    uint4 r[8];
    g2r(r, Ah, Al, Bh, Bl, bm, bn, K, 0, tid);
    r2s(sm, r, tid, 0);
    __syncthreads();

    const int arow = wm*32 + (piece & 1)*8 + pr;
    const int brow = wn*64 + (piece & 1)*8 + pr;
    const int kofp = (piece >> 1) * 8;

    for (int it = 0; it < nit; it++) {
        int st = it & 1;
        bool more = (it + 1) < nit;
        if (more) g2r(r, Ah, Al, Bh, Bl, bm, bn, K, (it + 1) << 5, tid);

        uint32_t tA = sbase + (uint32_t)(st*4) * (TILE_E*2);
        #pragma unroll
        for (int ks = 0; ks < 2; ks++) {
            int koff = ks*16 + kofp;
            uint32_t ah[2][4], al[2][4];
            #pragma unroll
            for (int mt = 0; mt < 2; mt++) {
                uint32_t ad = tA + ((arow + mt*16) * TSTRIDE + koff) * 2;
                ldsm4(ah[mt], ad);
                ldsm4(al[mt], ad + TILE_E*2);
            }
            #pragma unroll
            for (int np = 0; np < 4; np++) {
                uint32_t bd = tA + 2*(TILE_E*2)
                            + ((brow + np*16) * TSTRIDE + koff) * 2;
                uint32_t bh[4], bl[4];
                ldsm4(bh, bd);
                ldsm4(bl, bd + TILE_E*2);
                #pragma unroll
                for (int mt = 0; mt < 2; mt++) {
                    mma_bf(acc[mt][np*2],   ah[mt], bh[0], bh[2]);
                    mma_bf(acc[mt][np*2+1], ah[mt], bh[1], bh[3]);
                    mma_bf(acc[mt][np*2],   ah[mt], bl[0], bl[2]);
                    mma_bf(acc[mt][np*2+1], ah[mt], bl[1], bl[3]);
                    mma_bf(acc[mt][np*2],   al[mt], bh[0], bh[2]);
                    mma_bf(acc[mt][np*2+1], al[mt], bh[1], bh[3]);
                }
            }
        }
        // Single barrier per iteration (see R9 note).
        if (more) r2s(sm, r, tid, st ^ 1);
        __syncthreads();
    }

    const int cbase = bn + wn * 64;
    if (EPI == 0) {
        #pragma unroll
        for (int mt = 0; mt < 2; mt++)
            #pragma unroll
            for (int half = 0; half < 2; half++) {
                int m = bm + wm*32 + mt*16 + (lane >> 2) + half*8;
                #pragma unroll
                for (int nt = 0; nt < 8; nt++) {
                    int c = cbase + nt*8 + (lane & 3)*2;
                    float2 v;
                    v.x = acc[mt][nt][half*2+0] + bias[c];
                    v.y = acc[mt][nt][half*2+1] + bias[c+1];
                    *(float2*)&C[(size_t)m * N + c] = v;
                }
            }
    } else {
        // QKV epilogue: Q -> fp16 hi/lo (+RoPE, prescale); K -> fp16 (+RoPE);
        // V -> fp16.
        int which = cbase / DIM;
        int h = (cbase % DIM) >> 6;
        #pragma unroll
        for (int mt = 0; mt < 2; mt++)
            #pragma unroll
            for (int half = 0; half < 2; half++) {
                int m = bm + wm*32 + mt*16 + (lane >> 2) + half*8;
                int bb = m / NTOK, pos = m - bb * NTOK;
                size_t dof = ((size_t)(bb*HEADS + h) * NTOK + pos) * HD;
                if (which < 2) {
                    const float qs = (which == 0) ? 0.125f : 1.0f;
                    #pragma unroll
                    for (int nt = 0; nt < 4; nt++) {
                        int d0 = nt*8 + (lane & 3)*2;
                        float rl[2], rh[2];
                        #pragma unroll
                        for (int j = 0; j < 2; j++) {
                            float vlo = acc[mt][nt][half*2+j]   + bias[cbase + d0 + j];
                            float vhi = acc[mt][nt+4][half*2+j] + bias[cbase + 32 + d0 + j];
                            float sn = g_sin[pos*32 + d0 + j];
                            float cs = g_cos[pos*32 + d0 + j];
                            rl[j] = (vlo*cs - vhi*sn) * qs;
                            rh[j] = (vhi*cs + vlo*sn) * qs;
                        }
                        if (which == 0) {
                            uint32_t hh, ll;
                            split_h2(rl[0], rl[1], hh, ll);
                            *(uint32_t*)&g_qh[dof + d0] = hh;
                            *(uint32_t*)&g_ql[dof + d0] = ll;
                            split_h2(rh[0], rh[1], hh, ll);
                            *(uint32_t*)&g_qh[dof + 32 + d0] = hh;
                            *(uint32_t*)&g_ql[dof + 32 + d0] = ll;
                        } else {
                            __half2 p0 = __floats2half2_rn(rl[0], rl[1]);
                            __half2 p1 = __floats2half2_rn(rh[0], rh[1]);
                            *(__half2*)&g_kh[dof + d0]      = p0;
                            *(__half2*)&g_kh[dof + 32 + d0] = p1;
                        }
                    }
                } else {
                    #pragma unroll
                    for (int nt = 0; nt < 8; nt++) {
                        int d = nt*8 + (lane & 3)*2;
                        float v0 = acc[mt][nt][half*2+0] + bias[cbase + d];
                        float v1 = acc[mt][nt][half*2+1] + bias[cbase + d + 1];
                        *(__half2*)&g_vh[dof + d] = __floats2half2_rn(v0, v1);
                    }
                }
            }
    }
}

// ==================== attention: HMMA flash (fp16 K/V, split Q/P) ====
#define AST 72
#define ATTN_SMEM (128*AST*2*2)   // 36864 B (Q staging hi+lo; K/V reuse)

__global__ void __launch_bounds__(256, 2) attn_mma()
{
    extern __shared__ __align__(16) __half smh[];
    const uint32_t sb = smem_u32(smh);
    __half* sKh = smh;             // [64][AST]
    __half* sVh = smh + 64*AST;    // [64][AST]

    const int tid = threadIdx.x;
    const int lane = tid & 31, w = tid >> 5;
    const int l15 = lane & 15, l16 = lane >> 4;
    const int bh = blockIdx.y, q0 = blockIdx.x * 128;

    const __half* Qh = g_qh + ((size_t)bh * NTOK + q0) * HD;
    const __half* Ql = g_ql + ((size_t)bh * NTOK + q0) * HD;
    const __half* Kh = g_kh + (size_t)bh * NTOK * HD;
    const __half* Vh = g_vh + (size_t)bh * NTOK * HD;

    // ---- stage Q (hi/lo), extract A-fragments, then buffer is reused ----
    #pragma unroll
    for (int t = 0; t < 8; t++) {
        int lin = t * 256 + tid;
        int arr = lin >> 10, rem = lin & 1023;
        int row = rem >> 3, c = (rem & 7) * 8;
        const __half* src = (arr ? Ql : Qh) + (size_t)row * HD + c;
        __half* dst = smh + arr * 128*AST + row * AST + c;
        *(uint4*)dst = *(const uint4*)src;
    }
    __syncthreads();
    uint32_t qfh[4][4], qfl[4][4];
    {
        uint32_t qa = sb + (((w*16 + l15) * AST) + l16*8) * 2;
        #pragma unroll
        for (int ks = 0; ks < 4; ks++) {
            ldsm4(qfh[ks], qa + ks*32);
            ldsm4(qfl[ks], qa + ks*32 + 128*AST*2);
        }
    }

    float acc[8][4];
    #pragma unroll
    for (int i = 0; i < 8; i++)
        #pragma unroll
        for (int j = 0; j < 4; j++) acc[i][j] = 0.0f;
    float m0 = -1e30f, m1 = -1e30f, l0 = 0.0f, l1 = 0.0f;

    const uint32_t kbase = sb + (l15 * AST + l16*8) * 2;
    const uint32_t vbase = sb + 64*AST*2 + (l15 * AST + l16*8) * 2;

    for (int t = 0; t < NTOK/64; t++) {
        const int k0 = t * 64;
        uint4 rv[4];
        #pragma unroll
        for (int i = 0; i < 4; i++) {
            int lin = i * 256 + tid;
            int arr = lin >> 9, rem = lin & 511;
            int row = rem >> 3, c = (rem & 7) * 8;
            const __half* src = (arr == 0 ? Kh : Vh) + (size_t)(k0 + row) * HD + c;
            rv[i] = *(const uint4*)src;
        }
        __syncthreads();
        #pragma unroll
        for (int i = 0; i < 4; i++) {
            int lin = i * 256 + tid;
            int arr = lin >> 9, rem = lin & 511;
            int row = rem >> 3, c = (rem & 7) * 8;
            __half* dst = (arr == 0 ? sKh : sVh) + row * AST + c;
            *(uint4*)dst = rv[i];
        }
        __syncthreads();

        // ---- S = (Qh + Ql) K^T ----
        float s[8][4];
        #pragma unroll
        for (int i = 0; i < 8; i++)
            #pragma unroll
            for (int j = 0; j < 4; j++) s[i][j] = 0.0f;
        #pragma unroll
        for (int ks = 0; ks < 4; ks++) {
            #pragma unroll
            for (int nbp = 0; nbp < 8; nbp += 2) {
                uint32_t kh4[4];
                ldsm4(kh4, kbase + (nbp*8*AST + ks*16) * 2);
                mma_fp(s[nbp],   qfh[ks], kh4[0], kh4[2]);
                mma_fp(s[nbp+1], qfh[ks], kh4[1], kh4[3]);
                mma_fp(s[nbp],   qfl[ks], kh4[0], kh4[2]);
                mma_fp(s[nbp+1], qfl[ks], kh4[1], kh4[3]);
            }
        }

        // ---- online softmax ----
        float mx0 = -1e30f, mx1 = -1e30f;
        #pragma unroll
        for (int i = 0; i < 8; i++) {
            mx0 = fmaxf(mx0, fmaxf(s[i][0], s[i][1]));
            mx1 = fmaxf(mx1, fmaxf(s[i][2], s[i][3]));
        }
        mx0 = fmaxf(mx0, __shfl_xor_sync(0xffffffffu, mx0, 1));
        mx0 = fmaxf(mx0, __shfl_xor_sync(0xffffffffu, mx0, 2));
        mx1 = fmaxf(mx1, __shfl_xor_sync(0xffffffffu, mx1, 1));
        mx1 = fmaxf(mx1, __shfl_xor_sync(0xffffffffu, mx1, 2));
        float nm0 = fmaxf(m0, mx0), nm1 = fmaxf(m1, mx1);
        float f0 = fast_exp(m0 - nm0), f1 = fast_exp(m1 - nm1);
        m0 = nm0; m1 = nm1;
        float sum0 = 0.0f, sum1 = 0.0f;
        #pragma unroll
        for (int i = 0; i < 8; i++) {
            s[i][0] = fast_exp(s[i][0] - nm0); sum0 += s[i][0];
            s[i][1] = fast_exp(s[i][1] - nm0); sum0 += s[i][1];
            s[i][2] = fast_exp(s[i][2] - nm1); sum1 += s[i][2];
            s[i][3] = fast_exp(s[i][3] - nm1); sum1 += s[i][3];
        }
        sum0 += __shfl_xor_sync(0xffffffffu, sum0, 1);
        sum0 += __shfl_xor_sync(0xffffffffu, sum0, 2);
        sum1 += __shfl_xor_sync(0xffffffffu, sum1, 1);
        sum1 += __shfl_xor_sync(0xffffffffu, sum1, 2);
        l0 = l0 * f0 + sum0;
        l1 = l1 * f1 + sum1;
        #pragma unroll
        for (int i = 0; i < 8; i++) {
            acc[i][0] *= f0; acc[i][1] *= f0;
            acc[i][2] *= f1; acc[i][3] *= f1;
        }

        // ---- P -> fp16 hi/lo A-fragments ----
        uint32_t aph[4][4], apl[4][4];
        #pragma unroll
        for (int ks = 0; ks < 4; ks++) {
            int n0 = 2*ks, n1 = 2*ks + 1;
            split_h2(s[n0][0], s[n0][1], aph[ks][0], apl[ks][0]);
            split_h2(s[n0][2], s[n0][3], aph[ks][1], apl[ks][1]);
            split_h2(s[n1][0], s[n1][1], aph[ks][2], apl[ks][2]);
            split_h2(s[n1][2], s[n1][3], aph[ks][3], apl[ks][3]);
        }

        // ---- O += (Ph + Pl) V ----
        #pragma unroll
        for (int ks = 0; ks < 4; ks++) {
            #pragma unroll
            for (int nbp = 0; nbp < 8; nbp += 2) {
                uint32_t vh4[4];
                ldsm4t(vh4, vbase + (ks*16*AST + nbp*8) * 2);
                mma_fp(acc[nbp],   aph[ks], vh4[0], vh4[1]);
                mma_fp(acc[nbp+1], aph[ks], vh4[2], vh4[3]);
                mma_fp(acc[nbp],   apl[ks], vh4[0], vh4[1]);
                mma_fp(acc[nbp+1], apl[ks], vh4[2], vh4[3]);
            }
        }
    }

    // ---- normalize + write O as bf16 hi/lo, [b, n, h*64 + d] ----
    float inv0 = 1.0f / l0, inv1 = 1.0f / l1;
    int b = bh / HEADS, h = bh - b * HEADS;
    int r0 = q0 + w*16 + (lane >> 2);
    int col = h*HD + (lane & 3)*2;
    #pragma unroll
    for (int nb = 0; nb < 8; nb++) {
        size_t o0 = ((size_t)(b*NTOK + r0))     * DIM + col + nb*8;
        size_t o1 = ((size_t)(b*NTOK + r0 + 8)) * DIM + col + nb*8;
        float a0 = acc[nb][0]*inv0, a1 = acc[nb][1]*inv0;
        float a2 = acc[nb][2]*inv1, a3 = acc[nb][3]*inv1;
        __nv_bfloat162 hh, ll;
        hh = __floats2bfloat162_rn(a0, a1);
        ll = __floats2bfloat162_rn(a0 - __bfloat162float(hh.x),
                                   a1 - __bfloat162float(hh.y));
        *(__nv_bfloat162*)&g_ohh[o0] = hh;
        *(__nv_bfloat162*)&g_oll[o0] = ll;
        hh = __floats2bfloat162_rn(a2, a3);
        ll = __floats2bfloat162_rn(a2 - __bfloat162float(hh.x),
                                   a3 - __bfloat162float(hh.y));
        *(__nv_bfloat162*)&g_ohh[o1] = hh;
        *(__nv_bfloat162*)&g_oll[o1] = ll;
    }
}

// ==================== launcher ====================
extern "C" void kernel_launch(void* const* d_in, const int* in_sizes, int n_in,
                              void* d_out, int out_size)
{
    const float* x      = (const float*)d_in[0];
    const float* w_qkv  = (const float*)d_in[1];
    const float* b_qkv  = (const float*)d_in[2];
    const float* w_proj = (const float*)d_in[3];
    const float* b_proj = (const float*)d_in[4];
    float* out = (float*)d_out;

    void *xh, *xl, *wqh, *wql, *wph, *wpl, *ohh, *oll;
    cudaGetSymbolAddress(&xh,  g_xh);  cudaGetSymbolAddress(&xl,  g_xl);
    cudaGetSymbolAddress(&wqh, g_wqh); cudaGetSymbolAddress(&wql, g_wql);
    cudaGetSymbolAddress(&wph, g_wph); cudaGetSymbolAddress(&wpl, g_wpl);
    cudaGetSymbolAddress(&ohh, g_ohh); cudaGetSymbolAddress(&oll, g_oll);

    cudaFuncSetAttribute(gemm_mma<0>, cudaFuncAttributeMaxDynamicSharedMemorySize,
                         GEMM_SMEM_B);
    cudaFuncSetAttribute(gemm_mma<1>, cudaFuncAttributeMaxDynamicSharedMemorySize,
                         GEMM_SMEM_B);
    cudaFuncSetAttribute(attn_mma, cudaFuncAttributeMaxDynamicSharedMemorySize,
                         ATTN_SMEM);

    split_kernel<<<(MROWS*DIM/4 + 255)/256, 256>>>(
        x, (__nv_bfloat16*)xh, (__nv_bfloat16*)xl, MROWS*DIM/4);
    split_kernel<<<(3*DIM*DIM/4 + 255)/256, 256>>>(
        w_qkv, (__nv_bfloat16*)wqh, (__nv_bfloat16*)wql, 3*DIM*DIM/4);
    split_kernel<<<(DIM*DIM/4 + 255)/256, 256>>>(
        w_proj, (__nv_bfloat16*)wph, (__nv_bfloat16*)wpl, DIM*DIM/4);
    rope_tab_kernel<<<(NTOK*32 + 255)/256, 256>>>();

    // 1) QKV GEMM + bias + RoPE + fp16 scatter
    gemm_mma<1><<<dim3(3*DIM/128, MROWS/128), 256, GEMM_SMEM_B>>>(
        (const __nv_bfloat16*)xh, (const __nv_bfloat16*)xl,
        (const __nv_bfloat16*)wqh, (const __nv_bfloat16*)wql,
        b_qkv, nullptr, MROWS, 3*DIM, DIM);

    // 2) attention (HMMA flash, fp16 K/V, split Q/P)
    attn_mma<<<dim3(NTOK/128, BHC), 256, ATTN_SMEM>>>();

    // 3) output projection -> d_out
    gemm_mma<0><<<dim3(DIM/128, MROWS/128), 256, GEMM_SMEM_B>>>(
        (const __nv_bfloat16*)ohh, (const __nv_bfloat16*)oll,
        (const __nv_bfloat16*)wph, (const __nv_bfloat16*)wpl,
        b_proj, out, MROWS, DIM, DIM);
}

// round 11
// speedup vs baseline: 2.0911x; 1.1973x over previous
#include <cuda_runtime.h>
#include <cuda_bf16.h>
#include <cuda_fp16.h>
#include <math.h>
#include <stdint.h>

#define DIM   768
#define HEADS 12
#define HD    64
#define B_    2
#define WW    48
#define NTOK  2304
#define BHC   24
#define MROWS 4608

// -------- scratch (device globals; no allocation allowed) --------
__device__ __half g_qh[BHC*NTOK*HD];          // Q: fp16 (pre-scaled)
__device__ __half g_kh[BHC*NTOK*HD];          // K: fp16
__device__ __half g_vh[BHC*NTOK*HD];          // V: fp16
__device__ __nv_bfloat16 g_xh[MROWS*DIM],  g_xl[MROWS*DIM];
__device__ __nv_bfloat16 g_wqh[3*DIM*DIM], g_wql[3*DIM*DIM];
__device__ __nv_bfloat16 g_wph[DIM*DIM],   g_wpl[DIM*DIM];
__device__ __nv_bfloat16 g_ohh[MROWS*DIM], g_oll[MROWS*DIM];
__device__ float g_sin[NTOK*32], g_cos[NTOK*32];

// ==================== helpers ====================
__device__ __forceinline__ uint32_t smem_u32(const void* p) {
    uint32_t a;
    asm("{ .reg .u64 t; cvta.to.shared.u64 t, %1; cvt.u32.u64 %0, t; }" : "=r"(a) : "l"(p));
    return a;
}
__device__ __forceinline__ void ldsm4(uint32_t* r, uint32_t addr) {
    asm volatile("ldmatrix.sync.aligned.m8n8.x4.shared.b16 {%0,%1,%2,%3}, [%4];"
                 : "=r"(r[0]), "=r"(r[1]), "=r"(r[2]), "=r"(r[3]) : "r"(addr));
}
__device__ __forceinline__ void ldsm4t(uint32_t* r, uint32_t addr) {
    asm volatile("ldmatrix.sync.aligned.m8n8.x4.trans.shared.b16 {%0,%1,%2,%3}, [%4];"
                 : "=r"(r[0]), "=r"(r[1]), "=r"(r[2]), "=r"(r[3]) : "r"(addr));
}
__device__ __forceinline__ void mma_bf(float* d, const uint32_t* a,
                                       uint32_t b0, uint32_t b1) {
    asm volatile(
        "mma.sync.aligned.m16n8k16.row.col.f32.bf16.bf16.f32 "
        "{%0,%1,%2,%3}, {%4,%5,%6,%7}, {%8,%9}, {%0,%1,%2,%3};"
        : "+f"(d[0]), "+f"(d[1]), "+f"(d[2]), "+f"(d[3])
        : "r"(a[0]), "r"(a[1]), "r"(a[2]), "r"(a[3]), "r"(b0), "r"(b1));
}
__device__ __forceinline__ void mma_fp(float* d, const uint32_t* a,
                                       uint32_t b0, uint32_t b1) {
    asm volatile(
        "mma.sync.aligned.m16n8k16.row.col.f32.f16.f16.f32 "
        "{%0,%1,%2,%3}, {%4,%5,%6,%7}, {%8,%9}, {%0,%1,%2,%3};"
        : "+f"(d[0]), "+f"(d[1]), "+f"(d[2]), "+f"(d[3])
        : "r"(a[0]), "r"(a[1]), "r"(a[2]), "r"(a[3]), "r"(b0), "r"(b1));
}
// fast e^x on FMA/ALU pipes (no MUFU). |rel err| ~1e-7, x clamped >= -80.
__device__ __forceinline__ float fast_exp(float x) {
    x = fmaxf(x, -80.0f);
    float y = fmaf(x, 1.4426950409f, 12582912.0f);
    float z = y - 12582912.0f;
    int   n = __float_as_int(y) - 0x4B400000;
    float f = fmaf(x, 1.4426950409f, -z);
    float p = 1.3333558e-3f;
    p = fmaf(p, f, 9.6181291e-3f);
    p = fmaf(p, f, 5.5504109e-2f);
    p = fmaf(p, f, 2.4022651e-1f);
    p = fmaf(p, f, 6.9314718e-1f);
    p = fmaf(p, f, 1.0f);
    return __int_as_float(__float_as_int(p) + (n << 23));
}

// ==================== prep kernels ====================
__global__ void __launch_bounds__(256) split_kernel(
    const float* __restrict__ src, __nv_bfloat16* __restrict__ hi,
    __nv_bfloat16* __restrict__ lo, int n4)
{
    int i = blockIdx.x * 256 + threadIdx.x;
    if (i >= n4) return;
    float4 v = ((const float4*)src)[i];
    float f[4] = {v.x, v.y, v.z, v.w};
    __nv_bfloat16 h[4], l[4];
    #pragma unroll
    for (int j = 0; j < 4; j++) {
        h[j] = __float2bfloat16(f[j]);
        l[j] = __float2bfloat16(f[j] - __bfloat162float(h[j]));
    }
    ((__nv_bfloat162*)hi)[2*i]   = __halves2bfloat162(h[0], h[1]);
    ((__nv_bfloat162*)hi)[2*i+1] = __halves2bfloat162(h[2], h[3]);
    ((__nv_bfloat162*)lo)[2*i]   = __halves2bfloat162(l[0], l[1]);
    ((__nv_bfloat162*)lo)[2*i+1] = __halves2bfloat162(l[2], l[3]);
}

__global__ void __launch_bounds__(256) rope_tab_kernel()
{
    int idx = blockIdx.x * 256 + threadIdx.x;
    if (idx >= NTOK * 32) return;
    int n = idx >> 5, j = idx & 31;
    int axis = j >> 4, p = j & 15;
    int y = n / WW, x = n - y * WW;
    float idxf  = axis ? (float)x : (float)y;
    float coord = 2.0f * ((idxf + 0.5f) / 48.0f) - 1.0f;
    float invp  = exp2f(-(float)p * 0.41524101186092607f);  // 100^(-p/16)
    float sn, cs; sincosf(6.283185307179586f * coord * invp, &sn, &cs);
    g_sin[idx] = sn; g_cos[idx] = cs;
}

// ==================== mma.sync bf16-split GEMM ====================
#define TSTRIDE 40
#define TILE_E  (128*TSTRIDE)
#define GEMM_SMEM_B (8*TILE_E*2)

__device__ __forceinline__ void g2r(uint4* r,
    const __nv_bfloat16* Ah, const __nv_bfloat16* Al,
    const __nv_bfloat16* Bh, const __nv_bfloat16* Bl,
    int bm, int bn, int K, int k0, int tid)
{
    #pragma unroll
    for (int p = 0; p < 2; p++) {
        int id = p * 256 + tid;
        int row = id >> 2, kc = id & 3;
        size_t oA = (size_t)(bm + row) * K + k0 + kc * 8;
        size_t oB = (size_t)(bn + row) * K + k0 + kc * 8;
        r[0+p] = *(const uint4*)&Ah[oA];
        r[2+p] = *(const uint4*)&Al[oA];
        r[4+p] = *(const uint4*)&Bh[oB];
        r[6+p] = *(const uint4*)&Bl[oB];
    }
}
__device__ __forceinline__ void r2s(__nv_bfloat16* sm, const uint4* r,
                                    int tid, int st)
{
    #pragma unroll
    for (int p = 0; p < 2; p++) {
        int id = p * 256 + tid;
        int off = (id >> 2) * TSTRIDE + (id & 3) * 8;
        #pragma unroll
        for (int t = 0; t < 4; t++)
            *(uint4*)&sm[(st*4 + t) * TILE_E + off] = r[t*2 + p];
    }
}

template<int EPI>
__global__ void __launch_bounds__(256, 1) gemm_mma(
    const __nv_bfloat16* __restrict__ Ah, const __nv_bfloat16* __restrict__ Al,
    const __nv_bfloat16* __restrict__ Bh, const __nv_bfloat16* __restrict__ Bl,
    const float* __restrict__ bias, float* __restrict__ C, int M, int N, int K)
{
    extern __shared__ __align__(16) __nv_bfloat16 sm[];
    const uint32_t sbase = smem_u32(sm);
    const int tid = threadIdx.x;
    const int lane = tid & 31, wid = tid >> 5;
    const int wm = wid & 3, wn = wid >> 2;
    const int bm = blockIdx.y * 128, bn = blockIdx.x * 128;
    const int piece = lane >> 3, pr = lane & 7;

    float acc[2][8][4];
    #pragma unroll
    for (int i = 0; i < 2; i++)
        #pragma unroll
        for (int j = 0; j < 8; j++)
            #pragma unroll
            for (int k = 0; k < 4; k++) acc[i][j][k] = 0.0f;

    const int nit = K >> 5;
    uint4 r[8];
    g2r(r, Ah, Al, Bh, Bl, bm, bn, K, 0, tid);
    r2s(sm, r, tid, 0);
    __syncthreads();

    const int arow = wm*32 + (piece & 1)*8 + pr;
    const int brow = wn*64 + (piece & 1)*8 + pr;
    const int kofp = (piece >> 1) * 8;

    for (int it = 0; it < nit; it++) {
        int st = it & 1;
        bool more = (it + 1) < nit;
        if (more) g2r(r, Ah, Al, Bh, Bl, bm, bn, K, (it + 1) << 5, tid);

        uint32_t tA = sbase + (uint32_t)(st*4) * (TILE_E*2);
        #pragma unroll
        for (int ks = 0; ks < 2; ks++) {
            int koff = ks*16 + kofp;
            uint32_t ah[2][4], al[2][4];
            #pragma unroll
            for (int mt = 0; mt < 2; mt++) {
                uint32_t ad = tA + ((arow + mt*16) * TSTRIDE + koff) * 2;
                ldsm4(ah[mt], ad);
                ldsm4(al[mt], ad + TILE_E*2);
            }
            #pragma unroll
            for (int np = 0; np < 4; np++) {
                uint32_t bd = tA + 2*(TILE_E*2)
                            + ((brow + np*16) * TSTRIDE + koff) * 2;
                uint32_t bh[4], bl[4];
                ldsm4(bh, bd);
                ldsm4(bl, bd + TILE_E*2);
                #pragma unroll
                for (int mt = 0; mt < 2; mt++) {
                    mma_bf(acc[mt][np*2],   ah[mt], bh[0], bh[2]);
                    mma_bf(acc[mt][np*2+1], ah[mt], bh[1], bh[3]);
                    mma_bf(acc[mt][np*2],   ah[mt], bl[0], bl[2]);
                    mma_bf(acc[mt][np*2+1], ah[mt], bl[1], bl[3]);
                    mma_bf(acc[mt][np*2],   al[mt], bh[0], bh[2]);
                    mma_bf(acc[mt][np*2+1], al[mt], bh[1], bh[3]);
                }
            }
        }
        // Single barrier per iteration (see R9 note).
        if (more) r2s(sm, r, tid, st ^ 1);
        __syncthreads();
    }

    const int cbase = bn + wn * 64;
    if (EPI == 0) {
        #pragma unroll
        for (int mt = 0; mt < 2; mt++)
            #pragma unroll
            for (int half = 0; half < 2; half++) {
                int m = bm + wm*32 + mt*16 + (lane >> 2) + half*8;
                #pragma unroll
                for (int nt = 0; nt < 8; nt++) {
                    int c = cbase + nt*8 + (lane & 3)*2;
                    float2 v;
                    v.x = acc[mt][nt][half*2+0] + bias[c];
                    v.y = acc[mt][nt][half*2+1] + bias[c+1];
                    *(float2*)&C[(size_t)m * N + c] = v;
                }
            }
    } else {
        // QKV epilogue: Q (+RoPE, prescale) / K (+RoPE) / V -> plain fp16.
        int which = cbase / DIM;
        int h = (cbase % DIM) >> 6;
        __half* dstp = (which == 0) ? g_qh : (which == 1) ? g_kh : g_vh;
        #pragma unroll
        for (int mt = 0; mt < 2; mt++)
            #pragma unroll
            for (int half = 0; half < 2; half++) {
                int m = bm + wm*32 + mt*16 + (lane >> 2) + half*8;
                int bb = m / NTOK, pos = m - bb * NTOK;
                size_t dof = ((size_t)(bb*HEADS + h) * NTOK + pos) * HD;
                __half* dst = dstp + dof;
                if (which < 2) {
                    const float qs = (which == 0) ? 0.125f : 1.0f;
                    #pragma unroll
                    for (int nt = 0; nt < 4; nt++) {
                        int d0 = nt*8 + (lane & 3)*2;
                        float rl[2], rh[2];
                        #pragma unroll
                        for (int j = 0; j < 2; j++) {
                            float vlo = acc[mt][nt][half*2+j]   + bias[cbase + d0 + j];
                            float vhi = acc[mt][nt+4][half*2+j] + bias[cbase + 32 + d0 + j];
                            float sn = g_sin[pos*32 + d0 + j];
                            float cs = g_cos[pos*32 + d0 + j];
                            rl[j] = (vlo*cs - vhi*sn) * qs;
                            rh[j] = (vhi*cs + vlo*sn) * qs;
                        }
                        *(__half2*)&dst[d0]      = __floats2half2_rn(rl[0], rl[1]);
                        *(__half2*)&dst[32 + d0] = __floats2half2_rn(rh[0], rh[1]);
                    }
                } else {
                    #pragma unroll
                    for (int nt = 0; nt < 8; nt++) {
                        int d = nt*8 + (lane & 3)*2;
                        float v0 = acc[mt][nt][half*2+0] + bias[cbase + d];
                        float v1 = acc[mt][nt][half*2+1] + bias[cbase + d + 1];
                        *(__half2*)&dst[d] = __floats2half2_rn(v0, v1);
                    }
                }
            }
    }
}

// ==================== attention: HMMA flash (plain fp16, fp32 accum) ====
#define AST 72
#define ATTN_SMEM (128*AST*2)   // 18432 B (Q staging; K/V tiles reuse)

__global__ void __launch_bounds__(256, 2) attn_mma()
{
    extern __shared__ __align__(16) __half smh[];
    const uint32_t sb = smem_u32(smh);
    __half* sKh = smh;             // [64][AST]
    __half* sVh = smh + 64*AST;    // [64][AST]

    const int tid = threadIdx.x;
    const int lane = tid & 31, w = tid >> 5;
    const int l15 = lane & 15, l16 = lane >> 4;
    const int bh = blockIdx.y, q0 = blockIdx.x * 128;

    const __half* Qh = g_qh + ((size_t)bh * NTOK + q0) * HD;
    const __half* Kh = g_kh + (size_t)bh * NTOK * HD;
    const __half* Vh = g_vh + (size_t)bh * NTOK * HD;

    // ---- stage Q, extract A-fragments, then buffer is reused for K/V ----
    #pragma unroll
    for (int t = 0; t < 4; t++) {
        int lin = t * 256 + tid;
        int row = lin >> 3, c = (lin & 7) * 8;
        *(uint4*)&smh[row * AST + c] = *(const uint4*)&Qh[(size_t)row * HD + c];
    }
    __syncthreads();
    uint32_t qf[4][4];
    {
        uint32_t qa = sb + (((w*16 + l15) * AST) + l16*8) * 2;
        #pragma unroll
        for (int ks = 0; ks < 4; ks++)
            ldsm4(qf[ks], qa + ks*32);
    }

    float acc[8][4];
    #pragma unroll
    for (int i = 0; i < 8; i++)
        #pragma unroll
        for (int j = 0; j < 4; j++) acc[i][j] = 0.0f;
    float m0 = -1e30f, m1 = -1e30f, l0 = 0.0f, l1 = 0.0f;

    const uint32_t kbase = sb + (l15 * AST + l16*8) * 2;
    const uint32_t vbase = sb + 64*AST*2 + (l15 * AST + l16*8) * 2;

    for (int t = 0; t < NTOK/64; t++) {
        const int k0 = t * 64;
        uint4 rv[4];
        #pragma unroll
        for (int i = 0; i < 4; i++) {
            int lin = i * 256 + tid;
            int arr = lin >> 9, rem = lin & 511;
            int row = rem >> 3, c = (rem & 7) * 8;
            const __half* src = (arr == 0 ? Kh : Vh) + (size_t)(k0 + row) * HD + c;
            rv[i] = *(const uint4*)src;
        }
        __syncthreads();   // prior readers done (iter0: qf ldsm done)
        #pragma unroll
        for (int i = 0; i < 4; i++) {
            int lin = i * 256 + tid;
            int arr = lin >> 9, rem = lin & 511;
            int row = rem >> 3, c = (rem & 7) * 8;
            __half* dst = (arr == 0 ? sKh : sVh) + row * AST + c;
            *(uint4*)dst = rv[i];
        }
        __syncthreads();

        // ---- S = Q K^T (fp16 x fp16, fp32 accum) ----
        float s[8][4];
        #pragma unroll
        for (int i = 0; i < 8; i++)
            #pragma unroll
            for (int j = 0; j < 4; j++) s[i][j] = 0.0f;
        #pragma unroll
        for (int ks = 0; ks < 4; ks++) {
            #pragma unroll
            for (int nbp = 0; nbp < 8; nbp += 2) {
                uint32_t kh4[4];
                ldsm4(kh4, kbase + (nbp*8*AST + ks*16) * 2);
                mma_fp(s[nbp],   qf[ks], kh4[0], kh4[2]);
                mma_fp(s[nbp+1], qf[ks], kh4[1], kh4[3]);
            }
        }

        // ---- online softmax ----
        float mx0 = -1e30f, mx1 = -1e30f;
        #pragma unroll
        for (int i = 0; i < 8; i++) {
            mx0 = fmaxf(mx0, fmaxf(s[i][0], s[i][1]));
            mx1 = fmaxf(mx1, fmaxf(s[i][2], s[i][3]));
        }
        mx0 = fmaxf(mx0, __shfl_xor_sync(0xffffffffu, mx0, 1));
        mx0 = fmaxf(mx0, __shfl_xor_sync(0xffffffffu, mx0, 2));
        mx1 = fmaxf(mx1, __shfl_xor_sync(0xffffffffu, mx1, 1));
        mx1 = fmaxf(mx1, __shfl_xor_sync(0xffffffffu, mx1, 2));
        float nm0 = fmaxf(m0, mx0), nm1 = fmaxf(m1, mx1);
        float f0 = fast_exp(m0 - nm0), f1 = fast_exp(m1 - nm1);
        m0 = nm0; m1 = nm1;
        float sum0 = 0.0f, sum1 = 0.0f;
        #pragma unroll
        for (int i = 0; i < 8; i++) {
            s[i][0] = fast_exp(s[i][0] - nm0); sum0 += s[i][0];
            s[i][1] = fast_exp(s[i][1] - nm0); sum0 += s[i][1];
            s[i][2] = fast_exp(s[i][2] - nm1); sum1 += s[i][2];
            s[i][3] = fast_exp(s[i][3] - nm1); sum1 += s[i][3];
        }
        sum0 += __shfl_xor_sync(0xffffffffu, sum0, 1);
        sum0 += __shfl_xor_sync(0xffffffffu, sum0, 2);
        sum1 += __shfl_xor_sync(0xffffffffu, sum1, 1);
        sum1 += __shfl_xor_sync(0xffffffffu, sum1, 2);
        l0 = l0 * f0 + sum0;
        l1 = l1 * f1 + sum1;
        #pragma unroll
        for (int i = 0; i < 8; i++) {
            acc[i][0] *= f0; acc[i][1] *= f0;
            acc[i][2] *= f1; acc[i][3] *= f1;
        }

        // ---- P -> fp16 A-fragments (plain) ----
        uint32_t ap[4][4];
        #pragma unroll
        for (int ks = 0; ks < 4; ks++) {
            int n0 = 2*ks, n1 = 2*ks + 1;
            __half2 h0 = __floats2half2_rn(s[n0][0], s[n0][1]);
            __half2 h1 = __floats2half2_rn(s[n0][2], s[n0][3]);
            __half2 h2 = __floats2half2_rn(s[n1][0], s[n1][1]);
            __half2 h3 = __floats2half2_rn(s[n1][2], s[n1][3]);
            ap[ks][0] = *(uint32_t*)&h0;
            ap[ks][1] = *(uint32_t*)&h1;
            ap[ks][2] = *(uint32_t*)&h2;
            ap[ks][3] = *(uint32_t*)&h3;
        }

        // ---- O += P V ----
        #pragma unroll
        for (int ks = 0; ks < 4; ks++) {
            #pragma unroll
            for (int nbp = 0; nbp < 8; nbp += 2) {
                uint32_t vh4[4];
                ldsm4t(vh4, vbase + (ks*16*AST + nbp*8) * 2);
                mma_fp(acc[nbp],   ap[ks], vh4[0], vh4[1]);
                mma_fp(acc[nbp+1], ap[ks], vh4[2], vh4[3]);
            }
        }
    }

    // ---- normalize + write O as bf16 hi/lo, [b, n, h*64 + d] ----
    float inv0 = 1.0f / l0, inv1 = 1.0f / l1;
    int b = bh / HEADS, h = bh - b * HEADS;
    int r0 = q0 + w*16 + (lane >> 2);
    int col = h*HD + (lane & 3)*2;
    #pragma unroll
    for (int nb = 0; nb < 8; nb++) {
        size_t o0 = ((size_t)(b*NTOK + r0))     * DIM + col + nb*8;
        size_t o1 = ((size_t)(b*NTOK + r0 + 8)) * DIM + col + nb*8;
        float a0 = acc[nb][0]*inv0, a1 = acc[nb][1]*inv0;
        float a2 = acc[nb][2]*inv1, a3 = acc[nb][3]*inv1;
        __nv_bfloat162 hh, ll;
        hh = __floats2bfloat162_rn(a0, a1);
        ll = __floats2bfloat162_rn(a0 - __bfloat162float(hh.x),
                                   a1 - __bfloat162float(hh.y));
        *(__nv_bfloat162*)&g_ohh[o0] = hh;
        *(__nv_bfloat162*)&g_oll[o0] = ll;
        hh = __floats2bfloat162_rn(a2, a3);
        ll = __floats2bfloat162_rn(a2 - __bfloat162float(hh.x),
                                   a3 - __bfloat162float(hh.y));
        *(__nv_bfloat162*)&g_ohh[o1] = hh;
        *(__nv_bfloat162*)&g_oll[o1] = ll;
    }
}

// ==================== launcher ====================
extern "C" void kernel_launch(void* const* d_in, const int* in_sizes, int n_in,
                              void* d_out, int out_size)
{
    const float* x      = (const float*)d_in[0];
    const float* w_qkv  = (const float*)d_in[1];
    const float* b_qkv  = (const float*)d_in[2];
    const float* w_proj = (const float*)d_in[3];
    const float* b_proj = (const float*)d_in[4];
    float* out = (float*)d_out;

    void *xh, *xl, *wqh, *wql, *wph, *wpl, *ohh, *oll;
    cudaGetSymbolAddress(&xh,  g_xh);  cudaGetSymbolAddress(&xl,  g_xl);
    cudaGetSymbolAddress(&wqh, g_wqh); cudaGetSymbolAddress(&wql, g_wql);
    cudaGetSymbolAddress(&wph, g_wph); cudaGetSymbolAddress(&wpl, g_wpl);
    cudaGetSymbolAddress(&ohh, g_ohh); cudaGetSymbolAddress(&oll, g_oll);

    cudaFuncSetAttribute(gemm_mma<0>, cudaFuncAttributeMaxDynamicSharedMemorySize,
                         GEMM_SMEM_B);
    cudaFuncSetAttribute(gemm_mma<1>, cudaFuncAttributeMaxDynamicSharedMemorySize,
                         GEMM_SMEM_B);
    cudaFuncSetAttribute(attn_mma, cudaFuncAttributeMaxDynamicSharedMemorySize,
                         ATTN_SMEM);

    split_kernel<<<(MROWS*DIM/4 + 255)/256, 256>>>(
        x, (__nv_bfloat16*)xh, (__nv_bfloat16*)xl, MROWS*DIM/4);
    split_kernel<<<(3*DIM*DIM/4 + 255)/256, 256>>>(
        w_qkv, (__nv_bfloat16*)wqh, (__nv_bfloat16*)wql, 3*DIM*DIM/4);
    split_kernel<<<(DIM*DIM/4 + 255)/256, 256>>>(
        w_proj, (__nv_bfloat16*)wph, (__nv_bfloat16*)wpl, DIM*DIM/4);
    rope_tab_kernel<<<(NTOK*32 + 255)/256, 256>>>();

    // 1) QKV GEMM + bias + RoPE + fp16 scatter
    gemm_mma<1><<<dim3(3*DIM/128, MROWS/128), 256, GEMM_SMEM_B>>>(
        (const __nv_bfloat16*)xh, (const __nv_bfloat16*)xl,
        (const __nv_bfloat16*)wqh, (const __nv_bfloat16*)wql,
        b_qkv, nullptr, MROWS, 3*DIM, DIM);

    // 2) attention (HMMA flash, plain fp16 operands, fp32 accum)
    attn_mma<<<dim3(NTOK/128, BHC), 256, ATTN_SMEM>>>();

    // 3) output projection -> d_out
    gemm_mma<0><<<dim3(DIM/128, MROWS/128), 256, GEMM_SMEM_B>>>(
        (const __nv_bfloat16*)ohh, (const __nv_bfloat16*)oll,
        (const __nv_bfloat16*)wph, (const __nv_bfloat16*)wpl,
        b_proj, out, MROWS, DIM, DIM);
}

// round 12
// speedup vs baseline: 2.4842x; 1.1880x over previous
#include <cuda_runtime.h>
#include <cuda_fp16.h>
#include <math.h>
#include <stdint.h>

#define DIM   768
#define HEADS 12
#define HD    64
#define B_    2
#define WW    48
#define NTOK  2304
#define BHC   24
#define MROWS 4608

// -------- scratch (device globals; no allocation allowed) --------
__device__ __half g_qh[BHC*NTOK*HD];          // Q: fp16 (pre-scaled)
__device__ __half g_kh[BHC*NTOK*HD];          // K: fp16
__device__ __half g_vh[BHC*NTOK*HD];          // V: fp16
__device__ __half g_xh16[MROWS*DIM], g_xl16[MROWS*DIM];   // x hi/lo fp16
__device__ __half g_wq16[3*DIM*DIM];                      // w_qkv fp16
__device__ __half g_wp16[DIM*DIM];                        // w_proj fp16
__device__ __half g_oh16[MROWS*DIM], g_ol16[MROWS*DIM];   // O hi/lo fp16
__device__ float g_sin[NTOK*32], g_cos[NTOK*32];

// ==================== helpers ====================
__device__ __forceinline__ uint32_t smem_u32(const void* p) {
    uint32_t a;
    asm("{ .reg .u64 t; cvta.to.shared.u64 t, %1; cvt.u32.u64 %0, t; }" : "=r"(a) : "l"(p));
    return a;
}
__device__ __forceinline__ void ldsm4(uint32_t* r, uint32_t addr) {
    asm volatile("ldmatrix.sync.aligned.m8n8.x4.shared.b16 {%0,%1,%2,%3}, [%4];"
                 : "=r"(r[0]), "=r"(r[1]), "=r"(r[2]), "=r"(r[3]) : "r"(addr));
}
__device__ __forceinline__ void ldsm4t(uint32_t* r, uint32_t addr) {
    asm volatile("ldmatrix.sync.aligned.m8n8.x4.trans.shared.b16 {%0,%1,%2,%3}, [%4];"
                 : "=r"(r[0]), "=r"(r[1]), "=r"(r[2]), "=r"(r[3]) : "r"(addr));
}
__device__ __forceinline__ void mma_fp(float* d, const uint32_t* a,
                                       uint32_t b0, uint32_t b1) {
    asm volatile(
        "mma.sync.aligned.m16n8k16.row.col.f32.f16.f16.f32 "
        "{%0,%1,%2,%3}, {%4,%5,%6,%7}, {%8,%9}, {%0,%1,%2,%3};"
        : "+f"(d[0]), "+f"(d[1]), "+f"(d[2]), "+f"(d[3])
        : "r"(a[0]), "r"(a[1]), "r"(a[2]), "r"(a[3]), "r"(b0), "r"(b1));
}
// fast e^x on FMA/ALU pipes (no MUFU). |rel err| ~1e-7, x clamped >= -80.
__device__ __forceinline__ float fast_exp(float x) {
    x = fmaxf(x, -80.0f);
    float y = fmaf(x, 1.4426950409f, 12582912.0f);
    float z = y - 12582912.0f;
    int   n = __float_as_int(y) - 0x4B400000;
    float f = fmaf(x, 1.4426950409f, -z);
    float p = 1.3333558e-3f;
    p = fmaf(p, f, 9.6181291e-3f);
    p = fmaf(p, f, 5.5504109e-2f);
    p = fmaf(p, f, 2.4022651e-1f);
    p = fmaf(p, f, 6.9314718e-1f);
    p = fmaf(p, f, 1.0f);
    return __int_as_float(__float_as_int(p) + (n << 23));
}

// ==================== prep kernels ====================
__global__ void __launch_bounds__(256) split16_kernel(
    const float* __restrict__ src, __half* __restrict__ hi,
    __half* __restrict__ lo, int n4)
{
    int i = blockIdx.x * 256 + threadIdx.x;
    if (i >= n4) return;
    float4 v = ((const float4*)src)[i];
    float f[4] = {v.x, v.y, v.z, v.w};
    __half h[4], l[4];
    #pragma unroll
    for (int j = 0; j < 4; j++) {
        h[j] = __float2half_rn(f[j]);
        l[j] = __float2half_rn(f[j] - __half2float(h[j]));
    }
    ((__half2*)hi)[2*i]   = __halves2half2(h[0], h[1]);
    ((__half2*)hi)[2*i+1] = __halves2half2(h[2], h[3]);
    ((__half2*)lo)[2*i]   = __halves2half2(l[0], l[1]);
    ((__half2*)lo)[2*i+1] = __halves2half2(l[2], l[3]);
}

__global__ void __launch_bounds__(256) cvt16_kernel(
    const float* __restrict__ src, __half* __restrict__ dst, int n4)
{
    int i = blockIdx.x * 256 + threadIdx.x;
    if (i >= n4) return;
    float4 v = ((const float4*)src)[i];
    ((__half2*)dst)[2*i]   = __floats2half2_rn(v.x, v.y);
    ((__half2*)dst)[2*i+1] = __floats2half2_rn(v.z, v.w);
}

__global__ void __launch_bounds__(256) rope_tab_kernel()
{
    int idx = blockIdx.x * 256 + threadIdx.x;
    if (idx >= NTOK * 32) return;
    int n = idx >> 5, j = idx & 31;
    int axis = j >> 4, p = j & 15;
    int y = n / WW, x = n - y * WW;
    float idxf  = axis ? (float)x : (float)y;
    float coord = 2.0f * ((idxf + 0.5f) / 48.0f) - 1.0f;
    float invp  = exp2f(-(float)p * 0.41524101186092607f);  // 100^(-p/16)
    float sn, cs; sincosf(6.283185307179586f * coord * invp, &sn, &cs);
    g_sin[idx] = sn; g_cos[idx] = cs;
}

// ==================== mma.sync fp16 GEMM (A split hi/lo, B plain) ======
// C[M,N] = (Ah+Al)[M,K] @ B[N,K]^T + bias ; B fp16 (rounding ~2^-12).
#define TSTRIDE 40
#define TILE_B  (128*TSTRIDE*2)       // 10240 bytes per tile
#define STAGE_B (3*TILE_B)            // Ah | Al | B
#define GEMM_SMEM_B (2*STAGE_B)       // 61440 bytes

__device__ __forceinline__ void g2r(uint4* r,
    const __half* Ah, const __half* Al, const __half* B,
    int bm, int bn, int K, int k0, int tid)
{
    #pragma unroll
    for (int p = 0; p < 2; p++) {
        int id = p * 256 + tid;
        int row = id >> 2, kc = id & 3;
        size_t oA = (size_t)(bm + row) * K + k0 + kc * 8;
        size_t oB = (size_t)(bn + row) * K + k0 + kc * 8;
        r[0+p] = *(const uint4*)&Ah[oA];
        r[2+p] = *(const uint4*)&Al[oA];
        r[4+p] = *(const uint4*)&B[oB];
    }
}
__device__ __forceinline__ void r2s(__half* sm, const uint4* r, int tid, int st)
{
    #pragma unroll
    for (int p = 0; p < 2; p++) {
        int id = p * 256 + tid;
        int off = (id >> 2) * TSTRIDE + (id & 3) * 8;
        #pragma unroll
        for (int t = 0; t < 3; t++)
            *(uint4*)&sm[(st*3 + t) * (128*TSTRIDE) + off] = r[t*2 + p];
    }
}

template<int EPI>
__global__ void __launch_bounds__(256, 1) gemm_mma(
    const __half* __restrict__ Ah, const __half* __restrict__ Al,
    const __half* __restrict__ Bm,
    const float* __restrict__ bias, float* __restrict__ C, int M, int N, int K)
{
    extern __shared__ __align__(16) __half sm[];
    const uint32_t sbase = smem_u32(sm);
    const int tid = threadIdx.x;
    const int lane = tid & 31, wid = tid >> 5;
    const int wm = wid & 3, wn = wid >> 2;
    const int bm = blockIdx.y * 128, bn = blockIdx.x * 128;
    const int piece = lane >> 3, pr = lane & 7;

    float acc[2][8][4];
    #pragma unroll
    for (int i = 0; i < 2; i++)
        #pragma unroll
        for (int j = 0; j < 8; j++)
            #pragma unroll
            for (int k = 0; k < 4; k++) acc[i][j][k] = 0.0f;

    const int nit = K >> 5;
    uint4 r[6];
    g2r(r, Ah, Al, Bm, bm, bn, K, 0, tid);
    r2s(sm, r, tid, 0);
    __syncthreads();

    const int arow = wm*32 + (piece & 1)*8 + pr;
    const int brow = wn*64 + (piece & 1)*8 + pr;
    const int kofp = (piece >> 1) * 8;

    for (int it = 0; it < nit; it++) {
        int st = it & 1;
        bool more = (it + 1) < nit;
        if (more) g2r(r, Ah, Al, Bm, bm, bn, K, (it + 1) << 5, tid);

        uint32_t tA = sbase + (uint32_t)(st*3) * TILE_B;
        #pragma unroll
        for (int ks = 0; ks < 2; ks++) {
            int koff = ks*16 + kofp;
            uint32_t ah[2][4], al[2][4];
            #pragma unroll
            for (int mt = 0; mt < 2; mt++) {
                uint32_t ad = tA + ((arow + mt*16) * TSTRIDE + koff) * 2;
                ldsm4(ah[mt], ad);
                ldsm4(al[mt], ad + TILE_B);
            }
            #pragma unroll
            for (int np = 0; np < 4; np++) {
                uint32_t bd = tA + 2*TILE_B
                            + ((brow + np*16) * TSTRIDE + koff) * 2;
                uint32_t b4[4];
                ldsm4(b4, bd);
                #pragma unroll
                for (int mt = 0; mt < 2; mt++) {
                    mma_fp(acc[mt][np*2],   ah[mt], b4[0], b4[2]);
                    mma_fp(acc[mt][np*2+1], ah[mt], b4[1], b4[3]);
                    mma_fp(acc[mt][np*2],   al[mt], b4[0], b4[2]);
                    mma_fp(acc[mt][np*2+1], al[mt], b4[1], b4[3]);
                }
            }
        }
        // Single barrier per iteration (see R9 note).
        if (more) r2s(sm, r, tid, st ^ 1);
        __syncthreads();
    }

    const int cbase = bn + wn * 64;
    if (EPI == 0) {
        #pragma unroll
        for (int mt = 0; mt < 2; mt++)
            #pragma unroll
            for (int half = 0; half < 2; half++) {
                int m = bm + wm*32 + mt*16 + (lane >> 2) + half*8;
                #pragma unroll
                for (int nt = 0; nt < 8; nt++) {
                    int c = cbase + nt*8 + (lane & 3)*2;
                    float2 v;
                    v.x = acc[mt][nt][half*2+0] + bias[c];
                    v.y = acc[mt][nt][half*2+1] + bias[c+1];
                    *(float2*)&C[(size_t)m * N + c] = v;
                }
            }
    } else {
        // QKV epilogue: Q (+RoPE, prescale) / K (+RoPE) / V -> plain fp16.
        int which = cbase / DIM;
        int h = (cbase % DIM) >> 6;
        __half* dstp = (which == 0) ? g_qh : (which == 1) ? g_kh : g_vh;
        #pragma unroll
        for (int mt = 0; mt < 2; mt++)
            #pragma unroll
            for (int half = 0; half < 2; half++) {
                int m = bm + wm*32 + mt*16 + (lane >> 2) + half*8;
                int bb = m / NTOK, pos = m - bb * NTOK;
                size_t dof = ((size_t)(bb*HEADS + h) * NTOK + pos) * HD;
                __half* dst = dstp + dof;
                if (which < 2) {
                    const float qs = (which == 0) ? 0.125f : 1.0f;
                    #pragma unroll
                    for (int nt = 0; nt < 4; nt++) {
                        int d0 = nt*8 + (lane & 3)*2;
                        float rl[2], rh[2];
                        #pragma unroll
                        for (int j = 0; j < 2; j++) {
                            float vlo = acc[mt][nt][half*2+j]   + bias[cbase + d0 + j];
                            float vhi = acc[mt][nt+4][half*2+j] + bias[cbase + 32 + d0 + j];
                            float sn = g_sin[pos*32 + d0 + j];
                            float cs = g_cos[pos*32 + d0 + j];
                            rl[j] = (vlo*cs - vhi*sn) * qs;
                            rh[j] = (vhi*cs + vlo*sn) * qs;
                        }
                        *(__half2*)&dst[d0]      = __floats2half2_rn(rl[0], rl[1]);
                        *(__half2*)&dst[32 + d0] = __floats2half2_rn(rh[0], rh[1]);
                    }
                } else {
                    #pragma unroll
                    for (int nt = 0; nt < 8; nt++) {
                        int d = nt*8 + (lane & 3)*2;
                        float v0 = acc[mt][nt][half*2+0] + bias[cbase + d];
                        float v1 = acc[mt][nt][half*2+1] + bias[cbase + d + 1];
                        *(__half2*)&dst[d] = __floats2half2_rn(v0, v1);
                    }
                }
            }
    }
}

// ==================== attention: HMMA flash (plain fp16, fp32 accum) ====
#define AST 72
#define ATTN_SMEM (128*AST*2)   // 18432 B (Q staging; K/V tiles reuse)

__global__ void __launch_bounds__(256, 2) attn_mma()
{
    extern __shared__ __align__(16) __half smh[];
    const uint32_t sb = smem_u32(smh);
    __half* sKh = smh;             // [64][AST]
    __half* sVh = smh + 64*AST;    // [64][AST]

    const int tid = threadIdx.x;
    const int lane = tid & 31, w = tid >> 5;
    const int l15 = lane & 15, l16 = lane >> 4;
    const int bh = blockIdx.y, q0 = blockIdx.x * 128;

    const __half* Qh = g_qh + ((size_t)bh * NTOK + q0) * HD;
    const __half* Kh = g_kh + (size_t)bh * NTOK * HD;
    const __half* Vh = g_vh + (size_t)bh * NTOK * HD;

    // ---- stage Q, extract A-fragments, then buffer is reused for K/V ----
    #pragma unroll
    for (int t = 0; t < 4; t++) {
        int lin = t * 256 + tid;
        int row = lin >> 3, c = (lin & 7) * 8;
        *(uint4*)&smh[row * AST + c] = *(const uint4*)&Qh[(size_t)row * HD + c];
    }
    __syncthreads();
    uint32_t qf[4][4];
    {
        uint32_t qa = sb + (((w*16 + l15) * AST) + l16*8) * 2;
        #pragma unroll
        for (int ks = 0; ks < 4; ks++)
            ldsm4(qf[ks], qa + ks*32);
    }

    float acc[8][4];
    #pragma unroll
    for (int i = 0; i < 8; i++)
        #pragma unroll
        for (int j = 0; j < 4; j++) acc[i][j] = 0.0f;
    float m0 = -1e30f, m1 = -1e30f, l0 = 0.0f, l1 = 0.0f;

    const uint32_t kbase = sb + (l15 * AST + l16*8) * 2;
    const uint32_t vbase = sb + 64*AST*2 + (l15 * AST + l16*8) * 2;

    for (int t = 0; t < NTOK/64; t++) {
        const int k0 = t * 64;
        uint4 rv[4];
        #pragma unroll
        for (int i = 0; i < 4; i++) {
            int lin = i * 256 + tid;
            int arr = lin >> 9, rem = lin & 511;
            int row = rem >> 3, c = (rem & 7) * 8;
            const __half* src = (arr == 0 ? Kh : Vh) + (size_t)(k0 + row) * HD + c;
            rv[i] = *(const uint4*)src;
        }
        __syncthreads();   // prior readers done (iter0: qf ldsm done)
        #pragma unroll
        for (int i = 0; i < 4; i++) {
            int lin = i * 256 + tid;
            int arr = lin >> 9, rem = lin & 511;
            int row = rem >> 3, c = (rem & 7) * 8;
            __half* dst = (arr == 0 ? sKh : sVh) + row * AST + c;
            *(uint4*)dst = rv[i];
        }
        __syncthreads();

        // ---- S = Q K^T ----
        float s[8][4];
        #pragma unroll
        for (int i = 0; i < 8; i++)
            #pragma unroll
            for (int j = 0; j < 4; j++) s[i][j] = 0.0f;
        #pragma unroll
        for (int ks = 0; ks < 4; ks++) {
            #pragma unroll
            for (int nbp = 0; nbp < 8; nbp += 2) {
                uint32_t kh4[4];
                ldsm4(kh4, kbase + (nbp*8*AST + ks*16) * 2);
                mma_fp(s[nbp],   qf[ks], kh4[0], kh4[2]);
                mma_fp(s[nbp+1], qf[ks], kh4[1], kh4[3]);
            }
        }

        // ---- online softmax ----
        float mx0 = -1e30f, mx1 = -1e30f;
        #pragma unroll
        for (int i = 0; i < 8; i++) {
            mx0 = fmaxf(mx0, fmaxf(s[i][0], s[i][1]));
            mx1 = fmaxf(mx1, fmaxf(s[i][2], s[i][3]));
        }
        mx0 = fmaxf(mx0, __shfl_xor_sync(0xffffffffu, mx0, 1));
        mx0 = fmaxf(mx0, __shfl_xor_sync(0xffffffffu, mx0, 2));
        mx1 = fmaxf(mx1, __shfl_xor_sync(0xffffffffu, mx1, 1));
        mx1 = fmaxf(mx1, __shfl_xor_sync(0xffffffffu, mx1, 2));
        float nm0 = fmaxf(m0, mx0), nm1 = fmaxf(m1, mx1);
        float f0 = fast_exp(m0 - nm0), f1 = fast_exp(m1 - nm1);
        m0 = nm0; m1 = nm1;
        float sum0 = 0.0f, sum1 = 0.0f;
        #pragma unroll
        for (int i = 0; i < 8; i++) {
            s[i][0] = fast_exp(s[i][0] - nm0); sum0 += s[i][0];
            s[i][1] = fast_exp(s[i][1] - nm0); sum0 += s[i][1];
            s[i][2] = fast_exp(s[i][2] - nm1); sum1 += s[i][2];
            s[i][3] = fast_exp(s[i][3] - nm1); sum1 += s[i][3];
        }
        sum0 += __shfl_xor_sync(0xffffffffu, sum0, 1);
        sum0 += __shfl_xor_sync(0xffffffffu, sum0, 2);
        sum1 += __shfl_xor_sync(0xffffffffu, sum1, 1);
        sum1 += __shfl_xor_sync(0xffffffffu, sum1, 2);
        l0 = l0 * f0 + sum0;
        l1 = l1 * f1 + sum1;
        #pragma unroll
        for (int i = 0; i < 8; i++) {
            acc[i][0] *= f0; acc[i][1] *= f0;
            acc[i][2] *= f1; acc[i][3] *= f1;
        }

        // ---- P -> fp16 A-fragments ----
        uint32_t ap[4][4];
        #pragma unroll
        for (int ks = 0; ks < 4; ks++) {
            int n0 = 2*ks, n1 = 2*ks + 1;
            __half2 h0 = __floats2half2_rn(s[n0][0], s[n0][1]);
            __half2 h1 = __floats2half2_rn(s[n0][2], s[n0][3]);
            __half2 h2 = __floats2half2_rn(s[n1][0], s[n1][1]);
            __half2 h3 = __floats2half2_rn(s[n1][2], s[n1][3]);
            ap[ks][0] = *(uint32_t*)&h0;
            ap[ks][1] = *(uint32_t*)&h1;
            ap[ks][2] = *(uint32_t*)&h2;
            ap[ks][3] = *(uint32_t*)&h3;
        }

        // ---- O += P V ----
        #pragma unroll
        for (int ks = 0; ks < 4; ks++) {
            #pragma unroll
            for (int nbp = 0; nbp < 8; nbp += 2) {
                uint32_t vh4[4];
                ldsm4t(vh4, vbase + (ks*16*AST + nbp*8) * 2);
                mma_fp(acc[nbp],   ap[ks], vh4[0], vh4[1]);
                mma_fp(acc[nbp+1], ap[ks], vh4[2], vh4[3]);
            }
        }
    }

    // ---- normalize + write O as fp16 hi/lo, [b, n, h*64 + d] ----
    float inv0 = 1.0f / l0, inv1 = 1.0f / l1;
    int b = bh / HEADS, h = bh - b * HEADS;
    int r0 = q0 + w*16 + (lane >> 2);
    int col = h*HD + (lane & 3)*2;
    #pragma unroll
    for (int nb = 0; nb < 8; nb++) {
        size_t o0 = ((size_t)(b*NTOK + r0))     * DIM + col + nb*8;
        size_t o1 = ((size_t)(b*NTOK + r0 + 8)) * DIM + col + nb*8;
        float a0 = acc[nb][0]*inv0, a1 = acc[nb][1]*inv0;
        float a2 = acc[nb][2]*inv1, a3 = acc[nb][3]*inv1;
        __half2 hh, ll;
        hh = __floats2half2_rn(a0, a1);
        ll = __floats2half2_rn(a0 - __low2float(hh), a1 - __high2float(hh));
        *(__half2*)&g_oh16[o0] = hh;
        *(__half2*)&g_ol16[o0] = ll;
        hh = __floats2half2_rn(a2, a3);
        ll = __floats2half2_rn(a2 - __low2float(hh), a3 - __high2float(hh));
        *(__half2*)&g_oh16[o1] = hh;
        *(__half2*)&g_ol16[o1] = ll;
    }
}

// ==================== launcher ====================
extern "C" void kernel_launch(void* const* d_in, const int* in_sizes, int n_in,
                              void* d_out, int out_size)
{
    const float* x      = (const float*)d_in[0];
    const float* w_qkv  = (const float*)d_in[1];
    const float* b_qkv  = (const float*)d_in[2];
    const float* w_proj = (const float*)d_in[3];
    const float* b_proj = (const float*)d_in[4];
    float* out = (float*)d_out;

    void *xh, *xl, *wq, *wp, *oh, *ol;
    cudaGetSymbolAddress(&xh, g_xh16); cudaGetSymbolAddress(&xl, g_xl16);
    cudaGetSymbolAddress(&wq, g_wq16); cudaGetSymbolAddress(&wp, g_wp16);
    cudaGetSymbolAddress(&oh, g_oh16); cudaGetSymbolAddress(&ol, g_ol16);

    cudaFuncSetAttribute(gemm_mma<0>, cudaFuncAttributeMaxDynamicSharedMemorySize,
                         GEMM_SMEM_B);
    cudaFuncSetAttribute(gemm_mma<1>, cudaFuncAttributeMaxDynamicSharedMemorySize,
                         GEMM_SMEM_B);
    cudaFuncSetAttribute(attn_mma, cudaFuncAttributeMaxDynamicSharedMemorySize,
                         ATTN_SMEM);

    split16_kernel<<<(MROWS*DIM/4 + 255)/256, 256>>>(
        x, (__half*)xh, (__half*)xl, MROWS*DIM/4);
    cvt16_kernel<<<(3*DIM*DIM/4 + 255)/256, 256>>>(
        w_qkv, (__half*)wq, 3*DIM*DIM/4);
    cvt16_kernel<<<(DIM*DIM/4 + 255)/256, 256>>>(
        w_proj, (__half*)wp, DIM*DIM/4);
    rope_tab_kernel<<<(NTOK*32 + 255)/256, 256>>>();

    // 1) QKV GEMM + bias + RoPE + fp16 scatter
    gemm_mma<1><<<dim3(3*DIM/128, MROWS/128), 256, GEMM_SMEM_B>>>(
        (const __half*)xh, (const __half*)xl, (const __half*)wq,
        b_qkv, nullptr, MROWS, 3*DIM, DIM);

    // 2) attention (HMMA flash, plain fp16 operands, fp32 accum)
    attn_mma<<<dim3(NTOK/128, BHC), 256, ATTN_SMEM>>>();

    // 3) output projection -> d_out
    gemm_mma<0><<<dim3(DIM/128, MROWS/128), 256, GEMM_SMEM_B>>>(
        (const __half*)oh, (const __half*)ol, (const __half*)wp,
        b_proj, out, MROWS, DIM, DIM);
}

// round 13
// speedup vs baseline: 3.0914x; 1.2444x over previous
#include <cuda_runtime.h>
#include <cuda_fp16.h>
#include <math.h>
#include <stdint.h>

#define DIM   768
#define HEADS 12
#define HD    64
#define B_    2
#define WW    48
#define NTOK  2304
#define BHC   24
#define MROWS 4608

// -------- scratch (device globals; no allocation allowed) --------
__device__ __half g_qh[BHC*NTOK*HD];          // Q: fp16 (pre-scaled)
__device__ __half g_kh[BHC*NTOK*HD];          // K: fp16
__device__ __half g_vh[BHC*NTOK*HD];          // V: fp16
__device__ __half g_x16[MROWS*DIM];           // x fp16
__device__ __half g_wq16[3*DIM*DIM];          // w_qkv fp16
__device__ __half g_wp16[DIM*DIM];            // w_proj fp16
__device__ __half g_o16[MROWS*DIM];           // O fp16
__device__ float g_sin[NTOK*32], g_cos[NTOK*32];

// ==================== helpers ====================
__device__ __forceinline__ uint32_t smem_u32(const void* p) {
    uint32_t a;
    asm("{ .reg .u64 t; cvta.to.shared.u64 t, %1; cvt.u32.u64 %0, t; }" : "=r"(a) : "l"(p));
    return a;
}
__device__ __forceinline__ void ldsm4(uint32_t* r, uint32_t addr) {
    asm volatile("ldmatrix.sync.aligned.m8n8.x4.shared.b16 {%0,%1,%2,%3}, [%4];"
                 : "=r"(r[0]), "=r"(r[1]), "=r"(r[2]), "=r"(r[3]) : "r"(addr));
}
__device__ __forceinline__ void ldsm4t(uint32_t* r, uint32_t addr) {
    asm volatile("ldmatrix.sync.aligned.m8n8.x4.trans.shared.b16 {%0,%1,%2,%3}, [%4];"
                 : "=r"(r[0]), "=r"(r[1]), "=r"(r[2]), "=r"(r[3]) : "r"(addr));
}
__device__ __forceinline__ void mma_fp(float* d, const uint32_t* a,
                                       uint32_t b0, uint32_t b1) {
    asm volatile(
        "mma.sync.aligned.m16n8k16.row.col.f32.f16.f16.f32 "
        "{%0,%1,%2,%3}, {%4,%5,%6,%7}, {%8,%9}, {%0,%1,%2,%3};"
        : "+f"(d[0]), "+f"(d[1]), "+f"(d[2]), "+f"(d[3])
        : "r"(a[0]), "r"(a[1]), "r"(a[2]), "r"(a[3]), "r"(b0), "r"(b1));
}
// fast e^x on FMA/ALU pipes (no MUFU). |rel err| ~1e-7, x clamped >= -80.
__device__ __forceinline__ float fast_exp(float x) {
    x = fmaxf(x, -80.0f);
    float y = fmaf(x, 1.4426950409f, 12582912.0f);
    float z = y - 12582912.0f;
    int   n = __float_as_int(y) - 0x4B400000;
    float f = fmaf(x, 1.4426950409f, -z);
    float p = 1.3333558e-3f;
    p = fmaf(p, f, 9.6181291e-3f);
    p = fmaf(p, f, 5.5504109e-2f);
    p = fmaf(p, f, 2.4022651e-1f);
    p = fmaf(p, f, 6.9314718e-1f);
    p = fmaf(p, f, 1.0f);
    return __int_as_float(__float_as_int(p) + (n << 23));
}

// ==================== prep kernels ====================
__global__ void __launch_bounds__(256) cvt16_kernel(
    const float* __restrict__ src, __half* __restrict__ dst, int n4)
{
    int i = blockIdx.x * 256 + threadIdx.x;
    if (i >= n4) return;
    float4 v = ((const float4*)src)[i];
    ((__half2*)dst)[2*i]   = __floats2half2_rn(v.x, v.y);
    ((__half2*)dst)[2*i+1] = __floats2half2_rn(v.z, v.w);
}

__global__ void __launch_bounds__(256) rope_tab_kernel()
{
    int idx = blockIdx.x * 256 + threadIdx.x;
    if (idx >= NTOK * 32) return;
    int n = idx >> 5, j = idx & 31;
    int axis = j >> 4, p = j & 15;
    int y = n / WW, x = n - y * WW;
    float idxf  = axis ? (float)x : (float)y;
    float coord = 2.0f * ((idxf + 0.5f) / 48.0f) - 1.0f;
    float invp  = exp2f(-(float)p * 0.41524101186092607f);  // 100^(-p/16)
    float sn, cs; sincosf(6.283185307179586f * coord * invp, &sn, &cs);
    g_sin[idx] = sn; g_cos[idx] = cs;
}

// ==================== mma.sync fp16 GEMM (plain fp16, fp32 accum) ======
// C[M,N] = A[M,K] @ B[N,K]^T + bias
#define TSTRIDE 40
#define TILE_B  (128*TSTRIDE*2)       // 10240 bytes per tile
#define STAGE_B (2*TILE_B)            // A | B
#define GEMM_SMEM_B (2*STAGE_B)       // 40960 bytes

__device__ __forceinline__ void g2r(uint4* r,
    const __half* A, const __half* B,
    int bm, int bn, int K, int k0, int tid)
{
    #pragma unroll
    for (int p = 0; p < 2; p++) {
        int id = p * 256 + tid;
        int row = id >> 2, kc = id & 3;
        r[0+p] = *(const uint4*)&A[(size_t)(bm + row) * K + k0 + kc * 8];
        r[2+p] = *(const uint4*)&B[(size_t)(bn + row) * K + k0 + kc * 8];
    }
}
__device__ __forceinline__ void r2s(__half* sm, const uint4* r, int tid, int st)
{
    #pragma unroll
    for (int p = 0; p < 2; p++) {
        int id = p * 256 + tid;
        int off = (id >> 2) * TSTRIDE + (id & 3) * 8;
        #pragma unroll
        for (int t = 0; t < 2; t++)
            *(uint4*)&sm[(st*2 + t) * (128*TSTRIDE) + off] = r[t*2 + p];
    }
}

template<int EPI>
__global__ void __launch_bounds__(256, 1) gemm_mma(
    const __half* __restrict__ A, const __half* __restrict__ Bm,
    const float* __restrict__ bias, float* __restrict__ C, int M, int N, int K)
{
    extern __shared__ __align__(16) __half sm[];
    const uint32_t sbase = smem_u32(sm);
    const int tid = threadIdx.x;
    const int lane = tid & 31, wid = tid >> 5;
    const int wm = wid & 3, wn = wid >> 2;
    const int bm = blockIdx.y * 128, bn = blockIdx.x * 128;
    const int piece = lane >> 3, pr = lane & 7;

    float acc[2][8][4];
    #pragma unroll
    for (int i = 0; i < 2; i++)
        #pragma unroll
        for (int j = 0; j < 8; j++)
            #pragma unroll
            for (int k = 0; k < 4; k++) acc[i][j][k] = 0.0f;

    const int nit = K >> 5;
    uint4 r[4];
    g2r(r, A, Bm, bm, bn, K, 0, tid);
    r2s(sm, r, tid, 0);
    __syncthreads();

    const int arow = wm*32 + (piece & 1)*8 + pr;
    const int brow = wn*64 + (piece & 1)*8 + pr;
    const int kofp = (piece >> 1) * 8;

    for (int it = 0; it < nit; it++) {
        int st = it & 1;
        bool more = (it + 1) < nit;
        if (more) g2r(r, A, Bm, bm, bn, K, (it + 1) << 5, tid);

        uint32_t tA = sbase + (uint32_t)(st*2) * TILE_B;
        #pragma unroll
        for (int ks = 0; ks < 2; ks++) {
            int koff = ks*16 + kofp;
            uint32_t ah[2][4];
            #pragma unroll
            for (int mt = 0; mt < 2; mt++)
                ldsm4(ah[mt], tA + ((arow + mt*16) * TSTRIDE + koff) * 2);
            #pragma unroll
            for (int np = 0; np < 4; np++) {
                uint32_t b4[4];
                ldsm4(b4, tA + TILE_B + ((brow + np*16) * TSTRIDE + koff) * 2);
                #pragma unroll
                for (int mt = 0; mt < 2; mt++) {
                    mma_fp(acc[mt][np*2],   ah[mt], b4[0], b4[2]);
                    mma_fp(acc[mt][np*2+1], ah[mt], b4[1], b4[3]);
                }
            }
        }
        // Single barrier per iteration (see R9 note).
        if (more) r2s(sm, r, tid, st ^ 1);
        __syncthreads();
    }

    const int cbase = bn + wn * 64;
    if (EPI == 0) {
        #pragma unroll
        for (int mt = 0; mt < 2; mt++)
            #pragma unroll
            for (int half = 0; half < 2; half++) {
                int m = bm + wm*32 + mt*16 + (lane >> 2) + half*8;
                #pragma unroll
                for (int nt = 0; nt < 8; nt++) {
                    int c = cbase + nt*8 + (lane & 3)*2;
                    float2 v;
                    v.x = acc[mt][nt][half*2+0] + bias[c];
                    v.y = acc[mt][nt][half*2+1] + bias[c+1];
                    *(float2*)&C[(size_t)m * N + c] = v;
                }
            }
    } else {
        // QKV epilogue: Q (+RoPE, prescale) / K (+RoPE) / V -> plain fp16.
        int which = cbase / DIM;
        int h = (cbase % DIM) >> 6;
        __half* dstp = (which == 0) ? g_qh : (which == 1) ? g_kh : g_vh;
        #pragma unroll
        for (int mt = 0; mt < 2; mt++)
            #pragma unroll
            for (int half = 0; half < 2; half++) {
                int m = bm + wm*32 + mt*16 + (lane >> 2) + half*8;
                int bb = m / NTOK, pos = m - bb * NTOK;
                size_t dof = ((size_t)(bb*HEADS + h) * NTOK + pos) * HD;
                __half* dst = dstp + dof;
                if (which < 2) {
                    const float qs = (which == 0) ? 0.125f : 1.0f;
                    #pragma unroll
                    for (int nt = 0; nt < 4; nt++) {
                        int d0 = nt*8 + (lane & 3)*2;
                        float rl[2], rh[2];
                        #pragma unroll
                        for (int j = 0; j < 2; j++) {
                            float vlo = acc[mt][nt][half*2+j]   + bias[cbase + d0 + j];
                            float vhi = acc[mt][nt+4][half*2+j] + bias[cbase + 32 + d0 + j];
                            float sn = g_sin[pos*32 + d0 + j];
                            float cs = g_cos[pos*32 + d0 + j];
                            rl[j] = (vlo*cs - vhi*sn) * qs;
                            rh[j] = (vhi*cs + vlo*sn) * qs;
                        }
                        *(__half2*)&dst[d0]      = __floats2half2_rn(rl[0], rl[1]);
                        *(__half2*)&dst[32 + d0] = __floats2half2_rn(rh[0], rh[1]);
                    }
                } else {
                    #pragma unroll
                    for (int nt = 0; nt < 8; nt++) {
                        int d = nt*8 + (lane & 3)*2;
                        float v0 = acc[mt][nt][half*2+0] + bias[cbase + d];
                        float v1 = acc[mt][nt][half*2+1] + bias[cbase + d + 1];
                        *(__half2*)&dst[d] = __floats2half2_rn(v0, v1);
                    }
                }
            }
    }
}

// ==================== attention: HMMA flash (plain fp16, fp32 accum) ====
#define AST 72
#define ATTN_SMEM (128*AST*2)   // 18432 B (Q staging; K/V tiles reuse)

__global__ void __launch_bounds__(256, 2) attn_mma()
{
    extern __shared__ __align__(16) __half smh[];
    const uint32_t sb = smem_u32(smh);
    __half* sKh = smh;             // [64][AST]
    __half* sVh = smh + 64*AST;    // [64][AST]

    const int tid = threadIdx.x;
    const int lane = tid & 31, w = tid >> 5;
    const int l15 = lane & 15, l16 = lane >> 4;
    const int bh = blockIdx.y, q0 = blockIdx.x * 128;

    const __half* Qh = g_qh + ((size_t)bh * NTOK + q0) * HD;
    const __half* Kh = g_kh + (size_t)bh * NTOK * HD;
    const __half* Vh = g_vh + (size_t)bh * NTOK * HD;

    // ---- stage Q, extract A-fragments, then buffer is reused for K/V ----
    #pragma unroll
    for (int t = 0; t < 4; t++) {
        int lin = t * 256 + tid;
        int row = lin >> 3, c = (lin & 7) * 8;
        *(uint4*)&smh[row * AST + c] = *(const uint4*)&Qh[(size_t)row * HD + c];
    }
    __syncthreads();
    uint32_t qf[4][4];
    {
        uint32_t qa = sb + (((w*16 + l15) * AST) + l16*8) * 2;
        #pragma unroll
        for (int ks = 0; ks < 4; ks++)
            ldsm4(qf[ks], qa + ks*32);
    }

    float acc[8][4];
    #pragma unroll
    for (int i = 0; i < 8; i++)
        #pragma unroll
        for (int j = 0; j < 4; j++) acc[i][j] = 0.0f;
    float m0 = -1e30f, m1 = -1e30f, l0 = 0.0f, l1 = 0.0f;

    const uint32_t kbase = sb + (l15 * AST + l16*8) * 2;
    const uint32_t vbase = sb + 64*AST*2 + (l15 * AST + l16*8) * 2;

    for (int t = 0; t < NTOK/64; t++) {
        const int k0 = t * 64;
        uint4 rv[4];
        #pragma unroll
        for (int i = 0; i < 4; i++) {
            int lin = i * 256 + tid;
            int arr = lin >> 9, rem = lin & 511;
            int row = rem >> 3, c = (rem & 7) * 8;
            const __half* src = (arr == 0 ? Kh : Vh) + (size_t)(k0 + row) * HD + c;
            rv[i] = *(const uint4*)src;
        }
        __syncthreads();   // prior readers done (iter0: qf ldsm done)
        #pragma unroll
        for (int i = 0; i < 4; i++) {
            int lin = i * 256 + tid;
            int arr = lin >> 9, rem = lin & 511;
            int row = rem >> 3, c = (rem & 7) * 8;
            __half* dst = (arr == 0 ? sKh : sVh) + row * AST + c;
            *(uint4*)dst = rv[i];
        }
        __syncthreads();

        // ---- S = Q K^T ----
        float s[8][4];
        #pragma unroll
        for (int i = 0; i < 8; i++)
            #pragma unroll
            for (int j = 0; j < 4; j++) s[i][j] = 0.0f;
        #pragma unroll
        for (int ks = 0; ks < 4; ks++) {
            #pragma unroll
            for (int nbp = 0; nbp < 8; nbp += 2) {
                uint32_t kh4[4];
                ldsm4(kh4, kbase + (nbp*8*AST + ks*16) * 2);
                mma_fp(s[nbp],   qf[ks], kh4[0], kh4[2]);
                mma_fp(s[nbp+1], qf[ks], kh4[1], kh4[3]);
            }
        }

        // ---- online softmax ----
        float mx0 = -1e30f, mx1 = -1e30f;
        #pragma unroll
        for (int i = 0; i < 8; i++) {
            mx0 = fmaxf(mx0, fmaxf(s[i][0], s[i][1]));
            mx1 = fmaxf(mx1, fmaxf(s[i][2], s[i][3]));
        }
        mx0 = fmaxf(mx0, __shfl_xor_sync(0xffffffffu, mx0, 1));
        mx0 = fmaxf(mx0, __shfl_xor_sync(0xffffffffu, mx0, 2));
        mx1 = fmaxf(mx1, __shfl_xor_sync(0xffffffffu, mx1, 1));
        mx1 = fmaxf(mx1, __shfl_xor_sync(0xffffffffu, mx1, 2));
        float nm0 = fmaxf(m0, mx0), nm1 = fmaxf(m1, mx1);
        float f0 = fast_exp(m0 - nm0), f1 = fast_exp(m1 - nm1);
        m0 = nm0; m1 = nm1;
        float sum0 = 0.0f, sum1 = 0.0f;
        #pragma unroll
        for (int i = 0; i < 8; i++) {
            s[i][0] = fast_exp(s[i][0] - nm0); sum0 += s[i][0];
            s[i][1] = fast_exp(s[i][1] - nm0); sum0 += s[i][1];
            s[i][2] = fast_exp(s[i][2] - nm1); sum1 += s[i][2];
            s[i][3] = fast_exp(s[i][3] - nm1); sum1 += s[i][3];
        }
        sum0 += __shfl_xor_sync(0xffffffffu, sum0, 1);
        sum0 += __shfl_xor_sync(0xffffffffu, sum0, 2);
        sum1 += __shfl_xor_sync(0xffffffffu, sum1, 1);
        sum1 += __shfl_xor_sync(0xffffffffu, sum1, 2);
        l0 = l0 * f0 + sum0;
        l1 = l1 * f1 + sum1;
        #pragma unroll
        for (int i = 0; i < 8; i++) {
            acc[i][0] *= f0; acc[i][1] *= f0;
            acc[i][2] *= f1; acc[i][3] *= f1;
        }

        // ---- P -> fp16 A-fragments ----
        uint32_t ap[4][4];
        #pragma unroll
        for (int ks = 0; ks < 4; ks++) {
            int n0 = 2*ks, n1 = 2*ks + 1;
            __half2 h0 = __floats2half2_rn(s[n0][0], s[n0][1]);
            __half2 h1 = __floats2half2_rn(s[n0][2], s[n0][3]);
            __half2 h2 = __floats2half2_rn(s[n1][0], s[n1][1]);
            __half2 h3 = __floats2half2_rn(s[n1][2], s[n1][3]);
            ap[ks][0] = *(uint32_t*)&h0;
            ap[ks][1] = *(uint32_t*)&h1;
            ap[ks][2] = *(uint32_t*)&h2;
            ap[ks][3] = *(uint32_t*)&h3;
        }

        // ---- O += P V ----
        #pragma unroll
        for (int ks = 0; ks < 4; ks++) {
            #pragma unroll
            for (int nbp = 0; nbp < 8; nbp += 2) {
                uint32_t vh4[4];
                ldsm4t(vh4, vbase + (ks*16*AST + nbp*8) * 2);
                mma_fp(acc[nbp],   ap[ks], vh4[0], vh4[1]);
                mma_fp(acc[nbp+1], ap[ks], vh4[2], vh4[3]);
            }
        }
    }

    // ---- normalize + write O as fp16, [b, n, h*64 + d] ----
    float inv0 = 1.0f / l0, inv1 = 1.0f / l1;
    int b = bh / HEADS, h = bh - b * HEADS;
    int r0 = q0 + w*16 + (lane >> 2);
    int col = h*HD + (lane & 3)*2;
    #pragma unroll
    for (int nb = 0; nb < 8; nb++) {
        size_t o0 = ((size_t)(b*NTOK + r0))     * DIM + col + nb*8;
        size_t o1 = ((size_t)(b*NTOK + r0 + 8)) * DIM + col + nb*8;
        *(__half2*)&g_o16[o0] = __floats2half2_rn(acc[nb][0]*inv0, acc[nb][1]*inv0);
        *(__half2*)&g_o16[o1] = __floats2half2_rn(acc[nb][2]*inv1, acc[nb][3]*inv1);
    }
}

// ==================== launcher ====================
extern "C" void kernel_launch(void* const* d_in, const int* in_sizes, int n_in,
                              void* d_out, int out_size)
{
    const float* x      = (const float*)d_in[0];
    const float* w_qkv  = (const float*)d_in[1];
    const float* b_qkv  = (const float*)d_in[2];
    const float* w_proj = (const float*)d_in[3];
    const float* b_proj = (const float*)d_in[4];
    float* out = (float*)d_out;

    void *xp, *wq, *wp, *op;
    cudaGetSymbolAddress(&xp, g_x16);
    cudaGetSymbolAddress(&wq, g_wq16);
    cudaGetSymbolAddress(&wp, g_wp16);
    cudaGetSymbolAddress(&op, g_o16);

    cudaFuncSetAttribute(gemm_mma<0>, cudaFuncAttributeMaxDynamicSharedMemorySize,
                         GEMM_SMEM_B);
    cudaFuncSetAttribute(gemm_mma<1>, cudaFuncAttributeMaxDynamicSharedMemorySize,
                         GEMM_SMEM_B);
    cudaFuncSetAttribute(attn_mma, cudaFuncAttributeMaxDynamicSharedMemorySize,
                         ATTN_SMEM);

    cvt16_kernel<<<(MROWS*DIM/4 + 255)/256, 256>>>(x, (__half*)xp, MROWS*DIM/4);
    cvt16_kernel<<<(3*DIM*DIM/4 + 255)/256, 256>>>(w_qkv, (__half*)wq, 3*DIM*DIM/4);
    cvt16_kernel<<<(DIM*DIM/4 + 255)/256, 256>>>(w_proj, (__half*)wp, DIM*DIM/4);
    rope_tab_kernel<<<(NTOK*32 + 255)/256, 256>>>();

    // 1) QKV GEMM + bias + RoPE + fp16 scatter
    gemm_mma<1><<<dim3(3*DIM/128, MROWS/128), 256, GEMM_SMEM_B>>>(
        (const __half*)xp, (const __half*)wq, b_qkv, nullptr, MROWS, 3*DIM, DIM);

    // 2) attention (HMMA flash, plain fp16 operands, fp32 accum)
    attn_mma<<<dim3(NTOK/128, BHC), 256, ATTN_SMEM>>>();

    // 3) output projection -> d_out
    gemm_mma<0><<<dim3(DIM/128, MROWS/128), 256, GEMM_SMEM_B>>>(
        (const __half*)op, (const __half*)wp, b_proj, out, MROWS, DIM, DIM);
}

// round 14
// speedup vs baseline: 3.1803x; 1.0288x over previous
#include <cuda_runtime.h>
#include <cuda_fp16.h>
#include <math.h>
#include <stdint.h>

#define DIM   768
#define HEADS 12
#define HD    64
#define B_    2
#define WW    48
#define NTOK  2304
#define BHC   24
#define MROWS 4608

// -------- scratch (device globals; no allocation allowed) --------
__device__ __half g_qh[BHC*NTOK*HD];          // Q: fp16 (pre-scaled)
__device__ __half g_kh[BHC*NTOK*HD];          // K: fp16
__device__ __half g_vh[BHC*NTOK*HD];          // V: fp16
__device__ __half g_x16[MROWS*DIM];           // x fp16
__device__ __half g_wq16[3*DIM*DIM];          // w_qkv fp16
__device__ __half g_wp16[DIM*DIM];            // w_proj fp16
__device__ __half g_o16[MROWS*DIM];           // O fp16
__device__ float g_sin[NTOK*32], g_cos[NTOK*32];

// ==================== helpers ====================
__device__ __forceinline__ uint32_t smem_u32(const void* p) {
    uint32_t a;
    asm("{ .reg .u64 t; cvta.to.shared.u64 t, %1; cvt.u32.u64 %0, t; }" : "=r"(a) : "l"(p));
    return a;
}
__device__ __forceinline__ void ldsm4(uint32_t* r, uint32_t addr) {
    asm volatile("ldmatrix.sync.aligned.m8n8.x4.shared.b16 {%0,%1,%2,%3}, [%4];"
                 : "=r"(r[0]), "=r"(r[1]), "=r"(r[2]), "=r"(r[3]) : "r"(addr));
}
__device__ __forceinline__ void ldsm4t(uint32_t* r, uint32_t addr) {
    asm volatile("ldmatrix.sync.aligned.m8n8.x4.trans.shared.b16 {%0,%1,%2,%3}, [%4];"
                 : "=r"(r[0]), "=r"(r[1]), "=r"(r[2]), "=r"(r[3]) : "r"(addr));
}
__device__ __forceinline__ void mma_fp(float* d, const uint32_t* a,
                                       uint32_t b0, uint32_t b1) {
    asm volatile(
        "mma.sync.aligned.m16n8k16.row.col.f32.f16.f16.f32 "
        "{%0,%1,%2,%3}, {%4,%5,%6,%7}, {%8,%9}, {%0,%1,%2,%3};"
        : "+f"(d[0]), "+f"(d[1]), "+f"(d[2]), "+f"(d[3])
        : "r"(a[0]), "r"(a[1]), "r"(a[2]), "r"(a[3]), "r"(b0), "r"(b1));
}
// fast e^x on FMA/ALU pipes (no MUFU). |rel err| ~1e-7, x clamped >= -80.
__device__ __forceinline__ float fast_exp(float x) {
    x = fmaxf(x, -80.0f);
    float y = fmaf(x, 1.4426950409f, 12582912.0f);
    float z = y - 12582912.0f;
    int   n = __float_as_int(y) - 0x4B400000;
    float f = fmaf(x, 1.4426950409f, -z);
    float p = 1.3333558e-3f;
    p = fmaf(p, f, 9.6181291e-3f);
    p = fmaf(p, f, 5.5504109e-2f);
    p = fmaf(p, f, 2.4022651e-1f);
    p = fmaf(p, f, 6.9314718e-1f);
    p = fmaf(p, f, 1.0f);
    return __int_as_float(__float_as_int(p) + (n << 23));
}

// ==================== prep kernels ====================
__global__ void __launch_bounds__(256) cvt16_kernel(
    const float* __restrict__ src, __half* __restrict__ dst, int n4)
{
    int i = blockIdx.x * 256 + threadIdx.x;
    if (i >= n4) return;
    float4 v = ((const float4*)src)[i];
    ((__half2*)dst)[2*i]   = __floats2half2_rn(v.x, v.y);
    ((__half2*)dst)[2*i+1] = __floats2half2_rn(v.z, v.w);
}

__global__ void __launch_bounds__(256) rope_tab_kernel()
{
    int idx = blockIdx.x * 256 + threadIdx.x;
    if (idx >= NTOK * 32) return;
    int n = idx >> 5, j = idx & 31;
    int axis = j >> 4, p = j & 15;
    int y = n / WW, x = n - y * WW;
    float idxf  = axis ? (float)x : (float)y;
    float coord = 2.0f * ((idxf + 0.5f) / 48.0f) - 1.0f;
    float invp  = exp2f(-(float)p * 0.41524101186092607f);  // 100^(-p/16)
    float sn, cs; sincosf(6.283185307179586f * coord * invp, &sn, &cs);
    g_sin[idx] = sn; g_cos[idx] = cs;
}

// ==================== mma.sync fp16 GEMM (plain fp16, fp32 accum) ======
#define TSTRIDE 40
#define TILE_B  (128*TSTRIDE*2)       // 10240 bytes per tile
#define STAGE_B (2*TILE_B)            // A | B
#define GEMM_SMEM_B (2*STAGE_B)       // 40960 bytes

__device__ __forceinline__ void g2r(uint4* r,
    const __half* A, const __half* B,
    int bm, int bn, int K, int k0, int tid)
{
    #pragma unroll
    for (int p = 0; p < 2; p++) {
        int id = p * 256 + tid;
        int row = id >> 2, kc = id & 3;
        r[0+p] = *(const uint4*)&A[(size_t)(bm + row) * K + k0 + kc * 8];
        r[2+p] = *(const uint4*)&B[(size_t)(bn + row) * K + k0 + kc * 8];
    }
}
__device__ __forceinline__ void r2s(__half* sm, const uint4* r, int tid, int st)
{
    #pragma unroll
    for (int p = 0; p < 2; p++) {
        int id = p * 256 + tid;
        int off = (id >> 2) * TSTRIDE + (id & 3) * 8;
        #pragma unroll
        for (int t = 0; t < 2; t++)
            *(uint4*)&sm[(st*2 + t) * (128*TSTRIDE) + off] = r[t*2 + p];
    }
}

template<int EPI>
__global__ void __launch_bounds__(256, 1) gemm_mma(
    const __half* __restrict__ A, const __half* __restrict__ Bm,
    const float* __restrict__ bias, float* __restrict__ C, int M, int N, int K)
{
    extern __shared__ __align__(16) __half sm[];
    const uint32_t sbase = smem_u32(sm);
    const int tid = threadIdx.x;
    const int lane = tid & 31, wid = tid >> 5;
    const int wm = wid & 3, wn = wid >> 2;
    const int bm = blockIdx.y * 128, bn = blockIdx.x * 128;
    const int piece = lane >> 3, pr = lane & 7;

    float acc[2][8][4];
    #pragma unroll
    for (int i = 0; i < 2; i++)
        #pragma unroll
        for (int j = 0; j < 8; j++)
            #pragma unroll
            for (int k = 0; k < 4; k++) acc[i][j][k] = 0.0f;

    const int nit = K >> 5;
    uint4 r[4];
    g2r(r, A, Bm, bm, bn, K, 0, tid);
    r2s(sm, r, tid, 0);
    __syncthreads();

    const int arow = wm*32 + (piece & 1)*8 + pr;
    const int brow = wn*64 + (piece & 1)*8 + pr;
    const int kofp = (piece >> 1) * 8;

    for (int it = 0; it < nit; it++) {
        int st = it & 1;
        bool more = (it + 1) < nit;
        if (more) g2r(r, A, Bm, bm, bn, K, (it + 1) << 5, tid);

        uint32_t tA = sbase + (uint32_t)(st*2) * TILE_B;
        #pragma unroll
        for (int ks = 0; ks < 2; ks++) {
            int koff = ks*16 + kofp;
            uint32_t ah[2][4];
            #pragma unroll
            for (int mt = 0; mt < 2; mt++)
                ldsm4(ah[mt], tA + ((arow + mt*16) * TSTRIDE + koff) * 2);
            #pragma unroll
            for (int np = 0; np < 4; np++) {
                uint32_t b4[4];
                ldsm4(b4, tA + TILE_B + ((brow + np*16) * TSTRIDE + koff) * 2);
                #pragma unroll
                for (int mt = 0; mt < 2; mt++) {
                    mma_fp(acc[mt][np*2],   ah[mt], b4[0], b4[2]);
                    mma_fp(acc[mt][np*2+1], ah[mt], b4[1], b4[3]);
                }
            }
        }
        // Single barrier per iteration (see R9 note).
        if (more) r2s(sm, r, tid, st ^ 1);
        __syncthreads();
    }

    const int cbase = bn + wn * 64;
    if (EPI == 0) {
        #pragma unroll
        for (int mt = 0; mt < 2; mt++)
            #pragma unroll
            for (int half = 0; half < 2; half++) {
                int m = bm + wm*32 + mt*16 + (lane >> 2) + half*8;
                #pragma unroll
                for (int nt = 0; nt < 8; nt++) {
                    int c = cbase + nt*8 + (lane & 3)*2;
                    float2 v;
                    v.x = acc[mt][nt][half*2+0] + bias[c];
                    v.y = acc[mt][nt][half*2+1] + bias[c+1];
                    *(float2*)&C[(size_t)m * N + c] = v;
                }
            }
    } else {
        // QKV epilogue: Q (+RoPE, prescale) / K (+RoPE) / V -> plain fp16.
        int which = cbase / DIM;
        int h = (cbase % DIM) >> 6;
        __half* dstp = (which == 0) ? g_qh : (which == 1) ? g_kh : g_vh;
        #pragma unroll
        for (int mt = 0; mt < 2; mt++)
            #pragma unroll
            for (int half = 0; half < 2; half++) {
                int m = bm + wm*32 + mt*16 + (lane >> 2) + half*8;
                int bb = m / NTOK, pos = m - bb * NTOK;
                size_t dof = ((size_t)(bb*HEADS + h) * NTOK + pos) * HD;
                __half* dst = dstp + dof;
                if (which < 2) {
                    const float qs = (which == 0) ? 0.125f : 1.0f;
                    #pragma unroll
                    for (int nt = 0; nt < 4; nt++) {
                        int d0 = nt*8 + (lane & 3)*2;
                        float rl[2], rh[2];
                        #pragma unroll
                        for (int j = 0; j < 2; j++) {
                            float vlo = acc[mt][nt][half*2+j]   + bias[cbase + d0 + j];
                            float vhi = acc[mt][nt+4][half*2+j] + bias[cbase + 32 + d0 + j];
                            float sn = g_sin[pos*32 + d0 + j];
                            float cs = g_cos[pos*32 + d0 + j];
                            rl[j] = (vlo*cs - vhi*sn) * qs;
                            rh[j] = (vhi*cs + vlo*sn) * qs;
                        }
                        *(__half2*)&dst[d0]      = __floats2half2_rn(rl[0], rl[1]);
                        *(__half2*)&dst[32 + d0] = __floats2half2_rn(rh[0], rh[1]);
                    }
                } else {
                    #pragma unroll
                    for (int nt = 0; nt < 8; nt++) {
                        int d = nt*8 + (lane & 3)*2;
                        float v0 = acc[mt][nt][half*2+0] + bias[cbase + d];
                        float v1 = acc[mt][nt][half*2+1] + bias[cbase + d + 1];
                        *(__half2*)&dst[d] = __floats2half2_rn(v0, v1);
                    }
                }
            }
    }
}

// ==================== attention: HMMA flash, 2-stage K/V double buffer ==
#define AST 72
#define STAGEH (2*64*AST)            // halves per stage (K tile + V tile)
#define ATTN_SMEM (2*STAGEH*2)       // 36864 bytes

__device__ __forceinline__ void g2r_attn(uint4* rv,
    const __half* Kh, const __half* Vh, int k0, int tid)
{
    #pragma unroll
    for (int i = 0; i < 4; i++) {
        int lin = i * 256 + tid;
        int arr = lin >> 9, rem = lin & 511;
        int row = rem >> 3, c = (rem & 7) * 8;
        const __half* src = (arr == 0 ? Kh : Vh) + (size_t)(k0 + row) * HD + c;
        rv[i] = *(const uint4*)src;
    }
}
__device__ __forceinline__ void r2s_attn(__half* smh, const uint4* rv,
                                         int st, int tid)
{
    __half* base = smh + st * STAGEH;
    #pragma unroll
    for (int i = 0; i < 4; i++) {
        int lin = i * 256 + tid;
        int arr = lin >> 9, rem = lin & 511;
        int row = rem >> 3, c = (rem & 7) * 8;
        *(uint4*)&base[arr * (64*AST) + row * AST + c] = rv[i];
    }
}

__global__ void __launch_bounds__(256, 2) attn_mma()
{
    extern __shared__ __align__(16) __half smh[];
    const uint32_t sb = smem_u32(smh);

    const int tid = threadIdx.x;
    const int lane = tid & 31, w = tid >> 5;
    const int l15 = lane & 15, l16 = lane >> 4;
    const int bh = blockIdx.y, q0 = blockIdx.x * 128;

    const __half* Qh = g_qh + ((size_t)bh * NTOK + q0) * HD;
    const __half* Kh = g_kh + (size_t)bh * NTOK * HD;
    const __half* Vh = g_vh + (size_t)bh * NTOK * HD;

    // ---- stage Q (in stage-0 region, 128*AST = STAGEH), extract frags ----
    #pragma unroll
    for (int t = 0; t < 4; t++) {
        int lin = t * 256 + tid;
        int row = lin >> 3, c = (lin & 7) * 8;
        *(uint4*)&smh[row * AST + c] = *(const uint4*)&Qh[(size_t)row * HD + c];
    }
    __syncthreads();
    uint32_t qf[4][4];
    {
        uint32_t qa = sb + (((w*16 + l15) * AST) + l16*8) * 2;
        #pragma unroll
        for (int ks = 0; ks < 4; ks++)
            ldsm4(qf[ks], qa + ks*32);
    }

    // ---- pipeline prologue: tile0 -> stage0, tile1 in registers ----
    uint4 rv[4];
    g2r_attn(rv, Kh, Vh, 0, tid);
    __syncthreads();                 // all qf extractions done before overwrite
    r2s_attn(smh, rv, 0, tid);
    g2r_attn(rv, Kh, Vh, 64, tid);   // prefetch tile 1
    __syncthreads();                 // stage0 visible

    float acc[8][4];
    #pragma unroll
    for (int i = 0; i < 8; i++)
        #pragma unroll
        for (int j = 0; j < 4; j++) acc[i][j] = 0.0f;
    float m0 = -1e30f, m1 = -1e30f, l0 = 0.0f, l1 = 0.0f;

    const uint32_t lko = (l15 * AST + l16*8) * 2;
    const int NT = NTOK / 64;        // 36

    for (int t = 0; t < NT; t++) {
        // store prefetched tile t+1 into the other stage; start loads of t+2
        if (t + 1 < NT) r2s_attn(smh, rv, (t + 1) & 1, tid);
        if (t + 2 < NT) g2r_attn(rv, Kh, Vh, (t + 2) * 64, tid);

        uint32_t stg = sb + (uint32_t)(t & 1) * (STAGEH * 2);
        uint32_t kbase = stg + lko;
        uint32_t vbase = stg + 64*AST*2 + lko;

        // ---- S = Q K^T ----
        float s[8][4];
        #pragma unroll
        for (int i = 0; i < 8; i++)
            #pragma unroll
            for (int j = 0; j < 4; j++) s[i][j] = 0.0f;
        #pragma unroll
        for (int ks = 0; ks < 4; ks++) {
            #pragma unroll
            for (int nbp = 0; nbp < 8; nbp += 2) {
                uint32_t kh4[4];
                ldsm4(kh4, kbase + (nbp*8*AST + ks*16) * 2);
                mma_fp(s[nbp],   qf[ks], kh4[0], kh4[2]);
                mma_fp(s[nbp+1], qf[ks], kh4[1], kh4[3]);
            }
        }

        // ---- online softmax ----
        float mx0 = -1e30f, mx1 = -1e30f;
        #pragma unroll
        for (int i = 0; i < 8; i++) {
            mx0 = fmaxf(mx0, fmaxf(s[i][0], s[i][1]));
            mx1 = fmaxf(mx1, fmaxf(s[i][2], s[i][3]));
        }
        mx0 = fmaxf(mx0, __shfl_xor_sync(0xffffffffu, mx0, 1));
        mx0 = fmaxf(mx0, __shfl_xor_sync(0xffffffffu, mx0, 2));
        mx1 = fmaxf(mx1, __shfl_xor_sync(0xffffffffu, mx1, 1));
        mx1 = fmaxf(mx1, __shfl_xor_sync(0xffffffffu, mx1, 2));
        float nm0 = fmaxf(m0, mx0), nm1 = fmaxf(m1, mx1);
        float f0 = fast_exp(m0 - nm0), f1 = fast_exp(m1 - nm1);
        m0 = nm0; m1 = nm1;
        float sum0 = 0.0f, sum1 = 0.0f;
        #pragma unroll
        for (int i = 0; i < 8; i++) {
            s[i][0] = fast_exp(s[i][0] - nm0); sum0 += s[i][0];
            s[i][1] = fast_exp(s[i][1] - nm0); sum0 += s[i][1];
            s[i][2] = fast_exp(s[i][2] - nm1); sum1 += s[i][2];
            s[i][3] = fast_exp(s[i][3] - nm1); sum1 += s[i][3];
        }
        sum0 += __shfl_xor_sync(0xffffffffu, sum0, 1);
        sum0 += __shfl_xor_sync(0xffffffffu, sum0, 2);
        sum1 += __shfl_xor_sync(0xffffffffu, sum1, 1);
        sum1 += __shfl_xor_sync(0xffffffffu, sum1, 2);
        l0 = l0 * f0 + sum0;
        l1 = l1 * f1 + sum1;
        #pragma unroll
        for (int i = 0; i < 8; i++) {
            acc[i][0] *= f0; acc[i][1] *= f0;
            acc[i][2] *= f1; acc[i][3] *= f1;
        }

        // ---- P -> fp16 A-fragments ----
        uint32_t ap[4][4];
        #pragma unroll
        for (int ks = 0; ks < 4; ks++) {
            int n0 = 2*ks, n1 = 2*ks + 1;
            __half2 h0 = __floats2half2_rn(s[n0][0], s[n0][1]);
            __half2 h1 = __floats2half2_rn(s[n0][2], s[n0][3]);
            __half2 h2 = __floats2half2_rn(s[n1][0], s[n1][1]);
            __half2 h3 = __floats2half2_rn(s[n1][2], s[n1][3]);
            ap[ks][0] = *(uint32_t*)&h0;
            ap[ks][1] = *(uint32_t*)&h1;
            ap[ks][2] = *(uint32_t*)&h2;
            ap[ks][3] = *(uint32_t*)&h3;
        }

        // ---- O += P V ----
        #pragma unroll
        for (int ks = 0; ks < 4; ks++) {
            #pragma unroll
            for (int nbp = 0; nbp < 8; nbp += 2) {
                uint32_t vh4[4];
                ldsm4t(vh4, vbase + (ks*16*AST + nbp*8) * 2);
                mma_fp(acc[nbp],   ap[ks], vh4[0], vh4[1]);
                mma_fp(acc[nbp+1], ap[ks], vh4[2], vh4[3]);
            }
        }

        // Single barrier per iteration: fences this iteration's stores to
        // stage[(t+1)&1] (written above) against next iteration's readers,
        // and this iteration's readers of stage[t&1] against the store into
        // it two iterations from now.
        __syncthreads();
    }

    // ---- normalize + write O as fp16, [b, n, h*64 + d] ----
    float inv0 = 1.0f / l0, inv1 = 1.0f / l1;
    int b = bh / HEADS, h = bh - b * HEADS;
    int r0 = q0 + w*16 + (lane >> 2);
    int col = h*HD + (lane & 3)*2;
    #pragma unroll
    for (int nb = 0; nb < 8; nb++) {
        size_t o0 = ((size_t)(b*NTOK + r0))     * DIM + col + nb*8;
        size_t o1 = ((size_t)(b*NTOK + r0 + 8)) * DIM + col + nb*8;
        *(__half2*)&g_o16[o0] = __floats2half2_rn(acc[nb][0]*inv0, acc[nb][1]*inv0);
        *(__half2*)&g_o16[o1] = __floats2half2_rn(acc[nb][2]*inv1, acc[nb][3]*inv1);
    }
}

// ==================== launcher ====================
extern "C" void kernel_launch(void* const* d_in, const int* in_sizes, int n_in,
                              void* d_out, int out_size)
{
    const float* x      = (const float*)d_in[0];
    const float* w_qkv  = (const float*)d_in[1];
    const float* b_qkv  = (const float*)d_in[2];
    const float* w_proj = (const float*)d_in[3];
    const float* b_proj = (const float*)d_in[4];
    float* out = (float*)d_out;

    void *xp, *wq, *wp, *op;
    cudaGetSymbolAddress(&xp, g_x16);
    cudaGetSymbolAddress(&wq, g_wq16);
    cudaGetSymbolAddress(&wp, g_wp16);
    cudaGetSymbolAddress(&op, g_o16);

    cudaFuncSetAttribute(gemm_mma<0>, cudaFuncAttributeMaxDynamicSharedMemorySize,
                         GEMM_SMEM_B);
    cudaFuncSetAttribute(gemm_mma<1>, cudaFuncAttributeMaxDynamicSharedMemorySize,
                         GEMM_SMEM_B);
    cudaFuncSetAttribute(attn_mma, cudaFuncAttributeMaxDynamicSharedMemorySize,
                         ATTN_SMEM);

    cvt16_kernel<<<(MROWS*DIM/4 + 255)/256, 256>>>(x, (__half*)xp, MROWS*DIM/4);
    cvt16_kernel<<<(3*DIM*DIM/4 + 255)/256, 256>>>(w_qkv, (__half*)wq, 3*DIM*DIM/4);
    cvt16_kernel<<<(DIM*DIM/4 + 255)/256, 256>>>(w_proj, (__half*)wp, DIM*DIM/4);
    rope_tab_kernel<<<(NTOK*32 + 255)/256, 256>>>();

    // 1) QKV GEMM + bias + RoPE + fp16 scatter
    gemm_mma<1><<<dim3(3*DIM/128, MROWS/128), 256, GEMM_SMEM_B>>>(
        (const __half*)xp, (const __half*)wq, b_qkv, nullptr, MROWS, 3*DIM, DIM);

    // 2) attention (HMMA flash, fp16 operands, 2-stage K/V pipeline)
    attn_mma<<<dim3(NTOK/128, BHC), 256, ATTN_SMEM>>>();

    // 3) output projection -> d_out
    gemm_mma<0><<<dim3(DIM/128, MROWS/128), 256, GEMM_SMEM_B>>>(
        (const __half*)op, (const __half*)wp, b_proj, out, MROWS, DIM, DIM);
}

// round 15
// speedup vs baseline: 3.2917x; 1.0350x over previous
#include <cuda_runtime.h>
#include <cuda_fp16.h>
#include <math.h>
#include <stdint.h>

#define DIM   768
#define HEADS 12
#define HD    64
#define B_    2
#define WW    48
#define NTOK  2304
#define BHC   24
#define MROWS 4608

// -------- scratch (device globals; no allocation allowed) --------
__device__ __half g_qh[BHC*NTOK*HD];          // Q: fp16 (pre-scaled)
__device__ __half g_kh[BHC*NTOK*HD];          // K: fp16
__device__ __half g_vh[BHC*NTOK*HD];          // V: fp16
__device__ __half g_x16[MROWS*DIM];           // x fp16
__device__ __half g_wq16[3*DIM*DIM];          // w_qkv fp16
__device__ __half g_wp16[DIM*DIM];            // w_proj fp16
__device__ __half g_o16[MROWS*DIM];           // O fp16
__device__ float g_sin[NTOK*32], g_cos[NTOK*32];

// ==================== helpers ====================
__device__ __forceinline__ uint32_t smem_u32(const void* p) {
    uint32_t a;
    asm("{ .reg .u64 t; cvta.to.shared.u64 t, %1; cvt.u32.u64 %0, t; }" : "=r"(a) : "l"(p));
    return a;
}
__device__ __forceinline__ void ldsm4(uint32_t* r, uint32_t addr) {
    asm volatile("ldmatrix.sync.aligned.m8n8.x4.shared.b16 {%0,%1,%2,%3}, [%4];"
                 : "=r"(r[0]), "=r"(r[1]), "=r"(r[2]), "=r"(r[3]) : "r"(addr));
}
__device__ __forceinline__ void ldsm4t(uint32_t* r, uint32_t addr) {
    asm volatile("ldmatrix.sync.aligned.m8n8.x4.trans.shared.b16 {%0,%1,%2,%3}, [%4];"
                 : "=r"(r[0]), "=r"(r[1]), "=r"(r[2]), "=r"(r[3]) : "r"(addr));
}
__device__ __forceinline__ void mma_fp(float* d, const uint32_t* a,
                                       uint32_t b0, uint32_t b1) {
    asm volatile(
        "mma.sync.aligned.m16n8k16.row.col.f32.f16.f16.f32 "
        "{%0,%1,%2,%3}, {%4,%5,%6,%7}, {%8,%9}, {%0,%1,%2,%3};"
        : "+f"(d[0]), "+f"(d[1]), "+f"(d[2]), "+f"(d[3])
        : "r"(a[0]), "r"(a[1]), "r"(a[2]), "r"(a[3]), "r"(b0), "r"(b1));
}
// fast e^x on FMA/ALU pipes (no MUFU). |rel err| ~1e-7, x clamped >= -80.
__device__ __forceinline__ float fast_exp(float x) {
    x = fmaxf(x, -80.0f);
    float y = fmaf(x, 1.4426950409f, 12582912.0f);
    float z = y - 12582912.0f;
    int   n = __float_as_int(y) - 0x4B400000;
    float f = fmaf(x, 1.4426950409f, -z);
    float p = 1.3333558e-3f;
    p = fmaf(p, f, 9.6181291e-3f);
    p = fmaf(p, f, 5.5504109e-2f);
    p = fmaf(p, f, 2.4022651e-1f);
    p = fmaf(p, f, 6.9314718e-1f);
    p = fmaf(p, f, 1.0f);
    return __int_as_float(__float_as_int(p) + (n << 23));
}

// ==================== fused prep kernel (converts + rope table) =========
#define N4_X  (MROWS*DIM/4)
#define N4_WQ (3*DIM*DIM/4)
#define N4_WP (DIM*DIM/4)
#define N_ROPE (NTOK*32)
#define PREP_TOTAL (N4_X + N4_WQ + N4_WP + N_ROPE)

__global__ void __launch_bounds__(256) prep_kernel(
    const float* __restrict__ x, const float* __restrict__ wq,
    const float* __restrict__ wp)
{
    int idx = blockIdx.x * 256 + threadIdx.x;
    if (idx < N4_X + N4_WQ + N4_WP) {
        const float* src;
        __half* dst;
        int i;
        if (idx < N4_X)                { src = x;  dst = g_x16;  i = idx; }
        else if (idx < N4_X + N4_WQ)   { src = wq; dst = g_wq16; i = idx - N4_X; }
        else                           { src = wp; dst = g_wp16; i = idx - N4_X - N4_WQ; }
        float4 v = ((const float4*)src)[i];
        ((__half2*)dst)[2*i]   = __floats2half2_rn(v.x, v.y);
        ((__half2*)dst)[2*i+1] = __floats2half2_rn(v.z, v.w);
        return;
    }
    int r = idx - (N4_X + N4_WQ + N4_WP);
    if (r >= N_ROPE) return;
    int n = r >> 5, j = r & 31;
    int axis = j >> 4, p = j & 15;
    int y = n / WW, xx = n - y * WW;
    float idxf  = axis ? (float)xx : (float)y;
    float coord = 2.0f * ((idxf + 0.5f) / 48.0f) - 1.0f;
    float invp  = exp2f(-(float)p * 0.41524101186092607f);  // 100^(-p/16)
    float sn, cs; sincosf(6.283185307179586f * coord * invp, &sn, &cs);
    g_sin[r] = sn; g_cos[r] = cs;
}

// ==================== mma.sync fp16 GEMM (plain fp16, fp32 accum) ======
#define TSTRIDE 40
#define TILE_B  (128*TSTRIDE*2)       // 10240 bytes per tile
#define STAGE_B (2*TILE_B)            // A | B
#define GEMM_SMEM_B (2*STAGE_B)       // 40960 bytes

__device__ __forceinline__ void g2r(uint4* r,
    const __half* A, const __half* B,
    int bm, int bn, int K, int k0, int tid)
{
    #pragma unroll
    for (int p = 0; p < 2; p++) {
        int id = p * 256 + tid;
        int row = id >> 2, kc = id & 3;
        r[0+p] = *(const uint4*)&A[(size_t)(bm + row) * K + k0 + kc * 8];
        r[2+p] = *(const uint4*)&B[(size_t)(bn + row) * K + k0 + kc * 8];
    }
}
__device__ __forceinline__ void r2s(__half* sm, const uint4* r, int tid, int st)
{
    #pragma unroll
    for (int p = 0; p < 2; p++) {
        int id = p * 256 + tid;
        int off = (id >> 2) * TSTRIDE + (id & 3) * 8;
        #pragma unroll
        for (int t = 0; t < 2; t++)
            *(uint4*)&sm[(st*2 + t) * (128*TSTRIDE) + off] = r[t*2 + p];
    }
}

template<int EPI>
__global__ void __launch_bounds__(256, 2) gemm_mma(
    const __half* __restrict__ A, const __half* __restrict__ Bm,
    const float* __restrict__ bias, float* __restrict__ C, int M, int N, int K)
{
    extern __shared__ __align__(16) __half sm[];
    const uint32_t sbase = smem_u32(sm);
    const int tid = threadIdx.x;
    const int lane = tid & 31, wid = tid >> 5;
    const int wm = wid & 3, wn = wid >> 2;
    const int bm = blockIdx.y * 128, bn = blockIdx.x * 128;
    const int piece = lane >> 3, pr = lane & 7;

    float acc[2][8][4];
    #pragma unroll
    for (int i = 0; i < 2; i++)
        #pragma unroll
        for (int j = 0; j < 8; j++)
            #pragma unroll
            for (int k = 0; k < 4; k++) acc[i][j][k] = 0.0f;

    const int nit = K >> 5;
    uint4 r[4];
    g2r(r, A, Bm, bm, bn, K, 0, tid);
    r2s(sm, r, tid, 0);
    __syncthreads();

    const int arow = wm*32 + (piece & 1)*8 + pr;
    const int brow = wn*64 + (piece & 1)*8 + pr;
    const int kofp = (piece >> 1) * 8;

    for (int it = 0; it < nit; it++) {
        int st = it & 1;
        bool more = (it + 1) < nit;
        if (more) g2r(r, A, Bm, bm, bn, K, (it + 1) << 5, tid);

        uint32_t tA = sbase + (uint32_t)(st*2) * TILE_B;
        #pragma unroll
        for (int ks = 0; ks < 2; ks++) {
            int koff = ks*16 + kofp;
            uint32_t ah[2][4];
            #pragma unroll
            for (int mt = 0; mt < 2; mt++)
                ldsm4(ah[mt], tA + ((arow + mt*16) * TSTRIDE + koff) * 2);
            #pragma unroll
            for (int np = 0; np < 4; np++) {
                uint32_t b4[4];
                ldsm4(b4, tA + TILE_B + ((brow + np*16) * TSTRIDE + koff) * 2);
                #pragma unroll
                for (int mt = 0; mt < 2; mt++) {
                    mma_fp(acc[mt][np*2],   ah[mt], b4[0], b4[2]);
                    mma_fp(acc[mt][np*2+1], ah[mt], b4[1], b4[3]);
                }
            }
        }
        // Single barrier per iteration (see R9 note).
        if (more) r2s(sm, r, tid, st ^ 1);
        __syncthreads();
    }

    const int cbase = bn + wn * 64;
    if (EPI == 0) {
        #pragma unroll
        for (int mt = 0; mt < 2; mt++)
            #pragma unroll
            for (int half = 0; half < 2; half++) {
                int m = bm + wm*32 + mt*16 + (lane >> 2) + half*8;
                #pragma unroll
                for (int nt = 0; nt < 8; nt++) {
                    int c = cbase + nt*8 + (lane & 3)*2;
                    float2 v;
                    v.x = acc[mt][nt][half*2+0] + bias[c];
                    v.y = acc[mt][nt][half*2+1] + bias[c+1];
                    *(float2*)&C[(size_t)m * N + c] = v;
                }
            }
    } else {
        // QKV epilogue: Q (+RoPE, prescale) / K (+RoPE) / V -> plain fp16.
        int which = cbase / DIM;
        int h = (cbase % DIM) >> 6;
        __half* dstp = (which == 0) ? g_qh : (which == 1) ? g_kh : g_vh;
        #pragma unroll
        for (int mt = 0; mt < 2; mt++)
            #pragma unroll
            for (int half = 0; half < 2; half++) {
                int m = bm + wm*32 + mt*16 + (lane >> 2) + half*8;
                int bb = m / NTOK, pos = m - bb * NTOK;
                size_t dof = ((size_t)(bb*HEADS + h) * NTOK + pos) * HD;
                __half* dst = dstp + dof;
                if (which < 2) {
                    const float qs = (which == 0) ? 0.125f : 1.0f;
                    #pragma unroll
                    for (int nt = 0; nt < 4; nt++) {
                        int d0 = nt*8 + (lane & 3)*2;
                        float rl[2], rh[2];
                        #pragma unroll
                        for (int j = 0; j < 2; j++) {
                            float vlo = acc[mt][nt][half*2+j]   + bias[cbase + d0 + j];
                            float vhi = acc[mt][nt+4][half*2+j] + bias[cbase + 32 + d0 + j];
                            float sn = g_sin[pos*32 + d0 + j];
                            float cs = g_cos[pos*32 + d0 + j];
                            rl[j] = (vlo*cs - vhi*sn) * qs;
                            rh[j] = (vhi*cs + vlo*sn) * qs;
                        }
                        *(__half2*)&dst[d0]      = __floats2half2_rn(rl[0], rl[1]);
                        *(__half2*)&dst[32 + d0] = __floats2half2_rn(rh[0], rh[1]);
                    }
                } else {
                    #pragma unroll
                    for (int nt = 0; nt < 8; nt++) {
                        int d = nt*8 + (lane & 3)*2;
                        float v0 = acc[mt][nt][half*2+0] + bias[cbase + d];
                        float v1 = acc[mt][nt][half*2+1] + bias[cbase + d + 1];
                        *(__half2*)&dst[d] = __floats2half2_rn(v0, v1);
                    }
                }
            }
    }
}

// ==================== attention: HMMA flash, 2-stage K/V double buffer ==
#define AST 72
#define STAGEH (2*64*AST)            // halves per stage (K tile + V tile)
#define ATTN_SMEM (2*STAGEH*2)       // 36864 bytes

__device__ __forceinline__ void g2r_attn(uint4* rv,
    const __half* Kh, const __half* Vh, int k0, int tid)
{
    #pragma unroll
    for (int i = 0; i < 4; i++) {
        int lin = i * 256 + tid;
        int arr = lin >> 9, rem = lin & 511;
        int row = rem >> 3, c = (rem & 7) * 8;
        const __half* src = (arr == 0 ? Kh : Vh) + (size_t)(k0 + row) * HD + c;
        rv[i] = *(const uint4*)src;
    }
}
__device__ __forceinline__ void r2s_attn(__half* smh, const uint4* rv,
                                         int st, int tid)
{
    __half* base = smh + st * STAGEH;
    #pragma unroll
    for (int i = 0; i < 4; i++) {
        int lin = i * 256 + tid;
        int arr = lin >> 9, rem = lin & 511;
        int row = rem >> 3, c = (rem & 7) * 8;
        *(uint4*)&base[arr * (64*AST) + row * AST + c] = rv[i];
    }
}

__global__ void __launch_bounds__(256, 2) attn_mma()
{
    extern __shared__ __align__(16) __half smh[];
    const uint32_t sb = smem_u32(smh);

    const int tid = threadIdx.x;
    const int lane = tid & 31, w = tid >> 5;
    const int l15 = lane & 15, l16 = lane >> 4;
    const int bh = blockIdx.y, q0 = blockIdx.x * 128;

    const __half* Qh = g_qh + ((size_t)bh * NTOK + q0) * HD;
    const __half* Kh = g_kh + (size_t)bh * NTOK * HD;
    const __half* Vh = g_vh + (size_t)bh * NTOK * HD;

    // ---- stage Q (stage-0 region), extract A-fragments ----
    #pragma unroll
    for (int t = 0; t < 4; t++) {
        int lin = t * 256 + tid;
        int row = lin >> 3, c = (lin & 7) * 8;
        *(uint4*)&smh[row * AST + c] = *(const uint4*)&Qh[(size_t)row * HD + c];
    }
    __syncthreads();
    uint32_t qf[4][4];
    {
        uint32_t qa = sb + (((w*16 + l15) * AST) + l16*8) * 2;
        #pragma unroll
        for (int ks = 0; ks < 4; ks++)
            ldsm4(qf[ks], qa + ks*32);
    }

    // ---- pipeline prologue: tile0 -> stage0, tile1 in registers ----
    uint4 rv[4];
    g2r_attn(rv, Kh, Vh, 0, tid);
    __syncthreads();                 // all qf extractions done before overwrite
    r2s_attn(smh, rv, 0, tid);
    g2r_attn(rv, Kh, Vh, 64, tid);   // prefetch tile 1
    __syncthreads();                 // stage0 visible

    float acc[8][4];
    #pragma unroll
    for (int i = 0; i < 8; i++)
        #pragma unroll
        for (int j = 0; j < 4; j++) acc[i][j] = 0.0f;
    float m0 = -1e30f, m1 = -1e30f, l0 = 0.0f, l1 = 0.0f;

    const uint32_t lko = (l15 * AST + l16*8) * 2;
    const int NT = NTOK / 64;        // 36

    for (int t = 0; t < NT; t++) {
        if (t + 1 < NT) r2s_attn(smh, rv, (t + 1) & 1, tid);
        if (t + 2 < NT) g2r_attn(rv, Kh, Vh, (t + 2) * 64, tid);

        uint32_t stg = sb + (uint32_t)(t & 1) * (STAGEH * 2);
        uint32_t kbase = stg + lko;
        uint32_t vbase = stg + 64*AST*2 + lko;

        // ---- S = Q K^T ----
        float s[8][4];
        #pragma unroll
        for (int i = 0; i < 8; i++)
            #pragma unroll
            for (int j = 0; j < 4; j++) s[i][j] = 0.0f;
        #pragma unroll
        for (int ks = 0; ks < 4; ks++) {
            #pragma unroll
            for (int nbp = 0; nbp < 8; nbp += 2) {
                uint32_t kh4[4];
                ldsm4(kh4, kbase + (nbp*8*AST + ks*16) * 2);
                mma_fp(s[nbp],   qf[ks], kh4[0], kh4[2]);
                mma_fp(s[nbp+1], qf[ks], kh4[1], kh4[3]);
            }
        }

        // ---- online softmax ----
        float mx0 = -1e30f, mx1 = -1e30f;
        #pragma unroll
        for (int i = 0; i < 8; i++) {
            mx0 = fmaxf(mx0, fmaxf(s[i][0], s[i][1]));
            mx1 = fmaxf(mx1, fmaxf(s[i][2], s[i][3]));
        }
        mx0 = fmaxf(mx0, __shfl_xor_sync(0xffffffffu, mx0, 1));
        mx0 = fmaxf(mx0, __shfl_xor_sync(0xffffffffu, mx0, 2));
        mx1 = fmaxf(mx1, __shfl_xor_sync(0xffffffffu, mx1, 1));
        mx1 = fmaxf(mx1, __shfl_xor_sync(0xffffffffu, mx1, 2));
        float nm0 = fmaxf(m0, mx0), nm1 = fmaxf(m1, mx1);
        float f0 = fast_exp(m0 - nm0), f1 = fast_exp(m1 - nm1);
        m0 = nm0; m1 = nm1;
        float sum0 = 0.0f, sum1 = 0.0f;
        #pragma unroll
        for (int i = 0; i < 8; i++) {
            s[i][0] = fast_exp(s[i][0] - nm0); sum0 += s[i][0];
            s[i][1] = fast_exp(s[i][1] - nm0); sum0 += s[i][1];
            s[i][2] = fast_exp(s[i][2] - nm1); sum1 += s[i][2];
            s[i][3] = fast_exp(s[i][3] - nm1); sum1 += s[i][3];
        }
        sum0 += __shfl_xor_sync(0xffffffffu, sum0, 1);
        sum0 += __shfl_xor_sync(0xffffffffu, sum0, 2);
        sum1 += __shfl_xor_sync(0xffffffffu, sum1, 1);
        sum1 += __shfl_xor_sync(0xffffffffu, sum1, 2);
        l0 = l0 * f0 + sum0;
        l1 = l1 * f1 + sum1;
        #pragma unroll
        for (int i = 0; i < 8; i++) {
            acc[i][0] *= f0; acc[i][1] *= f0;
            acc[i][2] *= f1; acc[i][3] *= f1;
        }

        // ---- P -> fp16 A-fragments ----
        uint32_t ap[4][4];
        #pragma unroll
        for (int ks = 0; ks < 4; ks++) {
            int n0 = 2*ks, n1 = 2*ks + 1;
            __half2 h0 = __floats2half2_rn(s[n0][0], s[n0][1]);
            __half2 h1 = __floats2half2_rn(s[n0][2], s[n0][3]);
            __half2 h2 = __floats2half2_rn(s[n1][0], s[n1][1]);
            __half2 h3 = __floats2half2_rn(s[n1][2], s[n1][3]);
            ap[ks][0] = *(uint32_t*)&h0;
            ap[ks][1] = *(uint32_t*)&h1;
            ap[ks][2] = *(uint32_t*)&h2;
            ap[ks][3] = *(uint32_t*)&h3;
        }

        // ---- O += P V ----
        #pragma unroll
        for (int ks = 0; ks < 4; ks++) {
            #pragma unroll
            for (int nbp = 0; nbp < 8; nbp += 2) {
                uint32_t vh4[4];
                ldsm4t(vh4, vbase + (ks*16*AST + nbp*8) * 2);
                mma_fp(acc[nbp],   ap[ks], vh4[0], vh4[1]);
                mma_fp(acc[nbp+1], ap[ks], vh4[2], vh4[3]);
            }
        }

        __syncthreads();  // single barrier per iteration (see R14 note)
    }

    // ---- normalize + write O as fp16, [b, n, h*64 + d] ----
    float inv0 = 1.0f / l0, inv1 = 1.0f / l1;
    int b = bh / HEADS, h = bh - b * HEADS;
    int r0 = q0 + w*16 + (lane >> 2);
    int col = h*HD + (lane & 3)*2;
    #pragma unroll
    for (int nb = 0; nb < 8; nb++) {
        size_t o0 = ((size_t)(b*NTOK + r0))     * DIM + col + nb*8;
        size_t o1 = ((size_t)(b*NTOK + r0 + 8)) * DIM + col + nb*8;
        *(__half2*)&g_o16[o0] = __floats2half2_rn(acc[nb][0]*inv0, acc[nb][1]*inv0);
        *(__half2*)&g_o16[o1] = __floats2half2_rn(acc[nb][2]*inv1, acc[nb][3]*inv1);
    }
}

// ==================== launcher ====================
extern "C" void kernel_launch(void* const* d_in, const int* in_sizes, int n_in,
                              void* d_out, int out_size)
{
    const float* x      = (const float*)d_in[0];
    const float* w_qkv  = (const float*)d_in[1];
    const float* b_qkv  = (const float*)d_in[2];
    const float* w_proj = (const float*)d_in[3];
    const float* b_proj = (const float*)d_in[4];
    float* out = (float*)d_out;

    void *xp, *wq, *wp, *op;
    cudaGetSymbolAddress(&xp, g_x16);
    cudaGetSymbolAddress(&wq, g_wq16);
    cudaGetSymbolAddress(&wp, g_wp16);
    cudaGetSymbolAddress(&op, g_o16);

    cudaFuncSetAttribute(gemm_mma<0>, cudaFuncAttributeMaxDynamicSharedMemorySize,
                         GEMM_SMEM_B);
    cudaFuncSetAttribute(gemm_mma<1>, cudaFuncAttributeMaxDynamicSharedMemorySize,
                         GEMM_SMEM_B);
    cudaFuncSetAttribute(attn_mma, cudaFuncAttributeMaxDynamicSharedMemorySize,
                         ATTN_SMEM);

    // 0) fused prep: x/w_qkv/w_proj fp32->fp16 + rope table (one launch)
    prep_kernel<<<(PREP_TOTAL + 255)/256, 256>>>(x, w_qkv, w_proj);

    // 1) QKV GEMM + bias + RoPE + fp16 scatter
    gemm_mma<1><<<dim3(3*DIM/128, MROWS/128), 256, GEMM_SMEM_B>>>(
        (const __half*)xp, (const __half*)wq, b_qkv, nullptr, MROWS, 3*DIM, DIM);

    // 2) attention (HMMA flash, fp16 operands, 2-stage K/V pipeline)
    attn_mma<<<dim3(NTOK/128, BHC), 256, ATTN_SMEM>>>();

    // 3) output projection -> d_out
    gemm_mma<0><<<dim3(DIM/128, MROWS/128), 256, GEMM_SMEM_B>>>(
        (const __half*)op, (const __half*)wp, b_proj, out, MROWS, DIM, DIM);
}

// round 16
// speedup vs baseline: 3.7112x; 1.1274x over previous
#include <cuda_runtime.h>
#include <cuda_fp16.h>
#include <math.h>
#include <stdint.h>

#define DIM   768
#define HEADS 12
#define HD    64
#define B_    2
#define WW    48
#define NTOK  2304
#define BHC   24
#define MROWS 4608

// -------- scratch (device globals; no allocation allowed) --------
__device__ __half g_qh[BHC*NTOK*HD];          // Q: fp16 (pre-scaled)
__device__ __half g_kh[BHC*NTOK*HD];          // K: fp16
__device__ __half g_vh[BHC*NTOK*HD];          // V: fp16
__device__ __half g_x16[MROWS*DIM];           // x fp16
__device__ __half g_wq16[3*DIM*DIM];          // w_qkv fp16
__device__ __half g_wp16[DIM*DIM];            // w_proj fp16
__device__ __half g_o16[MROWS*DIM];           // O fp16
__device__ float g_sin[NTOK*32], g_cos[NTOK*32];

// ==================== helpers ====================
__device__ __forceinline__ uint32_t smem_u32(const void* p) {
    uint32_t a;
    asm("{ .reg .u64 t; cvta.to.shared.u64 t, %1; cvt.u32.u64 %0, t; }" : "=r"(a) : "l"(p));
    return a;
}
__device__ __forceinline__ void ldsm4(uint32_t* r, uint32_t addr) {
    asm volatile("ldmatrix.sync.aligned.m8n8.x4.shared.b16 {%0,%1,%2,%3}, [%4];"
                 : "=r"(r[0]), "=r"(r[1]), "=r"(r[2]), "=r"(r[3]) : "r"(addr));
}
__device__ __forceinline__ void ldsm4t(uint32_t* r, uint32_t addr) {
    asm volatile("ldmatrix.sync.aligned.m8n8.x4.trans.shared.b16 {%0,%1,%2,%3}, [%4];"
                 : "=r"(r[0]), "=r"(r[1]), "=r"(r[2]), "=r"(r[3]) : "r"(addr));
}
__device__ __forceinline__ void mma_fp(float* d, const uint32_t* a,
                                       uint32_t b0, uint32_t b1) {
    asm volatile(
        "mma.sync.aligned.m16n8k16.row.col.f32.f16.f16.f32 "
        "{%0,%1,%2,%3}, {%4,%5,%6,%7}, {%8,%9}, {%0,%1,%2,%3};"
        : "+f"(d[0]), "+f"(d[1]), "+f"(d[2]), "+f"(d[3])
        : "r"(a[0]), "r"(a[1]), "r"(a[2]), "r"(a[3]), "r"(b0), "r"(b1));
}
// e^x via MUFU (ex2.approx): 1 FMA + 1 MUFU op, runs on the otherwise-idle
// MUFU pipe instead of ~10 FMA-pipe ops. Underflows cleanly (x=-1e30 -> 0).
__device__ __forceinline__ float fast_exp(float x) {
    float r;
    asm("ex2.approx.f32 %0, %1;" : "=f"(r) : "f"(x * 1.4426950409f));
    return r;
}

// ==================== fused prep kernel (converts + rope table) =========
#define N4_X  (MROWS*DIM/4)
#define N4_WQ (3*DIM*DIM/4)
#define N4_WP (DIM*DIM/4)
#define N_ROPE (NTOK*32)
#define PREP_TOTAL (N4_X + N4_WQ + N4_WP + N_ROPE)

__global__ void __launch_bounds__(256) prep_kernel(
    const float* __restrict__ x, const float* __restrict__ wq,
    const float* __restrict__ wp)
{
    int idx = blockIdx.x * 256 + threadIdx.x;
    if (idx < N4_X + N4_WQ + N4_WP) {
        const float* src;
        __half* dst;
        int i;
        if (idx < N4_X)                { src = x;  dst = g_x16;  i = idx; }
        else if (idx < N4_X + N4_WQ)   { src = wq; dst = g_wq16; i = idx - N4_X; }
        else                           { src = wp; dst = g_wp16; i = idx - N4_X - N4_WQ; }
        float4 v = ((const float4*)src)[i];
        ((__half2*)dst)[2*i]   = __floats2half2_rn(v.x, v.y);
        ((__half2*)dst)[2*i+1] = __floats2half2_rn(v.z, v.w);
        return;
    }
    int r = idx - (N4_X + N4_WQ + N4_WP);
    if (r >= N_ROPE) return;
    int n = r >> 5, j = r & 31;
    int axis = j >> 4, p = j & 15;
    int y = n / WW, xx = n - y * WW;
    float idxf  = axis ? (float)xx : (float)y;
    float coord = 2.0f * ((idxf + 0.5f) / 48.0f) - 1.0f;
    float invp  = exp2f(-(float)p * 0.41524101186092607f);  // 100^(-p/16)
    float sn, cs; sincosf(6.283185307179586f * coord * invp, &sn, &cs);
    g_sin[r] = sn; g_cos[r] = cs;
}

// ==================== mma.sync fp16 GEMM (plain fp16, fp32 accum) ======
#define TSTRIDE 40
#define TILE_B  (128*TSTRIDE*2)       // 10240 bytes per tile
#define STAGE_B (2*TILE_B)            // A | B
#define GEMM_SMEM_B (2*STAGE_B)       // 40960 bytes

__device__ __forceinline__ void g2r(uint4* r,
    const __half* A, const __half* B,
    int bm, int bn, int K, int k0, int tid)
{
    #pragma unroll
    for (int p = 0; p < 2; p++) {
        int id = p * 256 + tid;
        int row = id >> 2, kc = id & 3;
        r[0+p] = *(const uint4*)&A[(size_t)(bm + row) * K + k0 + kc * 8];
        r[2+p] = *(const uint4*)&B[(size_t)(bn + row) * K + k0 + kc * 8];
    }
}
__device__ __forceinline__ void r2s(__half* sm, const uint4* r, int tid, int st)
{
    #pragma unroll
    for (int p = 0; p < 2; p++) {
        int id = p * 256 + tid;
        int off = (id >> 2) * TSTRIDE + (id & 3) * 8;
        #pragma unroll
        for (int t = 0; t < 2; t++)
            *(uint4*)&sm[(st*2 + t) * (128*TSTRIDE) + off] = r[t*2 + p];
    }
}

template<int EPI>
__global__ void __launch_bounds__(256, 2) gemm_mma(
    const __half* __restrict__ A, const __half* __restrict__ Bm,
    const float* __restrict__ bias, float* __restrict__ C, int M, int N, int K)
{
    extern __shared__ __align__(16) __half sm[];
    const uint32_t sbase = smem_u32(sm);
    const int tid = threadIdx.x;
    const int lane = tid & 31, wid = tid >> 5;
    const int wm = wid & 3, wn = wid >> 2;
    const int bm = blockIdx.y * 128, bn = blockIdx.x * 128;
    const int piece = lane >> 3, pr = lane & 7;

    float acc[2][8][4];
    #pragma unroll
    for (int i = 0; i < 2; i++)
        #pragma unroll
        for (int j = 0; j < 8; j++)
            #pragma unroll
            for (int k = 0; k < 4; k++) acc[i][j][k] = 0.0f;

    const int nit = K >> 5;
    uint4 r[4];
    g2r(r, A, Bm, bm, bn, K, 0, tid);
    r2s(sm, r, tid, 0);
    __syncthreads();

    const int arow = wm*32 + (piece & 1)*8 + pr;
    const int brow = wn*64 + (piece & 1)*8 + pr;
    const int kofp = (piece >> 1) * 8;

    for (int it = 0; it < nit; it++) {
        int st = it & 1;
        bool more = (it + 1) < nit;
        if (more) g2r(r, A, Bm, bm, bn, K, (it + 1) << 5, tid);

        uint32_t tA = sbase + (uint32_t)(st*2) * TILE_B;
        #pragma unroll
        for (int ks = 0; ks < 2; ks++) {
            int koff = ks*16 + kofp;
            uint32_t ah[2][4];
            #pragma unroll
            for (int mt = 0; mt < 2; mt++)
                ldsm4(ah[mt], tA + ((arow + mt*16) * TSTRIDE + koff) * 2);
            #pragma unroll
            for (int np = 0; np < 4; np++) {
                uint32_t b4[4];
                ldsm4(b4, tA + TILE_B + ((brow + np*16) * TSTRIDE + koff) * 2);
                #pragma unroll
                for (int mt = 0; mt < 2; mt++) {
                    mma_fp(acc[mt][np*2],   ah[mt], b4[0], b4[2]);
                    mma_fp(acc[mt][np*2+1], ah[mt], b4[1], b4[3]);
                }
            }
        }
        // Single barrier per iteration (see R9 note).
        if (more) r2s(sm, r, tid, st ^ 1);
        __syncthreads();
    }

    const int cbase = bn + wn * 64;
    if (EPI == 0) {
        #pragma unroll
        for (int mt = 0; mt < 2; mt++)
            #pragma unroll
            for (int half = 0; half < 2; half++) {
                int m = bm + wm*32 + mt*16 + (lane >> 2) + half*8;
                #pragma unroll
                for (int nt = 0; nt < 8; nt++) {
                    int c = cbase + nt*8 + (lane & 3)*2;
                    float2 v;
                    v.x = acc[mt][nt][half*2+0] + bias[c];
                    v.y = acc[mt][nt][half*2+1] + bias[c+1];
                    *(float2*)&C[(size_t)m * N + c] = v;
                }
            }
    } else {
        // QKV epilogue: Q (+RoPE, prescale) / K (+RoPE) / V -> plain fp16.
        int which = cbase / DIM;
        int h = (cbase % DIM) >> 6;
        __half* dstp = (which == 0) ? g_qh : (which == 1) ? g_kh : g_vh;
        #pragma unroll
        for (int mt = 0; mt < 2; mt++)
            #pragma unroll
            for (int half = 0; half < 2; half++) {
                int m = bm + wm*32 + mt*16 + (lane >> 2) + half*8;
                int bb = m / NTOK, pos = m - bb * NTOK;
                size_t dof = ((size_t)(bb*HEADS + h) * NTOK + pos) * HD;
                __half* dst = dstp + dof;
                if (which < 2) {
                    const float qs = (which == 0) ? 0.125f : 1.0f;
                    #pragma unroll
                    for (int nt = 0; nt < 4; nt++) {
                        int d0 = nt*8 + (lane & 3)*2;
                        float rl[2], rh[2];
                        #pragma unroll
                        for (int j = 0; j < 2; j++) {
                            float vlo = acc[mt][nt][half*2+j]   + bias[cbase + d0 + j];
                            float vhi = acc[mt][nt+4][half*2+j] + bias[cbase + 32 + d0 + j];
                            float sn = g_sin[pos*32 + d0 + j];
                            float cs = g_cos[pos*32 + d0 + j];
                            rl[j] = (vlo*cs - vhi*sn) * qs;
                            rh[j] = (vhi*cs + vlo*sn) * qs;
                        }
                        *(__half2*)&dst[d0]      = __floats2half2_rn(rl[0], rl[1]);
                        *(__half2*)&dst[32 + d0] = __floats2half2_rn(rh[0], rh[1]);
                    }
                } else {
                    #pragma unroll
                    for (int nt = 0; nt < 8; nt++) {
                        int d = nt*8 + (lane & 3)*2;
                        float v0 = acc[mt][nt][half*2+0] + bias[cbase + d];
                        float v1 = acc[mt][nt][half*2+1] + bias[cbase + d + 1];
                        *(__half2*)&dst[d] = __floats2half2_rn(v0, v1);
                    }
                }
            }
    }
}

// ==================== attention: HMMA flash, 2-stage K/V double buffer ==
#define AST 72
#define STAGEH (2*64*AST)            // halves per stage (K tile + V tile)
#define ATTN_SMEM (2*STAGEH*2)       // 36864 bytes

__device__ __forceinline__ void g2r_attn(uint4* rv,
    const __half* Kh, const __half* Vh, int k0, int tid)
{
    #pragma unroll
    for (int i = 0; i < 4; i++) {
        int lin = i * 256 + tid;
        int arr = lin >> 9, rem = lin & 511;
        int row = rem >> 3, c = (rem & 7) * 8;
        const __half* src = (arr == 0 ? Kh : Vh) + (size_t)(k0 + row) * HD + c;
        rv[i] = *(const uint4*)src;
    }
}
__device__ __forceinline__ void r2s_attn(__half* smh, const uint4* rv,
                                         int st, int tid)
{
    __half* base = smh + st * STAGEH;
    #pragma unroll
    for (int i = 0; i < 4; i++) {
        int lin = i * 256 + tid;
        int arr = lin >> 9, rem = lin & 511;
        int row = rem >> 3, c = (rem & 7) * 8;
        *(uint4*)&base[arr * (64*AST) + row * AST + c] = rv[i];
    }
}

__global__ void __launch_bounds__(256, 2) attn_mma()
{
    extern __shared__ __align__(16) __half smh[];
    const uint32_t sb = smem_u32(smh);

    const int tid = threadIdx.x;
    const int lane = tid & 31, w = tid >> 5;
    const int l15 = lane & 15, l16 = lane >> 4;
    const int bh = blockIdx.y, q0 = blockIdx.x * 128;

    const __half* Qh = g_qh + ((size_t)bh * NTOK + q0) * HD;
    const __half* Kh = g_kh + (size_t)bh * NTOK * HD;
    const __half* Vh = g_vh + (size_t)bh * NTOK * HD;

    // ---- stage Q (stage-0 region), extract A-fragments ----
    #pragma unroll
    for (int t = 0; t < 4; t++) {
        int lin = t * 256 + tid;
        int row = lin >> 3, c = (lin & 7) * 8;
        *(uint4*)&smh[row * AST + c] = *(const uint4*)&Qh[(size_t)row * HD + c];
    }
    __syncthreads();
    uint32_t qf[4][4];
    {
        uint32_t qa = sb + (((w*16 + l15) * AST) + l16*8) * 2;
        #pragma unroll
        for (int ks = 0; ks < 4; ks++)
            ldsm4(qf[ks], qa + ks*32);
    }

    // ---- pipeline prologue: tile0 -> stage0, tile1 in registers ----
    uint4 rv[4];
    g2r_attn(rv, Kh, Vh, 0, tid);
    __syncthreads();                 // all qf extractions done before overwrite
    r2s_attn(smh, rv, 0, tid);
    g2r_attn(rv, Kh, Vh, 64, tid);   // prefetch tile 1
    __syncthreads();                 // stage0 visible

    float acc[8][4];
    #pragma unroll
    for (int i = 0; i < 8; i++)
        #pragma unroll
        for (int j = 0; j < 4; j++) acc[i][j] = 0.0f;
    float m0 = -1e30f, m1 = -1e30f, l0 = 0.0f, l1 = 0.0f;

    const uint32_t lko = (l15 * AST + l16*8) * 2;
    const int NT = NTOK / 64;        // 36

    for (int t = 0; t < NT; t++) {
        if (t + 1 < NT) r2s_attn(smh, rv, (t + 1) & 1, tid);
        if (t + 2 < NT) g2r_attn(rv, Kh, Vh, (t + 2) * 64, tid);

        uint32_t stg = sb + (uint32_t)(t & 1) * (STAGEH * 2);
        uint32_t kbase = stg + lko;
        uint32_t vbase = stg + 64*AST*2 + lko;

        // ---- S = Q K^T ----
        float s[8][4];
        #pragma unroll
        for (int i = 0; i < 8; i++)
            #pragma unroll
            for (int j = 0; j < 4; j++) s[i][j] = 0.0f;
        #pragma unroll
        for (int ks = 0; ks < 4; ks++) {
            #pragma unroll
            for (int nbp = 0; nbp < 8; nbp += 2) {
                uint32_t kh4[4];
                ldsm4(kh4, kbase + (nbp*8*AST + ks*16) * 2);
                mma_fp(s[nbp],   qf[ks], kh4[0], kh4[2]);
                mma_fp(s[nbp+1], qf[ks], kh4[1], kh4[3]);
            }
        }

        // ---- online softmax ----
        float mx0 = -1e30f, mx1 = -1e30f;
        #pragma unroll
        for (int i = 0; i < 8; i++) {
            mx0 = fmaxf(mx0, fmaxf(s[i][0], s[i][1]));
            mx1 = fmaxf(mx1, fmaxf(s[i][2], s[i][3]));
        }
        mx0 = fmaxf(mx0, __shfl_xor_sync(0xffffffffu, mx0, 1));
        mx0 = fmaxf(mx0, __shfl_xor_sync(0xffffffffu, mx0, 2));
        mx1 = fmaxf(mx1, __shfl_xor_sync(0xffffffffu, mx1, 1));
        mx1 = fmaxf(mx1, __shfl_xor_sync(0xffffffffu, mx1, 2));
        float nm0 = fmaxf(m0, mx0), nm1 = fmaxf(m1, mx1);
        float f0 = fast_exp(m0 - nm0), f1 = fast_exp(m1 - nm1);
        m0 = nm0; m1 = nm1;
        float sum0 = 0.0f, sum1 = 0.0f;
        #pragma unroll
        for (int i = 0; i < 8; i++) {
            s[i][0] = fast_exp(s[i][0] - nm0); sum0 += s[i][0];
            s[i][1] = fast_exp(s[i][1] - nm0); sum0 += s[i][1];
            s[i][2] = fast_exp(s[i][2] - nm1); sum1 += s[i][2];
            s[i][3] = fast_exp(s[i][3] - nm1); sum1 += s[i][3];
        }
        sum0 += __shfl_xor_sync(0xffffffffu, sum0, 1);
        sum0 += __shfl_xor_sync(0xffffffffu, sum0, 2);
        sum1 += __shfl_xor_sync(0xffffffffu, sum1, 1);
        sum1 += __shfl_xor_sync(0xffffffffu, sum1, 2);
        l0 = l0 * f0 + sum0;
        l1 = l1 * f1 + sum1;
        #pragma unroll
        for (int i = 0; i < 8; i++) {
            acc[i][0] *= f0; acc[i][1] *= f0;
            acc[i][2] *= f1; acc[i][3] *= f1;
        }

        // ---- P -> fp16 A-fragments ----
        uint32_t ap[4][4];
        #pragma unroll
        for (int ks = 0; ks < 4; ks++) {
            int n0 = 2*ks, n1 = 2*ks + 1;
            __half2 h0 = __floats2half2_rn(s[n0][0], s[n0][1]);
            __half2 h1 = __floats2half2_rn(s[n0][2], s[n0][3]);
            __half2 h2 = __floats2half2_rn(s[n1][0], s[n1][1]);
            __half2 h3 = __floats2half2_rn(s[n1][2], s[n1][3]);
            ap[ks][0] = *(uint32_t*)&h0;
            ap[ks][1] = *(uint32_t*)&h1;
            ap[ks][2] = *(uint32_t*)&h2;
            ap[ks][3] = *(uint32_t*)&h3;
        }

        // ---- O += P V ----
        #pragma unroll
        for (int ks = 0; ks < 4; ks++) {
            #pragma unroll
            for (int nbp = 0; nbp < 8; nbp += 2) {
                uint32_t vh4[4];
                ldsm4t(vh4, vbase + (ks*16*AST + nbp*8) * 2);
                mma_fp(acc[nbp],   ap[ks], vh4[0], vh4[1]);
                mma_fp(acc[nbp+1], ap[ks], vh4[2], vh4[3]);
            }
        }

        __syncthreads();  // single barrier per iteration (see R14 note)
    }

    // ---- normalize + write O as fp16, [b, n, h*64 + d] ----
    float inv0 = 1.0f / l0, inv1 = 1.0f / l1;
    int b = bh / HEADS, h = bh - b * HEADS;
    int r0 = q0 + w*16 + (lane >> 2);
    int col = h*HD + (lane & 3)*2;
    #pragma unroll
    for (int nb = 0; nb < 8; nb++) {
        size_t o0 = ((size_t)(b*NTOK + r0))     * DIM + col + nb*8;
        size_t o1 = ((size_t)(b*NTOK + r0 + 8)) * DIM + col + nb*8;
        *(__half2*)&g_o16[o0] = __floats2half2_rn(acc[nb][0]*inv0, acc[nb][1]*inv0);
        *(__half2*)&g_o16[o1] = __floats2half2_rn(acc[nb][2]*inv1, acc[nb][3]*inv1);
    }
}

// ==================== launcher ====================
extern "C" void kernel_launch(void* const* d_in, const int* in_sizes, int n_in,
                              void* d_out, int out_size)
{
    const float* x      = (const float*)d_in[0];
    const float* w_qkv  = (const float*)d_in[1];
    const float* b_qkv  = (const float*)d_in[2];
    const float* w_proj = (const float*)d_in[3];
    const float* b_proj = (const float*)d_in[4];
    float* out = (float*)d_out;

    void *xp, *wq, *wp, *op;
    cudaGetSymbolAddress(&xp, g_x16);
    cudaGetSymbolAddress(&wq, g_wq16);
    cudaGetSymbolAddress(&wp, g_wp16);
    cudaGetSymbolAddress(&op, g_o16);

    cudaFuncSetAttribute(gemm_mma<0>, cudaFuncAttributeMaxDynamicSharedMemorySize,
                         GEMM_SMEM_B);
    cudaFuncSetAttribute(gemm_mma<1>, cudaFuncAttributeMaxDynamicSharedMemorySize,
                         GEMM_SMEM_B);
    cudaFuncSetAttribute(attn_mma, cudaFuncAttributeMaxDynamicSharedMemorySize,
                         ATTN_SMEM);

    // 0) fused prep: x/w_qkv/w_proj fp32->fp16 + rope table (one launch)
    prep_kernel<<<(PREP_TOTAL + 255)/256, 256>>>(x, w_qkv, w_proj);

    // 1) QKV GEMM + bias + RoPE + fp16 scatter
    gemm_mma<1><<<dim3(3*DIM/128, MROWS/128), 256, GEMM_SMEM_B>>>(
        (const __half*)xp, (const __half*)wq, b_qkv, nullptr, MROWS, 3*DIM, DIM);

    // 2) attention (HMMA flash, fp16 operands, 2-stage K/V pipeline)
    attn_mma<<<dim3(NTOK/128, BHC), 256, ATTN_SMEM>>>();

    // 3) output projection -> d_out
    gemm_mma<0><<<dim3(DIM/128, MROWS/128), 256, GEMM_SMEM_B>>>(
        (const __half*)op, (const __half*)wp, b_proj, out, MROWS, DIM, DIM);
}